// round 1
// baseline (speedup 1.0000x reference)
#include <cuda_runtime.h>
#include <math.h>

// Problem constants
#define B_ 2
#define S_ 1024
#define D_ 1024
#define H_ 16
#define DK_ 64
#define DFF_ 4096
#define L_ 4
#define V_ 50257
#define M_TOK (B_ * S_)   // 2048 rows

// -------- scratch (static device globals; no allocation allowed) --------
__device__ float g_x[M_TOK * D_];
__device__ float g_q[M_TOK * D_];
__device__ float g_k[M_TOK * D_];
__device__ float g_v[M_TOK * D_];
__device__ float g_y[M_TOK * D_];
__device__ float g_t[M_TOK * D_];
__device__ float g_h[M_TOK * DFF_];

// ------------------------- block reductions -------------------------
__device__ __forceinline__ float block_reduce_sum(float val, float* sh) {
    const int lane = threadIdx.x & 31;
    const int wid  = threadIdx.x >> 5;
#pragma unroll
    for (int o = 16; o; o >>= 1) val += __shfl_down_sync(0xffffffffu, val, o);
    if (lane == 0) sh[wid] = val;
    __syncthreads();
    const int nw = (blockDim.x + 31) >> 5;
    val = (threadIdx.x < nw) ? sh[threadIdx.x] : 0.0f;
    if (wid == 0) {
#pragma unroll
        for (int o = 16; o; o >>= 1) val += __shfl_down_sync(0xffffffffu, val, o);
        if (lane == 0) sh[0] = val;
    }
    __syncthreads();
    val = sh[0];
    __syncthreads();
    return val;
}

__device__ __forceinline__ float block_reduce_max(float val, float* sh) {
    const int lane = threadIdx.x & 31;
    const int wid  = threadIdx.x >> 5;
#pragma unroll
    for (int o = 16; o; o >>= 1) val = fmaxf(val, __shfl_down_sync(0xffffffffu, val, o));
    if (lane == 0) sh[wid] = val;
    __syncthreads();
    const int nw = (blockDim.x + 31) >> 5;
    val = (threadIdx.x < nw) ? sh[threadIdx.x] : -INFINITY;
    if (wid == 0) {
#pragma unroll
        for (int o = 16; o; o >>= 1) val = fmaxf(val, __shfl_down_sync(0xffffffffu, val, o));
        if (lane == 0) sh[0] = val;
    }
    __syncthreads();
    val = sh[0];
    __syncthreads();
    return val;
}

// ------------------------- embedding -------------------------
__global__ void __launch_bounds__(256) embed_kernel(
    const int* __restrict__ idx, const float* __restrict__ te,
    const float* __restrict__ pe, float* __restrict__ x)
{
    const int bs = blockIdx.x;           // 0..M_TOK-1
    const int s  = bs & (S_ - 1);
    const int tok = idx[bs];
    const float4* tr = (const float4*)(te + (size_t)tok * D_);
    const float4* pr = (const float4*)(pe + (size_t)s * D_);
    float4* xr = (float4*)(x + (size_t)bs * D_);
    for (int i = threadIdx.x; i < D_ / 4; i += blockDim.x) {
        float4 t = tr[i], p = pr[i];
        xr[i] = make_float4(t.x + p.x, t.y + p.y, t.z + p.z, t.w + p.w);
    }
}

// ------------------------- layernorm -------------------------
__global__ void __launch_bounds__(256) ln_kernel(
    const float* __restrict__ x, const float* __restrict__ g,
    const float* __restrict__ bta, float* __restrict__ out)
{
    __shared__ float red[32];
    const int row = blockIdx.x;
    const float* xr = x + (size_t)row * D_;
    float s = 0.0f, s2 = 0.0f;
    for (int i = threadIdx.x; i < D_; i += 256) {
        float v = xr[i];
        s += v; s2 += v * v;
    }
    s  = block_reduce_sum(s,  red);
    s2 = block_reduce_sum(s2, red);
    const float mean = s * (1.0f / D_);
    const float var  = s2 * (1.0f / D_) - mean * mean;
    const float rstd = rsqrtf(var + 1e-5f);
    float* orow = out + (size_t)row * D_;
    for (int i = threadIdx.x; i < D_; i += 256)
        orow[i] = (xr[i] - mean) * rstd * g[i] + bta[i];
}

// ------------------------- GEMM -------------------------
// C[M,N] = act(A[M,K] @ B + bias) (+ residual)
// NT=false: B stored [K,N] row-major.  NT=true: B stored [N,K] row-major (B^T used).
// Requires: M % BM == 0, K % BK == 0. For NT=false also N % BN == 0 and N % 4 == 0.
// Block: 256 threads = (BM/TM)*(BN/TN). For NT, BM must equal BN (shared load indexing).
template<int BM, int BN, int BK, int TM, int TN, bool NT, bool GELU, bool RES>
__global__ void __launch_bounds__(256) gemm_kernel(
    const float* __restrict__ A, const float* __restrict__ Bmat,
    const float* __restrict__ bias, const float* __restrict__ res,
    float* __restrict__ C, int M, int N, int K)
{
    __shared__ float As[BK][BM];
    __shared__ float Bs[BK][BN];
    const int tid = threadIdx.x;
    const int bm = blockIdx.y * BM;
    const int bn = blockIdx.x * BN;
    const int tx = tid % (BN / TN);
    const int ty = tid / (BN / TN);

    float acc[TM][TN];
#pragma unroll
    for (int i = 0; i < TM; i++)
#pragma unroll
        for (int j = 0; j < TN; j++) acc[i][j] = 0.0f;

    // load index precompute (each thread loads exactly one float4 of A and one of B)
    const int KV   = BK / 4;
    const int arow = tid / KV;            // BM rows
    const int acol = (tid % KV) * 4;      // BK cols
    const int brow = tid / (BN / 4);      // BK rows (NN)
    const int bcol = (tid % (BN / 4)) * 4;

    for (int k0 = 0; k0 < K; k0 += BK) {
        // A tile: [BM x BK] -> As[k][m]
        float4 av = *(const float4*)(A + (size_t)(bm + arow) * K + k0 + acol);
        As[acol + 0][arow] = av.x;
        As[acol + 1][arow] = av.y;
        As[acol + 2][arow] = av.z;
        As[acol + 3][arow] = av.w;

        if (!NT) {
            float4 bv = *(const float4*)(Bmat + (size_t)(k0 + brow) * N + bn + bcol);
            *(float4*)&Bs[brow][bcol] = bv;
        } else {
            const int n = bn + arow;      // BM == BN for NT
            float4 bv = make_float4(0.f, 0.f, 0.f, 0.f);
            if (n < N) bv = *(const float4*)(Bmat + (size_t)n * K + k0 + acol);
            Bs[acol + 0][arow] = bv.x;
            Bs[acol + 1][arow] = bv.y;
            Bs[acol + 2][arow] = bv.z;
            Bs[acol + 3][arow] = bv.w;
        }
        __syncthreads();

#pragma unroll
        for (int k = 0; k < BK; k++) {
            float a[TM], b[TN];
#pragma unroll
            for (int i = 0; i < TM / 4; i++) {
                float4 v4 = *(const float4*)&As[k][ty * TM + i * 4];
                a[i * 4 + 0] = v4.x; a[i * 4 + 1] = v4.y;
                a[i * 4 + 2] = v4.z; a[i * 4 + 3] = v4.w;
            }
#pragma unroll
            for (int j = 0; j < TN / 4; j++) {
                float4 v4 = *(const float4*)&Bs[k][tx * TN + j * 4];
                b[j * 4 + 0] = v4.x; b[j * 4 + 1] = v4.y;
                b[j * 4 + 2] = v4.z; b[j * 4 + 3] = v4.w;
            }
#pragma unroll
            for (int i = 0; i < TM; i++)
#pragma unroll
                for (int j = 0; j < TN; j++)
                    acc[i][j] += a[i] * b[j];
        }
        __syncthreads();
    }

#pragma unroll
    for (int i = 0; i < TM; i++) {
        const int m = bm + ty * TM + i;
#pragma unroll
        for (int j = 0; j < TN; j++) {
            const int n = bn + tx * TN + j;
            if (NT && n >= N) continue;
            float c = acc[i][j];
            if (bias) c += bias[n];
            if (GELU) c = 0.5f * c * (1.0f + erff(c * 0.70710678118654752f));
            if (RES)  c += res[(size_t)m * N + n];
            C[(size_t)m * N + n] = c;
        }
    }
}

// ------------------------- attention -------------------------
// One block per (query s, head h, batch b). 128 threads.
// q/k/v layout: [B, S, H*DK] with head h at column offset h*DK.
__global__ void __launch_bounds__(128) attn_kernel(
    const float* __restrict__ q, const float* __restrict__ k,
    const float* __restrict__ v, float* __restrict__ y)
{
    const int s = blockIdx.x, h = blockIdx.y, b = blockIdx.z;
    __shared__ float qs[DK_];
    __shared__ float sc[S_];
    __shared__ float red[32];
    __shared__ float ob[128];
    const int tid = threadIdx.x;
    const size_t base = (size_t)b * S_ * D_ + (size_t)h * DK_;

    if (tid < DK_) qs[tid] = q[base + (size_t)s * D_ + tid];
    __syncthreads();

    const int nk = s + 1;  // causal
    float lmax = -INFINITY;
    for (int t = tid; t < nk; t += 128) {
        const float* kr = k + base + (size_t)t * D_;
        float d = 0.0f;
#pragma unroll
        for (int i = 0; i < DK_; i += 4) {
            float4 kv4 = *(const float4*)(kr + i);
            d += qs[i] * kv4.x + qs[i + 1] * kv4.y
               + qs[i + 2] * kv4.z + qs[i + 3] * kv4.w;
        }
        d *= 0.125f;   // 1/sqrt(64)
        sc[t] = d;
        lmax = fmaxf(lmax, d);
    }
    const float mx = block_reduce_max(lmax, red);

    float lsum = 0.0f;
    for (int t = tid; t < nk; t += 128) {
        float e = expf(sc[t] - mx);
        sc[t] = e;
        lsum += e;
    }
    const float ssum = block_reduce_sum(lsum, red);  // also syncs sc[] writes
    const float inv = 1.0f / ssum;

    // output: threads 0..63 own dim d group 0, 64..127 group 1 over t
    const int dd = tid & 63, grp = tid >> 6;
    float accv = 0.0f;
    for (int t = grp; t < nk; t += 2)
        accv += sc[t] * v[base + (size_t)t * D_ + dd];
    ob[tid] = accv;
    __syncthreads();
    if (tid < 64)
        y[base + (size_t)s * D_ + tid] = (ob[tid] + ob[tid + 64]) * inv;
}

// ------------------------- driver -------------------------
extern "C" void kernel_launch(void* const* d_in, const int* in_sizes, int n_in,
                              void* d_out, int out_size)
{
    const int*   idx   = (const int*)  d_in[0];
    const float* te    = (const float*)d_in[1];
    const float* pe    = (const float*)d_in[2];
    const float* wq    = (const float*)d_in[3];
    const float* bq    = (const float*)d_in[4];
    const float* wk    = (const float*)d_in[5];
    const float* bk    = (const float*)d_in[6];
    const float* wv    = (const float*)d_in[7];
    const float* bv    = (const float*)d_in[8];
    const float* wo    = (const float*)d_in[9];
    const float* bo    = (const float*)d_in[10];
    const float* ln2g  = (const float*)d_in[11];
    const float* ln2b  = (const float*)d_in[12];
    const float* w1    = (const float*)d_in[13];
    const float* b1    = (const float*)d_in[14];
    const float* w2    = (const float*)d_in[15];
    const float* b2    = (const float*)d_in[16];
    const float* lnfg  = (const float*)d_in[17];
    const float* lnfb  = (const float*)d_in[18];
    float* out = (float*)d_out;

    float *x, *q, *k, *v, *y, *t, *hb;
    cudaGetSymbolAddress((void**)&x,  g_x);
    cudaGetSymbolAddress((void**)&q,  g_q);
    cudaGetSymbolAddress((void**)&k,  g_k);
    cudaGetSymbolAddress((void**)&v,  g_v);
    cudaGetSymbolAddress((void**)&y,  g_y);
    cudaGetSymbolAddress((void**)&t,  g_t);
    cudaGetSymbolAddress((void**)&hb, g_h);

    const int M = M_TOK;

    embed_kernel<<<M, 256>>>(idx, te, pe, x);

    const dim3 gDD(D_   / 64, M / 64);   // 16 x 32
    const dim3 gDF(DFF_ / 64, M / 64);   // 64 x 32
    const dim3 gLM((V_ + 127) / 128, M / 128);
    const dim3 gAT(S_, H_, B_);

    for (int l = 0; l < L_; l++) {
        const float* Wq = wq + (size_t)l * D_ * D_;
        const float* Wk = wk + (size_t)l * D_ * D_;
        const float* Wv = wv + (size_t)l * D_ * D_;
        const float* Wo = wo + (size_t)l * D_ * D_;
        const float* W1 = w1 + (size_t)l * D_ * DFF_;
        const float* W2 = w2 + (size_t)l * DFF_ * D_;

        // q/k/v projections from raw x (reference applies no ln1 — faithful)
        gemm_kernel<64,64,16,4,4,false,false,false><<<gDD,256>>>(x, Wq, bq + (size_t)l*D_,   nullptr, q, M, D_, D_);
        gemm_kernel<64,64,16,4,4,false,false,false><<<gDD,256>>>(x, Wk, bk + (size_t)l*D_,   nullptr, k, M, D_, D_);
        gemm_kernel<64,64,16,4,4,false,false,false><<<gDD,256>>>(x, Wv, bv + (size_t)l*D_,   nullptr, v, M, D_, D_);

        attn_kernel<<<gAT, 128>>>(q, k, v, y);

        // x = x + y @ Wo + bo   (in-place residual: each element read once, written once)
        gemm_kernel<64,64,16,4,4,false,false,true ><<<gDD,256>>>(y, Wo, bo + (size_t)l*D_,   x,       x, M, D_, D_);

        // t = LN(x)
        ln_kernel<<<M, 256>>>(x, ln2g + (size_t)l*D_, ln2b + (size_t)l*D_, t);

        // h = gelu(t @ W1 + b1)
        gemm_kernel<64,64,16,4,4,false,true ,false><<<gDF,256>>>(t, W1, b1 + (size_t)l*DFF_, nullptr, hb, M, DFF_, D_);

        // x = x + h @ W2 + b2
        gemm_kernel<64,64,16,4,4,false,false,true ><<<gDD,256>>>(hb, W2, b2 + (size_t)l*D_,  x,       x, M, D_, DFF_);
    }

    // final LN + weight-tied LM head: logits = LN(x) @ te^T
    ln_kernel<<<M, 256>>>(x, lnfg, lnfb, t);
    gemm_kernel<128,128,8,8,8,true,false,false><<<gLM,256>>>(t, te, nullptr, nullptr, out, M, V_, D_);
}

// round 4
// speedup vs baseline: 1.8354x; 1.8354x over previous
#include <cuda_runtime.h>
#include <cuda_bf16.h>
#include <math.h>
#include <stdint.h>

// Problem constants
#define B_ 2
#define S_ 1024
#define D_ 1024
#define H_ 16
#define DK_ 64
#define DFF_ 4096
#define L_ 4
#define V_ 50257
#define M_TOK (B_ * S_)   // 2048 rows

// ---------------- scratch (static device globals; no allocation allowed) ----
__device__ float g_x[M_TOK * D_];
__device__ float g_q[M_TOK * D_];
__device__ float g_k[M_TOK * D_];
__device__ float g_v[M_TOK * D_];
__device__ float g_y[M_TOK * D_];
__device__ float g_t[M_TOK * D_];
__device__ float g_h[M_TOK * DFF_];

// split activations (hi/lo bf16), sized for largest A [2048 x 4096]
__device__ __nv_bfloat16 g_ah[M_TOK * DFF_];
__device__ __nv_bfloat16 g_al[M_TOK * DFF_];

// transposed+split weights
#define LAYER_WELEMS (4 * D_ * D_ + D_ * DFF_ + DFF_ * D_)
__device__ __nv_bfloat16 g_wh[L_ * LAYER_WELEMS];
__device__ __nv_bfloat16 g_wl[L_ * LAYER_WELEMS];

// split token embedding ([V, D] = [N, K] for LM head)
__device__ __nv_bfloat16 g_teh[(size_t)V_ * D_];
__device__ __nv_bfloat16 g_tel[(size_t)V_ * D_];

// ---------------- PTX helpers (sm_80+ portable only) ----------------
__device__ __forceinline__ uint32_t smem_u32(const void* p) {
    uint32_t a;
    asm("{ .reg .u64 t; cvta.to.shared.u64 t, %1; cvt.u32.u64 %0, t; }" : "=r"(a) : "l"(p));
    return a;
}
__device__ __forceinline__ void cp_async16(uint32_t dst, const void* src, int szbytes) {
    asm volatile("cp.async.cg.shared.global [%0], [%1], 16, %2;" :: "r"(dst), "l"(src), "r"(szbytes));
}
__device__ __forceinline__ void cp_commit() { asm volatile("cp.async.commit_group;" ::: "memory"); }
template<int N> __device__ __forceinline__ void cp_wait() { asm volatile("cp.async.wait_group %0;" :: "n"(N) : "memory"); }

__device__ __forceinline__ void ldsm_x4(uint32_t& r0, uint32_t& r1, uint32_t& r2, uint32_t& r3, uint32_t addr) {
    asm volatile("ldmatrix.sync.aligned.m8n8.x4.shared.b16 {%0,%1,%2,%3}, [%4];"
                 : "=r"(r0), "=r"(r1), "=r"(r2), "=r"(r3) : "r"(addr));
}
__device__ __forceinline__ void mma16816(float* c, const uint32_t* a, uint32_t b0, uint32_t b1) {
    asm volatile("mma.sync.aligned.m16n8k16.row.col.f32.bf16.bf16.f32 "
                 "{%0,%1,%2,%3}, {%4,%5,%6,%7}, {%8,%9}, {%0,%1,%2,%3};"
                 : "+f"(c[0]), "+f"(c[1]), "+f"(c[2]), "+f"(c[3])
                 : "r"(a[0]), "r"(a[1]), "r"(a[2]), "r"(a[3]), "r"(b0), "r"(b1));
}

#define SW128(o) ((o) ^ (((o) >> 3) & 0x70))

// ---------------- HMMA split-bf16 GEMM ----------------
// C[M,N] = act( (Ah+Al)[M,K] @ (Bh+Bl)[N,K]^T + bias ) (+ res)
// CTA 128x128, BK=64, double-buffered cp.async, 8 warps (2x4), warp tile 64x32.
// M % 128 == 0, K % 64 == 0. N tail OK (zfill + scalar store guard).
#define GEMM_SMEM (2 * 4 * 16384)   // 2 stages x {Ah,Al,Bh,Bl} 16KB tiles = 128KB

template<bool GELU_, bool RES_>
__global__ void __launch_bounds__(256, 1)
mma_gemm(const __nv_bfloat16* __restrict__ Ah, const __nv_bfloat16* __restrict__ Al,
         const __nv_bfloat16* __restrict__ Bh, const __nv_bfloat16* __restrict__ Bl,
         const float* __restrict__ bias, const float* __restrict__ res,
         float* __restrict__ C, int M, int N, int K)
{
    extern __shared__ __align__(1024) char smem_raw[];
    const uint32_t sb = smem_u32(smem_raw);
    const int tid = threadIdx.x, wid = tid >> 5, lane = tid & 31;
    const int bm = blockIdx.y << 7, bn = blockIdx.x << 7;
    const int wr = wid >> 2, wc = wid & 3;       // 2 x 4 warp grid
    const int rl = lane & 15, qh = lane >> 4;    // ldmatrix addressing

    float acc[4][4][4];
#pragma unroll
    for (int i = 0; i < 4; i++)
#pragma unroll
        for (int j = 0; j < 4; j++)
#pragma unroll
            for (int r = 0; r < 4; r++) acc[i][j][r] = 0.0f;

    // stage s tile t (0=Ah,1=Al,2=Bh,3=Bl): sb + s*65536 + t*16384
    auto tileoff = [&](int s, int t) -> uint32_t {
        return sb + (uint32_t)s * 65536 + (uint32_t)t * 16384;
    };

    auto load_chunk = [&](int c, int stage) {
        const int k0 = c << 6;
#pragma unroll
        for (int i = 0; i < 4; i++) {
            const int ch = tid + (i << 8);        // 0..1023
            const int r = ch >> 3, q = ch & 7;    // row, 16B chunk in 128B row
            const uint32_t so = SW128((uint32_t)(r * 128 + q * 16));
            const size_t aoff = (size_t)(bm + r) * K + k0 + q * 8;
            cp_async16(tileoff(stage, 0) + so, Ah + aoff, 16);
            cp_async16(tileoff(stage, 1) + so, Al + aoff, 16);
            const int gn = bn + r;
            const int vn = gn < N ? gn : N - 1;
            const int vsz = gn < N ? 16 : 0;      // zero-fill OOB B rows
            const size_t boff = (size_t)vn * K + k0 + q * 8;
            cp_async16(tileoff(stage, 2) + so, Bh + boff, vsz);
            cp_async16(tileoff(stage, 3) + so, Bl + boff, vsz);
        }
    };

    const int NC = K >> 6;
    load_chunk(0, 0);
    cp_commit();

    for (int c = 0; c < NC; c++) {
        const int buf = c & 1;
        if (c + 1 < NC) {
            load_chunk(c + 1, buf ^ 1);
            cp_commit();
            cp_wait<1>();
        } else {
            cp_wait<0>();
        }
        __syncthreads();

        const uint32_t tAh = tileoff(buf, 0), tAl = tileoff(buf, 1);
        const uint32_t tBh = tileoff(buf, 2), tBl = tileoff(buf, 3);
#pragma unroll
        for (int k16 = 0; k16 < 4; k16++) {
            const int q16 = (k16 * 2 + qh) * 16;
            uint32_t ah[4][4], al[4][4], bh[2][4], bl[2][4];
#pragma unroll
            for (int i = 0; i < 4; i++) {
                const uint32_t off = SW128((uint32_t)((wr * 64 + i * 16 + rl) * 128 + q16));
                ldsm_x4(ah[i][0], ah[i][1], ah[i][2], ah[i][3], tAh + off);
                ldsm_x4(al[i][0], al[i][1], al[i][2], al[i][3], tAl + off);
            }
#pragma unroll
            for (int g = 0; g < 2; g++) {
                const uint32_t off = SW128((uint32_t)((wc * 32 + g * 16 + rl) * 128 + q16));
                ldsm_x4(bh[g][0], bh[g][1], bh[g][2], bh[g][3], tBh + off);
                ldsm_x4(bl[g][0], bl[g][1], bl[g][2], bl[g][3], tBl + off);
            }
#pragma unroll
            for (int i = 0; i < 4; i++)
#pragma unroll
                for (int j = 0; j < 4; j++) {
                    const int g = j >> 1, o = j & 1;
                    mma16816(acc[i][j], ah[i], bh[g][o], bh[g][o + 2]);  // ah*bh
                    mma16816(acc[i][j], ah[i], bl[g][o], bl[g][o + 2]);  // ah*bl
                    mma16816(acc[i][j], al[i], bh[g][o], bh[g][o + 2]);  // al*bh
                }
        }
        __syncthreads();
    }

    // epilogue (scalar stores: N may be odd -> float2 at m*N+n0 can be 4-mod-8 misaligned)
    const int quad = lane >> 2, tq = lane & 3;
#pragma unroll
    for (int i = 0; i < 4; i++) {
        const int m0 = bm + wr * 64 + i * 16 + quad;
#pragma unroll
        for (int j = 0; j < 4; j++) {
            const int n0 = bn + wc * 32 + j * 8 + tq * 2;
#pragma unroll
            for (int half = 0; half < 2; half++) {
                const int m = m0 + half * 8;
                float c0 = acc[i][j][half * 2 + 0];
                float c1 = acc[i][j][half * 2 + 1];
                if (bias) { c0 += bias[n0]; c1 += bias[n0 + 1]; }
                if (GELU_) {
                    c0 = 0.5f * c0 * (1.0f + erff(c0 * 0.70710678118654752f));
                    c1 = 0.5f * c1 * (1.0f + erff(c1 * 0.70710678118654752f));
                }
                if (RES_) {
                    c0 += res[(size_t)m * N + n0];
                    c1 += res[(size_t)m * N + n0 + 1];
                }
                if (n0 < N)     C[(size_t)m * N + n0]     = c0;
                if (n0 + 1 < N) C[(size_t)m * N + n0 + 1] = c1;
            }
        }
    }
}

// ---------------- conversion kernels ----------------
__global__ void __launch_bounds__(256) split_kernel(
    const float* __restrict__ x, __nv_bfloat16* __restrict__ hi,
    __nv_bfloat16* __restrict__ lo, int n)
{
    const int i = (blockIdx.x * 256 + threadIdx.x) * 4;
    if (i >= n) return;
    const float4 v = *(const float4*)(x + i);
    __nv_bfloat16 h0 = __float2bfloat16(v.x), h1 = __float2bfloat16(v.y);
    __nv_bfloat16 h2 = __float2bfloat16(v.z), h3 = __float2bfloat16(v.w);
    __nv_bfloat16 l0 = __float2bfloat16(v.x - __bfloat162float(h0));
    __nv_bfloat16 l1 = __float2bfloat16(v.y - __bfloat162float(h1));
    __nv_bfloat16 l2 = __float2bfloat16(v.z - __bfloat162float(h2));
    __nv_bfloat16 l3 = __float2bfloat16(v.w - __bfloat162float(h3));
    *(__nv_bfloat162*)(hi + i)     = __halves2bfloat162(h0, h1);
    *(__nv_bfloat162*)(hi + i + 2) = __halves2bfloat162(h2, h3);
    *(__nv_bfloat162*)(lo + i)     = __halves2bfloat162(l0, l1);
    *(__nv_bfloat162*)(lo + i + 2) = __halves2bfloat162(l2, l3);
}

// W [K,N] fp32 -> hi/lo [N,K] bf16 (transpose + split). K,N multiples of 32.
__global__ void __launch_bounds__(256) tsplit_kernel(
    const float* __restrict__ W, __nv_bfloat16* __restrict__ hi,
    __nv_bfloat16* __restrict__ lo, int K, int N)
{
    __shared__ float tile[32][33];
    const int tx = threadIdx.x & 31, ty = threadIdx.x >> 5;
    const int k0 = blockIdx.y << 5, n0 = blockIdx.x << 5;
#pragma unroll
    for (int i = 0; i < 4; i++)
        tile[ty + i * 8][tx] = W[(size_t)(k0 + ty + i * 8) * N + n0 + tx];
    __syncthreads();
#pragma unroll
    for (int i = 0; i < 4; i++) {
        const int n = n0 + ty + i * 8, k = k0 + tx;
        const float v = tile[tx][ty + i * 8];
        const __nv_bfloat16 h = __float2bfloat16(v);
        hi[(size_t)n * K + k] = h;
        lo[(size_t)n * K + k] = __float2bfloat16(v - __bfloat162float(h));
    }
}

// ---------------- embedding ----------------
__global__ void __launch_bounds__(256) embed_kernel(
    const int* __restrict__ idx, const float* __restrict__ te,
    const float* __restrict__ pe, float* __restrict__ x)
{
    const int bs = blockIdx.x;
    const int s  = bs & (S_ - 1);
    const int tok = idx[bs];
    const float4* tr = (const float4*)(te + (size_t)tok * D_);
    const float4* pr = (const float4*)(pe + (size_t)s * D_);
    float4* xr = (float4*)(x + (size_t)bs * D_);
    for (int i = threadIdx.x; i < D_ / 4; i += blockDim.x) {
        float4 t = tr[i], p = pr[i];
        xr[i] = make_float4(t.x + p.x, t.y + p.y, t.z + p.z, t.w + p.w);
    }
}

// ---------------- layernorm ----------------
__device__ __forceinline__ float block_reduce_sum(float val, float* sh) {
    const int lane = threadIdx.x & 31;
    const int wid  = threadIdx.x >> 5;
#pragma unroll
    for (int o = 16; o; o >>= 1) val += __shfl_down_sync(0xffffffffu, val, o);
    if (lane == 0) sh[wid] = val;
    __syncthreads();
    const int nw = (blockDim.x + 31) >> 5;
    val = (threadIdx.x < nw) ? sh[threadIdx.x] : 0.0f;
    if (wid == 0) {
#pragma unroll
        for (int o = 16; o; o >>= 1) val += __shfl_down_sync(0xffffffffu, val, o);
        if (lane == 0) sh[0] = val;
    }
    __syncthreads();
    val = sh[0];
    __syncthreads();
    return val;
}

__global__ void __launch_bounds__(256) ln_kernel(
    const float* __restrict__ x, const float* __restrict__ g,
    const float* __restrict__ bta, float* __restrict__ out)
{
    __shared__ float red[32];
    const int row = blockIdx.x;
    const float* xr = x + (size_t)row * D_;
    float s = 0.0f, s2 = 0.0f;
    for (int i = threadIdx.x; i < D_; i += 256) {
        float v = xr[i];
        s += v; s2 += v * v;
    }
    s  = block_reduce_sum(s,  red);
    s2 = block_reduce_sum(s2, red);
    const float mean = s * (1.0f / D_);
    const float var  = s2 * (1.0f / D_) - mean * mean;
    const float rstd = rsqrtf(var + 1e-5f);
    float* orow = out + (size_t)row * D_;
    for (int i = threadIdx.x; i < D_; i += 256)
        orow[i] = (xr[i] - mean) * rstd * g[i] + bta[i];
}

// ---------------- attention: warp-per-query ----------------
__global__ void __launch_bounds__(256) attn_kernel(
    const float* __restrict__ q, const float* __restrict__ k,
    const float* __restrict__ v, float* __restrict__ y)
{
    __shared__ float qs[8][DK_];
    __shared__ float sp[8][S_];
    const int tid = threadIdx.x, wid = tid >> 5, lane = tid & 31;
    const int s = blockIdx.x * 8 + wid;
    const int h = blockIdx.y, b = blockIdx.z;
    const size_t base = (size_t)b * S_ * D_ + (size_t)h * DK_;

    {
        const float2 qv = *(const float2*)(q + base + (size_t)s * D_ + lane * 2);
        qs[wid][lane * 2] = qv.x;
        qs[wid][lane * 2 + 1] = qv.y;
    }
    __syncwarp();

    const int nk = s + 1;
    float lmax = -INFINITY;
    for (int t = lane; t < nk; t += 32) {
        const float* kr = k + base + (size_t)t * D_;
        float d = 0.0f;
#pragma unroll
        for (int i = 0; i < DK_; i += 4) {
            const float4 kv = *(const float4*)(kr + i);
            d += qs[wid][i] * kv.x + qs[wid][i + 1] * kv.y
               + qs[wid][i + 2] * kv.z + qs[wid][i + 3] * kv.w;
        }
        d *= 0.125f;
        sp[wid][t] = d;
        lmax = fmaxf(lmax, d);
    }
#pragma unroll
    for (int o = 16; o; o >>= 1) lmax = fmaxf(lmax, __shfl_xor_sync(0xffffffffu, lmax, o));

    float lsum = 0.0f;
    for (int t = lane; t < nk; t += 32) {
        const float e = expf(sp[wid][t] - lmax);
        sp[wid][t] = e;
        lsum += e;
    }
#pragma unroll
    for (int o = 16; o; o >>= 1) lsum += __shfl_xor_sync(0xffffffffu, lsum, o);
    const float inv = 1.0f / lsum;
    __syncwarp();

    const int dd = lane * 2;
    float a0 = 0.0f, a1 = 0.0f;
    int t = 0;
    for (; t + 4 <= nk; t += 4) {
#pragma unroll
        for (int u = 0; u < 4; u++) {
            const float p = sp[wid][t + u];
            const float2 vv = *(const float2*)(v + base + (size_t)(t + u) * D_ + dd);
            a0 += p * vv.x; a1 += p * vv.y;
        }
    }
    for (; t < nk; t++) {
        const float p = sp[wid][t];
        const float2 vv = *(const float2*)(v + base + (size_t)t * D_ + dd);
        a0 += p * vv.x; a1 += p * vv.y;
    }
    *(float2*)(y + base + (size_t)s * D_ + dd) = make_float2(a0 * inv, a1 * inv);
}

// ---------------- driver ----------------
extern "C" void kernel_launch(void* const* d_in, const int* in_sizes, int n_in,
                              void* d_out, int out_size)
{
    const int*   idx   = (const int*)  d_in[0];
    const float* te    = (const float*)d_in[1];
    const float* pe    = (const float*)d_in[2];
    const float* wq    = (const float*)d_in[3];
    const float* bq    = (const float*)d_in[4];
    const float* wk    = (const float*)d_in[5];
    const float* bk    = (const float*)d_in[6];
    const float* wv    = (const float*)d_in[7];
    const float* bv    = (const float*)d_in[8];
    const float* wo    = (const float*)d_in[9];
    const float* bo    = (const float*)d_in[10];
    const float* ln2g  = (const float*)d_in[11];
    const float* ln2b  = (const float*)d_in[12];
    const float* w1    = (const float*)d_in[13];
    const float* b1    = (const float*)d_in[14];
    const float* w2    = (const float*)d_in[15];
    const float* b2    = (const float*)d_in[16];
    const float* lnfg  = (const float*)d_in[17];
    const float* lnfb  = (const float*)d_in[18];
    float* out = (float*)d_out;

    float *x, *q, *k, *v, *y, *t, *hb;
    __nv_bfloat16 *ah, *al, *wh, *wl, *teh, *tel;
    cudaGetSymbolAddress((void**)&x,   g_x);
    cudaGetSymbolAddress((void**)&q,   g_q);
    cudaGetSymbolAddress((void**)&k,   g_k);
    cudaGetSymbolAddress((void**)&v,   g_v);
    cudaGetSymbolAddress((void**)&y,   g_y);
    cudaGetSymbolAddress((void**)&t,   g_t);
    cudaGetSymbolAddress((void**)&hb,  g_h);
    cudaGetSymbolAddress((void**)&ah,  g_ah);
    cudaGetSymbolAddress((void**)&al,  g_al);
    cudaGetSymbolAddress((void**)&wh,  g_wh);
    cudaGetSymbolAddress((void**)&wl,  g_wl);
    cudaGetSymbolAddress((void**)&teh, g_teh);
    cudaGetSymbolAddress((void**)&tel, g_tel);

    cudaFuncSetAttribute(mma_gemm<false, false>, cudaFuncAttributeMaxDynamicSharedMemorySize, GEMM_SMEM);
    cudaFuncSetAttribute(mma_gemm<false, true >, cudaFuncAttributeMaxDynamicSharedMemorySize, GEMM_SMEM);
    cudaFuncSetAttribute(mma_gemm<true , false>, cudaFuncAttributeMaxDynamicSharedMemorySize, GEMM_SMEM);

    const int M = M_TOK;

    embed_kernel<<<M, 256>>>(idx, te, pe, x);

    // split token embedding for LM head (no transpose needed: te is [V, D] = [N, K])
    {
        const int n = V_ * D_;
        split_kernel<<<(n / 4 + 255) / 256, 256>>>(te, teh, tel, n);
    }
    // transpose+split all weights
    for (int l = 0; l < L_; l++) {
        const size_t lw = (size_t)l * LAYER_WELEMS;
        const dim3 gDD(D_ / 32, D_ / 32);
        tsplit_kernel<<<gDD, 256>>>(wq + (size_t)l * D_ * D_, wh + lw + 0 * D_ * D_, wl + lw + 0 * D_ * D_, D_, D_);
        tsplit_kernel<<<gDD, 256>>>(wk + (size_t)l * D_ * D_, wh + lw + 1 * D_ * D_, wl + lw + 1 * D_ * D_, D_, D_);
        tsplit_kernel<<<gDD, 256>>>(wv + (size_t)l * D_ * D_, wh + lw + 2 * D_ * D_, wl + lw + 2 * D_ * D_, D_, D_);
        tsplit_kernel<<<gDD, 256>>>(wo + (size_t)l * D_ * D_, wh + lw + 3 * D_ * D_, wl + lw + 3 * D_ * D_, D_, D_);
        tsplit_kernel<<<dim3(DFF_ / 32, D_ / 32), 256>>>(w1 + (size_t)l * D_ * DFF_,
                                                         wh + lw + 4 * D_ * D_, wl + lw + 4 * D_ * D_, D_, DFF_);
        tsplit_kernel<<<dim3(D_ / 32, DFF_ / 32), 256>>>(w2 + (size_t)l * DFF_ * D_,
                                                         wh + lw + 4 * D_ * D_ + (size_t)D_ * DFF_,
                                                         wl + lw + 4 * D_ * D_ + (size_t)D_ * DFF_, DFF_, D_);
    }

    const dim3 gDD(D_ / 128, M / 128);     // 8 x 16
    const dim3 gDF(DFF_ / 128, M / 128);   // 32 x 16
    const dim3 gLM((V_ + 127) / 128, M / 128);
    const dim3 gAT(S_ / 8, H_, B_);
    const int nXD = M * D_;

    for (int l = 0; l < L_; l++) {
        const size_t lw = (size_t)l * LAYER_WELEMS;
        const __nv_bfloat16 *whq = wh + lw, *wlq = wl + lw;
        const __nv_bfloat16 *whk = wh + lw + 1 * D_ * D_, *wlk = wl + lw + 1 * D_ * D_;
        const __nv_bfloat16 *whv = wh + lw + 2 * D_ * D_, *wlv = wl + lw + 2 * D_ * D_;
        const __nv_bfloat16 *who = wh + lw + 3 * D_ * D_, *wlo = wl + lw + 3 * D_ * D_;
        const __nv_bfloat16 *wh1 = wh + lw + 4 * D_ * D_, *wl1 = wl + lw + 4 * D_ * D_;
        const __nv_bfloat16 *wh2 = wh1 + (size_t)D_ * DFF_, *wl2 = wl1 + (size_t)D_ * DFF_;

        split_kernel<<<nXD / 4 / 256, 256>>>(x, ah, al, nXD);
        mma_gemm<false, false><<<gDD, 256, GEMM_SMEM>>>(ah, al, whq, wlq, bq + (size_t)l * D_, nullptr, q, M, D_, D_);
        mma_gemm<false, false><<<gDD, 256, GEMM_SMEM>>>(ah, al, whk, wlk, bk + (size_t)l * D_, nullptr, k, M, D_, D_);
        mma_gemm<false, false><<<gDD, 256, GEMM_SMEM>>>(ah, al, whv, wlv, bv + (size_t)l * D_, nullptr, v, M, D_, D_);

        attn_kernel<<<gAT, 256>>>(q, k, v, y);

        split_kernel<<<nXD / 4 / 256, 256>>>(y, ah, al, nXD);
        mma_gemm<false, true><<<gDD, 256, GEMM_SMEM>>>(ah, al, who, wlo, bo + (size_t)l * D_, x, x, M, D_, D_);

        ln_kernel<<<M, 256>>>(x, ln2g + (size_t)l * D_, ln2b + (size_t)l * D_, t);

        split_kernel<<<nXD / 4 / 256, 256>>>(t, ah, al, nXD);
        mma_gemm<true, false><<<gDF, 256, GEMM_SMEM>>>(ah, al, wh1, wl1, b1 + (size_t)l * DFF_, nullptr, hb, M, DFF_, D_);

        split_kernel<<<(M * DFF_) / 4 / 256, 256>>>(hb, ah, al, M * DFF_);
        mma_gemm<false, true><<<gDD, 256, GEMM_SMEM>>>(ah, al, wh2, wl2, b2 + (size_t)l * D_, x, x, M, D_, DFF_);
    }

    ln_kernel<<<M, 256>>>(x, lnfg, lnfb, t);
    split_kernel<<<nXD / 4 / 256, 256>>>(t, ah, al, nXD);
    mma_gemm<false, false><<<gLM, 256, GEMM_SMEM>>>(ah, al, teh, tel, nullptr, nullptr, out, M, V_, D_);
}

// round 5
// speedup vs baseline: 2.1254x; 1.1580x over previous
#include <cuda_runtime.h>
#include <math.h>
#include <stdint.h>

// Problem constants
#define B_ 2
#define S_ 1024
#define D_ 1024
#define H_ 16
#define DK_ 64
#define DFF_ 4096
#define L_ 4
#define V_ 50257
#define M_TOK (B_ * S_)   // 2048 rows

// ---------------- scratch (static device globals; no allocation allowed) ----
__device__ float g_x[M_TOK * D_];
__device__ float g_q[M_TOK * D_];
__device__ float g_k[M_TOK * D_];
__device__ float g_v[M_TOK * D_];
__device__ float g_y[M_TOK * D_];
__device__ float g_t[M_TOK * D_];
__device__ float g_h[M_TOK * DFF_];

// transposed fp32 weights: per layer [wqT][wkT][wvT][woT][w1T (DFF x D)][w2T (D x DFF)]
#define LAYER_WELEMS (4 * D_ * D_ + D_ * DFF_ + DFF_ * D_)
__device__ float g_wT[(size_t)L_ * LAYER_WELEMS];

// ---------------- PTX helpers (sm_80+ portable only) ----------------
__device__ __forceinline__ uint32_t smem_u32(const void* p) {
    uint32_t a;
    asm("{ .reg .u64 t; cvta.to.shared.u64 t, %1; cvt.u32.u64 %0, t; }" : "=r"(a) : "l"(p));
    return a;
}
__device__ __forceinline__ void cp_async16(uint32_t dst, const void* src, int szbytes) {
    asm volatile("cp.async.cg.shared.global [%0], [%1], 16, %2;" :: "r"(dst), "l"(src), "r"(szbytes));
}
__device__ __forceinline__ void cp_commit() { asm volatile("cp.async.commit_group;" ::: "memory"); }
template<int N> __device__ __forceinline__ void cp_wait() { asm volatile("cp.async.wait_group %0;" :: "n"(N) : "memory"); }

__device__ __forceinline__ void ldsm_x4(uint32_t& r0, uint32_t& r1, uint32_t& r2, uint32_t& r3, uint32_t addr) {
    asm volatile("ldmatrix.sync.aligned.m8n8.x4.shared.b16 {%0,%1,%2,%3}, [%4];"
                 : "=r"(r0), "=r"(r1), "=r"(r2), "=r"(r3) : "r"(addr));
}
// fp32 -> tf32 round-to-nearest (unbiased; HW truncation would bias dot products)
__device__ __forceinline__ uint32_t f2tf(uint32_t x) {
    uint32_t r;
    asm("cvt.rna.tf32.f32 %0, %1;" : "=r"(r) : "f"(__uint_as_float(x)));
    return r;
}
__device__ __forceinline__ void mma1688_tf32(float* c, const uint32_t* a, uint32_t b0, uint32_t b1) {
    asm volatile("mma.sync.aligned.m16n8k8.row.col.f32.tf32.tf32.f32 "
                 "{%0,%1,%2,%3}, {%4,%5,%6,%7}, {%8,%9}, {%0,%1,%2,%3};"
                 : "+f"(c[0]), "+f"(c[1]), "+f"(c[2]), "+f"(c[3])
                 : "r"(a[0]), "r"(a[1]), "r"(a[2]), "r"(a[3]), "r"(b0), "r"(b1));
}

#define SW128(o) ((o) ^ (((o) >> 3) & 0x70))

// ---------------- TF32 GEMM ----------------
// C[M,N] = act( A[M,K] @ B[N,K]^T + bias ) (+ res), fp32 in, tf32 MMA, fp32 accum.
// CTA 128x128, BK=32 fp32 (128B rows, SW128), 2-stage cp.async, 8 warps (2x4),
// warp tile 64x32. M % 128 == 0, K % 32 == 0. N tail OK (clamp+zfill, scalar stores).
#define GEMM_SMEM (2 * 2 * 16384)   // 2 stages x {A, B} 16KB fp32 tiles = 64KB

template<bool GELU_, bool RES_>
__global__ void __launch_bounds__(256, 2)
mma_gemm(const float* __restrict__ A, const float* __restrict__ B,
         const float* __restrict__ bias, const float* __restrict__ res,
         float* __restrict__ C, int M, int N, int K)
{
    extern __shared__ __align__(1024) char smem_raw[];
    const uint32_t sb = smem_u32(smem_raw);
    const int tid = threadIdx.x, wid = tid >> 5, lane = tid & 31;
    const int bm = blockIdx.y << 7, bn = blockIdx.x << 7;
    const int wr = wid >> 2, wc = wid & 3;       // 2 x 4 warp grid
    const int rl = lane & 15, qh = lane >> 4;    // A-fragment ldmatrix addressing
    const int brl = (lane & 7) + ((lane & 16) >> 1);  // B-fragment row
    const int bqh = (lane >> 3) & 1;                  // B-fragment chunk parity

    float acc[4][4][4];
#pragma unroll
    for (int i = 0; i < 4; i++)
#pragma unroll
        for (int j = 0; j < 4; j++)
#pragma unroll
            for (int r = 0; r < 4; r++) acc[i][j][r] = 0.0f;

    auto tileoff = [&](int s, int t) -> uint32_t {   // t: 0=A, 1=B
        return sb + (uint32_t)s * 32768 + (uint32_t)t * 16384;
    };

    auto load_chunk = [&](int c, int stage) {
        const int k0 = c << 5;                    // fp32 K offset
#pragma unroll
        for (int i = 0; i < 4; i++) {
            const int ch = tid + (i << 8);        // 0..1023
            const int r = ch >> 3, q = ch & 7;    // row, 16B chunk in 128B row
            const uint32_t so = SW128((uint32_t)(r * 128 + q * 16));
            cp_async16(tileoff(stage, 0) + so, A + (size_t)(bm + r) * K + k0 + q * 4, 16);
            const int gn = bn + r;
            const int vn = gn < N ? gn : N - 1;
            const int vsz = gn < N ? 16 : 0;      // zero-fill OOB B rows
            cp_async16(tileoff(stage, 1) + so, B + (size_t)vn * K + k0 + q * 4, vsz);
        }
    };

    const int NC = K >> 5;
    load_chunk(0, 0);
    cp_commit();

    for (int c = 0; c < NC; c++) {
        const int buf = c & 1;
        if (c + 1 < NC) {
            load_chunk(c + 1, buf ^ 1);
            cp_commit();
            cp_wait<1>();
        } else {
            cp_wait<0>();
        }
        __syncthreads();

        const uint32_t tA = tileoff(buf, 0), tB = tileoff(buf, 1);
#pragma unroll
        for (int s = 0; s < 4; s++) {             // 4 k8 steps in the 32-K chunk
            uint32_t a[4][4], b[2][4];
#pragma unroll
            for (int i = 0; i < 4; i++) {
                const uint32_t off = SW128((uint32_t)((wr * 64 + i * 16 + rl) * 128 + (2 * s + qh) * 16));
                ldsm_x4(a[i][0], a[i][1], a[i][2], a[i][3], tA + off);
            }
#pragma unroll
            for (int p = 0; p < 2; p++) {
                const uint32_t off = SW128((uint32_t)((wc * 32 + p * 16 + brl) * 128 + (2 * s + bqh) * 16));
                ldsm_x4(b[p][0], b[p][1], b[p][2], b[p][3], tB + off);
            }
#pragma unroll
            for (int i = 0; i < 4; i++)
#pragma unroll
                for (int r = 0; r < 4; r++) a[i][r] = f2tf(a[i][r]);
#pragma unroll
            for (int p = 0; p < 2; p++)
#pragma unroll
                for (int r = 0; r < 4; r++) b[p][r] = f2tf(b[p][r]);
#pragma unroll
            for (int i = 0; i < 4; i++)
#pragma unroll
                for (int j = 0; j < 4; j++)
                    mma1688_tf32(acc[i][j], a[i], b[j >> 1][(j & 1) * 2], b[j >> 1][(j & 1) * 2 + 1]);
        }
        __syncthreads();
    }

    // epilogue (scalar stores: N may be odd)
    const int quad = lane >> 2, tq = lane & 3;
#pragma unroll
    for (int i = 0; i < 4; i++) {
        const int m0 = bm + wr * 64 + i * 16 + quad;
#pragma unroll
        for (int j = 0; j < 4; j++) {
            const int n0 = bn + wc * 32 + j * 8 + tq * 2;
#pragma unroll
            for (int half = 0; half < 2; half++) {
                const int m = m0 + half * 8;
                float c0 = acc[i][j][half * 2 + 0];
                float c1 = acc[i][j][half * 2 + 1];
                if (bias) { c0 += bias[n0]; c1 += bias[n0 + 1]; }
                if (GELU_) {
                    c0 = 0.5f * c0 * (1.0f + erff(c0 * 0.70710678118654752f));
                    c1 = 0.5f * c1 * (1.0f + erff(c1 * 0.70710678118654752f));
                }
                if (RES_) {
                    c0 += res[(size_t)m * N + n0];
                    c1 += res[(size_t)m * N + n0 + 1];
                }
                if (n0 < N)     C[(size_t)m * N + n0]     = c0;
                if (n0 + 1 < N) C[(size_t)m * N + n0 + 1] = c1;
            }
        }
    }
}

// ---------------- weight transpose: W [K,N] -> WT [N,K] (fp32) ----------------
__global__ void __launch_bounds__(256) t32_kernel(
    const float* __restrict__ W, float* __restrict__ WT, int K, int N)
{
    __shared__ float tile[32][33];
    const int tx = threadIdx.x & 31, ty = threadIdx.x >> 5;
    const int k0 = blockIdx.y << 5, n0 = blockIdx.x << 5;
#pragma unroll
    for (int i = 0; i < 4; i++)
        tile[ty + i * 8][tx] = W[(size_t)(k0 + ty + i * 8) * N + n0 + tx];
    __syncthreads();
#pragma unroll
    for (int i = 0; i < 4; i++)
        WT[(size_t)(n0 + ty + i * 8) * K + k0 + tx] = tile[tx][ty + i * 8];
}

// ---------------- embedding ----------------
__global__ void __launch_bounds__(256) embed_kernel(
    const int* __restrict__ idx, const float* __restrict__ te,
    const float* __restrict__ pe, float* __restrict__ x)
{
    const int bs = blockIdx.x;
    const int s  = bs & (S_ - 1);
    const int tok = idx[bs];
    const float4* tr = (const float4*)(te + (size_t)tok * D_);
    const float4* pr = (const float4*)(pe + (size_t)s * D_);
    float4* xr = (float4*)(x + (size_t)bs * D_);
    for (int i = threadIdx.x; i < D_ / 4; i += blockDim.x) {
        float4 t = tr[i], p = pr[i];
        xr[i] = make_float4(t.x + p.x, t.y + p.y, t.z + p.z, t.w + p.w);
    }
}

// ---------------- layernorm ----------------
__device__ __forceinline__ float block_reduce_sum(float val, float* sh) {
    const int lane = threadIdx.x & 31;
    const int wid  = threadIdx.x >> 5;
#pragma unroll
    for (int o = 16; o; o >>= 1) val += __shfl_down_sync(0xffffffffu, val, o);
    if (lane == 0) sh[wid] = val;
    __syncthreads();
    const int nw = (blockDim.x + 31) >> 5;
    val = (threadIdx.x < nw) ? sh[threadIdx.x] : 0.0f;
    if (wid == 0) {
#pragma unroll
        for (int o = 16; o; o >>= 1) val += __shfl_down_sync(0xffffffffu, val, o);
        if (lane == 0) sh[0] = val;
    }
    __syncthreads();
    val = sh[0];
    __syncthreads();
    return val;
}

__global__ void __launch_bounds__(256) ln_kernel(
    const float* __restrict__ x, const float* __restrict__ g,
    const float* __restrict__ bta, float* __restrict__ out)
{
    __shared__ float red[32];
    const int row = blockIdx.x;
    const float* xr = x + (size_t)row * D_;
    float s = 0.0f, s2 = 0.0f;
    for (int i = threadIdx.x; i < D_; i += 256) {
        float v = xr[i];
        s += v; s2 += v * v;
    }
    s  = block_reduce_sum(s,  red);
    s2 = block_reduce_sum(s2, red);
    const float mean = s * (1.0f / D_);
    const float var  = s2 * (1.0f / D_) - mean * mean;
    const float rstd = rsqrtf(var + 1e-5f);
    float* orow = out + (size_t)row * D_;
    for (int i = threadIdx.x; i < D_; i += 256)
        orow[i] = (xr[i] - mean) * rstd * g[i] + bta[i];
}

// ---------------- attention: warp-per-query ----------------
__global__ void __launch_bounds__(256) attn_kernel(
    const float* __restrict__ q, const float* __restrict__ k,
    const float* __restrict__ v, float* __restrict__ y)
{
    __shared__ float qs[8][DK_];
    __shared__ float sp[8][S_];
    const int tid = threadIdx.x, wid = tid >> 5, lane = tid & 31;
    const int s = blockIdx.x * 8 + wid;
    const int h = blockIdx.y, b = blockIdx.z;
    const size_t base = (size_t)b * S_ * D_ + (size_t)h * DK_;

    {
        const float2 qv = *(const float2*)(q + base + (size_t)s * D_ + lane * 2);
        qs[wid][lane * 2] = qv.x;
        qs[wid][lane * 2 + 1] = qv.y;
    }
    __syncwarp();

    const int nk = s + 1;
    float lmax = -INFINITY;
    for (int t = lane; t < nk; t += 32) {
        const float* kr = k + base + (size_t)t * D_;
        float d = 0.0f;
#pragma unroll
        for (int i = 0; i < DK_; i += 4) {
            const float4 kv = *(const float4*)(kr + i);
            d += qs[wid][i] * kv.x + qs[wid][i + 1] * kv.y
               + qs[wid][i + 2] * kv.z + qs[wid][i + 3] * kv.w;
        }
        d *= 0.125f;
        sp[wid][t] = d;
        lmax = fmaxf(lmax, d);
    }
#pragma unroll
    for (int o = 16; o; o >>= 1) lmax = fmaxf(lmax, __shfl_xor_sync(0xffffffffu, lmax, o));

    float lsum = 0.0f;
    for (int t = lane; t < nk; t += 32) {
        const float e = expf(sp[wid][t] - lmax);
        sp[wid][t] = e;
        lsum += e;
    }
#pragma unroll
    for (int o = 16; o; o >>= 1) lsum += __shfl_xor_sync(0xffffffffu, lsum, o);
    const float inv = 1.0f / lsum;
    __syncwarp();

    const int dd = lane * 2;
    float a0 = 0.0f, a1 = 0.0f;
    int t = 0;
    for (; t + 4 <= nk; t += 4) {
#pragma unroll
        for (int u = 0; u < 4; u++) {
            const float p = sp[wid][t + u];
            const float2 vv = *(const float2*)(v + base + (size_t)(t + u) * D_ + dd);
            a0 += p * vv.x; a1 += p * vv.y;
        }
    }
    for (; t < nk; t++) {
        const float p = sp[wid][t];
        const float2 vv = *(const float2*)(v + base + (size_t)t * D_ + dd);
        a0 += p * vv.x; a1 += p * vv.y;
    }
    *(float2*)(y + base + (size_t)s * D_ + dd) = make_float2(a0 * inv, a1 * inv);
}

// ---------------- driver ----------------
extern "C" void kernel_launch(void* const* d_in, const int* in_sizes, int n_in,
                              void* d_out, int out_size)
{
    const int*   idx   = (const int*)  d_in[0];
    const float* te    = (const float*)d_in[1];
    const float* pe    = (const float*)d_in[2];
    const float* wq    = (const float*)d_in[3];
    const float* bq    = (const float*)d_in[4];
    const float* wk    = (const float*)d_in[5];
    const float* bk    = (const float*)d_in[6];
    const float* wv    = (const float*)d_in[7];
    const float* bv    = (const float*)d_in[8];
    const float* wo    = (const float*)d_in[9];
    const float* bo    = (const float*)d_in[10];
    const float* ln2g  = (const float*)d_in[11];
    const float* ln2b  = (const float*)d_in[12];
    const float* w1    = (const float*)d_in[13];
    const float* b1    = (const float*)d_in[14];
    const float* w2    = (const float*)d_in[15];
    const float* b2    = (const float*)d_in[16];
    const float* lnfg  = (const float*)d_in[17];
    const float* lnfb  = (const float*)d_in[18];
    float* out = (float*)d_out;

    float *x, *q, *k, *v, *y, *t, *hb, *wT;
    cudaGetSymbolAddress((void**)&x,  g_x);
    cudaGetSymbolAddress((void**)&q,  g_q);
    cudaGetSymbolAddress((void**)&k,  g_k);
    cudaGetSymbolAddress((void**)&v,  g_v);
    cudaGetSymbolAddress((void**)&y,  g_y);
    cudaGetSymbolAddress((void**)&t,  g_t);
    cudaGetSymbolAddress((void**)&hb, g_h);
    cudaGetSymbolAddress((void**)&wT, g_wT);

    cudaFuncSetAttribute(mma_gemm<false, false>, cudaFuncAttributeMaxDynamicSharedMemorySize, GEMM_SMEM);
    cudaFuncSetAttribute(mma_gemm<false, true >, cudaFuncAttributeMaxDynamicSharedMemorySize, GEMM_SMEM);
    cudaFuncSetAttribute(mma_gemm<true , false>, cudaFuncAttributeMaxDynamicSharedMemorySize, GEMM_SMEM);

    const int M = M_TOK;

    embed_kernel<<<M, 256>>>(idx, te, pe, x);

    // transpose weights to [N,K] fp32 (te already [N,K]; no prep needed)
    for (int l = 0; l < L_; l++) {
        const size_t lw = (size_t)l * LAYER_WELEMS;
        const dim3 gDD(D_ / 32, D_ / 32);
        t32_kernel<<<gDD, 256>>>(wq + (size_t)l * D_ * D_, wT + lw + 0 * D_ * D_, D_, D_);
        t32_kernel<<<gDD, 256>>>(wk + (size_t)l * D_ * D_, wT + lw + 1 * D_ * D_, D_, D_);
        t32_kernel<<<gDD, 256>>>(wv + (size_t)l * D_ * D_, wT + lw + 2 * D_ * D_, D_, D_);
        t32_kernel<<<gDD, 256>>>(wo + (size_t)l * D_ * D_, wT + lw + 3 * D_ * D_, D_, D_);
        t32_kernel<<<dim3(DFF_ / 32, D_ / 32), 256>>>(w1 + (size_t)l * D_ * DFF_,
                                                      wT + lw + 4 * D_ * D_, D_, DFF_);
        t32_kernel<<<dim3(D_ / 32, DFF_ / 32), 256>>>(w2 + (size_t)l * DFF_ * D_,
                                                      wT + lw + 4 * D_ * D_ + (size_t)D_ * DFF_, DFF_, D_);
    }

    const dim3 gDD(D_ / 128, M / 128);     // 8 x 16
    const dim3 gDF(DFF_ / 128, M / 128);   // 32 x 16
    const dim3 gLM((V_ + 127) / 128, M / 128);
    const dim3 gAT(S_ / 8, H_, B_);

    for (int l = 0; l < L_; l++) {
        const size_t lw = (size_t)l * LAYER_WELEMS;
        const float *wqT = wT + lw;
        const float *wkT = wT + lw + 1 * D_ * D_;
        const float *wvT = wT + lw + 2 * D_ * D_;
        const float *woT = wT + lw + 3 * D_ * D_;
        const float *w1T = wT + lw + 4 * D_ * D_;
        const float *w2T = w1T + (size_t)D_ * DFF_;

        mma_gemm<false, false><<<gDD, 256, GEMM_SMEM>>>(x, wqT, bq + (size_t)l * D_, nullptr, q, M, D_, D_);
        mma_gemm<false, false><<<gDD, 256, GEMM_SMEM>>>(x, wkT, bk + (size_t)l * D_, nullptr, k, M, D_, D_);
        mma_gemm<false, false><<<gDD, 256, GEMM_SMEM>>>(x, wvT, bv + (size_t)l * D_, nullptr, v, M, D_, D_);

        attn_kernel<<<gAT, 256>>>(q, k, v, y);

        mma_gemm<false, true><<<gDD, 256, GEMM_SMEM>>>(y, woT, bo + (size_t)l * D_, x, x, M, D_, D_);

        ln_kernel<<<M, 256>>>(x, ln2g + (size_t)l * D_, ln2b + (size_t)l * D_, t);

        mma_gemm<true, false><<<gDF, 256, GEMM_SMEM>>>(t, w1T, b1 + (size_t)l * DFF_, nullptr, hb, M, DFF_, D_);

        mma_gemm<false, true><<<gDD, 256, GEMM_SMEM>>>(hb, w2T, b2 + (size_t)l * D_, x, x, M, D_, DFF_);
    }

    ln_kernel<<<M, 256>>>(x, lnfg, lnfb, t);
    mma_gemm<false, false><<<gLM, 256, GEMM_SMEM>>>(t, te, nullptr, nullptr, out, M, V_, D_);
}

// round 6
// speedup vs baseline: 3.6591x; 1.7216x over previous
#include <cuda_runtime.h>
#include <math.h>
#include <stdint.h>

// Problem constants
#define B_ 2
#define S_ 1024
#define D_ 1024
#define H_ 16
#define DK_ 64
#define DFF_ 4096
#define L_ 4
#define V_ 50257
#define M_TOK (B_ * S_)   // 2048 rows

// ---------------- scratch (static device globals; no allocation allowed) ----
__device__ float g_x[M_TOK * D_];    // residual stream (fp32)
__device__ float g_xr[M_TOK * D_];   // tf32-rounded copy of x (GEMM A input)
__device__ float g_q[M_TOK * D_];
__device__ float g_k[M_TOK * D_];
__device__ float g_v[M_TOK * D_];
__device__ float g_y[M_TOK * D_];    // attention out (tf32-rounded at write)
__device__ float g_t[M_TOK * D_];    // ln out (tf32-rounded at write)
__device__ float g_h[M_TOK * DFF_];  // mlp hidden (tf32-rounded at write)

// transposed + tf32-rounded weights: per layer [wqT][wkT][wvT][woT][w1T][w2T]
#define LAYER_WELEMS (4 * D_ * D_ + D_ * DFF_ + DFF_ * D_)
__device__ float g_wT[(size_t)L_ * LAYER_WELEMS];
// tf32-rounded token embedding ([V,D] = [N,K] for LM head B operand)
__device__ float g_teR[(size_t)V_ * D_];

// ---------------- PTX helpers (sm_80+ portable only) ----------------
__device__ __forceinline__ uint32_t smem_u32(const void* p) {
    uint32_t a;
    asm("{ .reg .u64 t; cvta.to.shared.u64 t, %1; cvt.u32.u64 %0, t; }" : "=r"(a) : "l"(p));
    return a;
}
__device__ __forceinline__ void cp_async16(uint32_t dst, const void* src, int szbytes) {
    asm volatile("cp.async.cg.shared.global [%0], [%1], 16, %2;" :: "r"(dst), "l"(src), "r"(szbytes));
}
__device__ __forceinline__ void cp_commit() { asm volatile("cp.async.commit_group;" ::: "memory"); }
template<int N> __device__ __forceinline__ void cp_wait() { asm volatile("cp.async.wait_group %0;" :: "n"(N) : "memory"); }

__device__ __forceinline__ void ldsm_x4(uint32_t& r0, uint32_t& r1, uint32_t& r2, uint32_t& r3, uint32_t addr) {
    asm volatile("ldmatrix.sync.aligned.m8n8.x4.shared.b16 {%0,%1,%2,%3}, [%4];"
                 : "=r"(r0), "=r"(r1), "=r"(r2), "=r"(r3) : "r"(addr));
}
// fp32 -> tf32 round-to-nearest (unbiased)
__device__ __forceinline__ float f2tf(float x) {
    uint32_t r;
    asm("cvt.rna.tf32.f32 %0, %1;" : "=r"(r) : "f"(x));
    return __uint_as_float(r);
}
__device__ __forceinline__ void mma1688_tf32(float* c, const uint32_t* a, uint32_t b0, uint32_t b1) {
    asm volatile("mma.sync.aligned.m16n8k8.row.col.f32.tf32.tf32.f32 "
                 "{%0,%1,%2,%3}, {%4,%5,%6,%7}, {%8,%9}, {%0,%1,%2,%3};"
                 : "+f"(c[0]), "+f"(c[1]), "+f"(c[2]), "+f"(c[3])
                 : "r"(a[0]), "r"(a[1]), "r"(a[2]), "r"(a[3]), "r"(b0), "r"(b1));
}

#define SW128(o) ((o) ^ (((o) >> 3) & 0x70))

// ---------------- TF32 GEMM (inputs pre-rounded to tf32) ----------------
// C[M,N] = act( A[M,K] @ B[N,K]^T + bias ) (+ res), tf32-valued fp32 in, fp32 accum.
// CTA 128x128, BK=32 fp32 (128B rows, SW128), 2-stage cp.async, 8 warps (2x4),
// warp tile 64x32. M % 128 == 0, K % 32 == 0. N tail OK (clamp+zfill, scalar stores).
#define GEMM_SMEM (2 * 2 * 16384)   // 2 stages x {A, B} 16KB tiles = 64KB

template<bool GELU_, bool RES_, bool ROUND_, bool WR_>
__global__ void __launch_bounds__(256, 2)
mma_gemm(const float* __restrict__ A, const float* __restrict__ B,
         const float* __restrict__ bias, const float* __restrict__ res,
         float* __restrict__ C, float* __restrict__ Cr, int M, int N, int K)
{
    extern __shared__ __align__(1024) char smem_raw[];
    const uint32_t sb = smem_u32(smem_raw);
    const int tid = threadIdx.x, wid = tid >> 5, lane = tid & 31;
    const int bm = blockIdx.y << 7, bn = blockIdx.x << 7;
    const int wr = wid >> 2, wc = wid & 3;       // 2 x 4 warp grid
    const int rl = lane & 15, qh = lane >> 4;    // A-fragment ldmatrix addressing
    const int brl = (lane & 7) + ((lane & 16) >> 1);  // B-fragment row
    const int bqh = (lane >> 3) & 1;                  // B-fragment chunk parity

    float acc[4][4][4];
#pragma unroll
    for (int i = 0; i < 4; i++)
#pragma unroll
        for (int j = 0; j < 4; j++)
#pragma unroll
            for (int r = 0; r < 4; r++) acc[i][j][r] = 0.0f;

    auto tileoff = [&](int s, int t) -> uint32_t {   // t: 0=A, 1=B
        return sb + (uint32_t)s * 32768 + (uint32_t)t * 16384;
    };

    auto load_chunk = [&](int c, int stage) {
        const int k0 = c << 5;
#pragma unroll
        for (int i = 0; i < 4; i++) {
            const int ch = tid + (i << 8);
            const int r = ch >> 3, q = ch & 7;
            const uint32_t so = SW128((uint32_t)(r * 128 + q * 16));
            cp_async16(tileoff(stage, 0) + so, A + (size_t)(bm + r) * K + k0 + q * 4, 16);
            const int gn = bn + r;
            const int vn = gn < N ? gn : N - 1;
            const int vsz = gn < N ? 16 : 0;
            cp_async16(tileoff(stage, 1) + so, B + (size_t)vn * K + k0 + q * 4, vsz);
        }
    };

    const int NC = K >> 5;
    load_chunk(0, 0);
    cp_commit();

    for (int c = 0; c < NC; c++) {
        const int buf = c & 1;
        if (c + 1 < NC) {
            load_chunk(c + 1, buf ^ 1);
            cp_commit();
            cp_wait<1>();
        } else {
            cp_wait<0>();
        }
        __syncthreads();

        const uint32_t tA = tileoff(buf, 0), tB = tileoff(buf, 1);
#pragma unroll
        for (int s = 0; s < 4; s++) {             // 4 k8 steps per 32-K chunk
            uint32_t a[4][4], b[2][4];
#pragma unroll
            for (int i = 0; i < 4; i++) {
                const uint32_t off = SW128((uint32_t)((wr * 64 + i * 16 + rl) * 128 + (2 * s + qh) * 16));
                ldsm_x4(a[i][0], a[i][1], a[i][2], a[i][3], tA + off);
            }
#pragma unroll
            for (int p = 0; p < 2; p++) {
                const uint32_t off = SW128((uint32_t)((wc * 32 + p * 16 + brl) * 128 + (2 * s + bqh) * 16));
                ldsm_x4(b[p][0], b[p][1], b[p][2], b[p][3], tB + off);
            }
#pragma unroll
            for (int i = 0; i < 4; i++)
#pragma unroll
                for (int j = 0; j < 4; j++)
                    mma1688_tf32(acc[i][j], a[i], b[j >> 1][(j & 1) * 2], b[j >> 1][(j & 1) * 2 + 1]);
        }
        __syncthreads();
    }

    // epilogue (scalar stores: N may be odd)
    const int quad = lane >> 2, tq = lane & 3;
#pragma unroll
    for (int i = 0; i < 4; i++) {
        const int m0 = bm + wr * 64 + i * 16 + quad;
#pragma unroll
        for (int j = 0; j < 4; j++) {
            const int n0 = bn + wc * 32 + j * 8 + tq * 2;
#pragma unroll
            for (int half = 0; half < 2; half++) {
                const int m = m0 + half * 8;
                float c0 = acc[i][j][half * 2 + 0];
                float c1 = acc[i][j][half * 2 + 1];
                if (bias) { c0 += bias[n0]; c1 += bias[n0 + 1]; }
                if (GELU_) {
                    c0 = 0.5f * c0 * (1.0f + erff(c0 * 0.70710678118654752f));
                    c1 = 0.5f * c1 * (1.0f + erff(c1 * 0.70710678118654752f));
                }
                if (RES_) {
                    c0 += res[(size_t)m * N + n0];
                    c1 += res[(size_t)m * N + n0 + 1];
                }
                float s0 = ROUND_ ? f2tf(c0) : c0;
                float s1 = ROUND_ ? f2tf(c1) : c1;
                if (n0 < N)     C[(size_t)m * N + n0]     = s0;
                if (n0 + 1 < N) C[(size_t)m * N + n0 + 1] = s1;
                if (WR_) {
                    if (n0 < N)     Cr[(size_t)m * N + n0]     = f2tf(c0);
                    if (n0 + 1 < N) Cr[(size_t)m * N + n0 + 1] = f2tf(c1);
                }
            }
        }
    }
}

// ---------------- merged weight prep (transpose + tf32 round) ----------------
// all 16 DxD matrices: z = layer*4 + {q,k,v,o}
__global__ void __launch_bounds__(256) tDD_kernel(
    const float* __restrict__ wq, const float* __restrict__ wk,
    const float* __restrict__ wv, const float* __restrict__ wo,
    float* __restrict__ wT)
{
    __shared__ float tile[32][33];
    const int m = blockIdx.z, l = m >> 2, which = m & 3;
    const float* W = (which == 0 ? wq : which == 1 ? wk : which == 2 ? wv : wo)
                     + (size_t)l * D_ * D_;
    float* WT = wT + (size_t)l * LAYER_WELEMS + (size_t)which * D_ * D_;
    const int tx = threadIdx.x & 31, ty = threadIdx.x >> 5;
    const int k0 = blockIdx.y << 5, n0 = blockIdx.x << 5;
#pragma unroll
    for (int i = 0; i < 4; i++)
        tile[ty + i * 8][tx] = W[(size_t)(k0 + ty + i * 8) * D_ + n0 + tx];
    __syncthreads();
#pragma unroll
    for (int i = 0; i < 4; i++)
        WT[(size_t)(n0 + ty + i * 8) * D_ + k0 + tx] = f2tf(tile[tx][ty + i * 8]);
}

// w1 [K=D, N=DFF] -> [DFF, D], z = layer
__global__ void __launch_bounds__(256) tW1_kernel(const float* __restrict__ w1, float* __restrict__ wT)
{
    __shared__ float tile[32][33];
    const int l = blockIdx.z;
    const float* W = w1 + (size_t)l * D_ * DFF_;
    float* WT = wT + (size_t)l * LAYER_WELEMS + (size_t)4 * D_ * D_;
    const int tx = threadIdx.x & 31, ty = threadIdx.x >> 5;
    const int k0 = blockIdx.y << 5, n0 = blockIdx.x << 5;
#pragma unroll
    for (int i = 0; i < 4; i++)
        tile[ty + i * 8][tx] = W[(size_t)(k0 + ty + i * 8) * DFF_ + n0 + tx];
    __syncthreads();
#pragma unroll
    for (int i = 0; i < 4; i++)
        WT[(size_t)(n0 + ty + i * 8) * D_ + k0 + tx] = f2tf(tile[tx][ty + i * 8]);
}

// w2 [K=DFF, N=D] -> [D, DFF], z = layer
__global__ void __launch_bounds__(256) tW2_kernel(const float* __restrict__ w2, float* __restrict__ wT)
{
    __shared__ float tile[32][33];
    const int l = blockIdx.z;
    const float* W = w2 + (size_t)l * DFF_ * D_;
    float* WT = wT + (size_t)l * LAYER_WELEMS + (size_t)4 * D_ * D_ + (size_t)D_ * DFF_;
    const int tx = threadIdx.x & 31, ty = threadIdx.x >> 5;
    const int k0 = blockIdx.y << 5, n0 = blockIdx.x << 5;
#pragma unroll
    for (int i = 0; i < 4; i++)
        tile[ty + i * 8][tx] = W[(size_t)(k0 + ty + i * 8) * D_ + n0 + tx];
    __syncthreads();
#pragma unroll
    for (int i = 0; i < 4; i++)
        WT[(size_t)(n0 + ty + i * 8) * DFF_ + k0 + tx] = f2tf(tile[tx][ty + i * 8]);
}

// elementwise tf32 round (te -> teR); n % 4 == 0
__global__ void __launch_bounds__(256) round_kernel(
    const float* __restrict__ x, float* __restrict__ r, int n)
{
    const int i = (blockIdx.x * 256 + threadIdx.x) * 4;
    if (i >= n) return;
    const float4 v = *(const float4*)(x + i);
    float4 o;
    o.x = f2tf(v.x); o.y = f2tf(v.y); o.z = f2tf(v.z); o.w = f2tf(v.w);
    *(float4*)(r + i) = o;
}

// ---------------- embedding (writes x fp32 + xr tf32) ----------------
__global__ void __launch_bounds__(256) embed_kernel(
    const int* __restrict__ idx, const float* __restrict__ te,
    const float* __restrict__ pe, float* __restrict__ x, float* __restrict__ xr)
{
    const int bs = blockIdx.x;
    const int s  = bs & (S_ - 1);
    const int tok = idx[bs];
    const float4* tr = (const float4*)(te + (size_t)tok * D_);
    const float4* pr = (const float4*)(pe + (size_t)s * D_);
    float4* xo = (float4*)(x + (size_t)bs * D_);
    float4* xro = (float4*)(xr + (size_t)bs * D_);
    for (int i = threadIdx.x; i < D_ / 4; i += blockDim.x) {
        float4 t = tr[i], p = pr[i];
        float4 s4 = make_float4(t.x + p.x, t.y + p.y, t.z + p.z, t.w + p.w);
        xo[i] = s4;
        xro[i] = make_float4(f2tf(s4.x), f2tf(s4.y), f2tf(s4.z), f2tf(s4.w));
    }
}

// ---------------- layernorm (output tf32-rounded: only feeds GEMMs) --------
__device__ __forceinline__ float block_reduce_sum(float val, float* sh) {
    const int lane = threadIdx.x & 31;
    const int wid  = threadIdx.x >> 5;
#pragma unroll
    for (int o = 16; o; o >>= 1) val += __shfl_down_sync(0xffffffffu, val, o);
    if (lane == 0) sh[wid] = val;
    __syncthreads();
    const int nw = (blockDim.x + 31) >> 5;
    val = (threadIdx.x < nw) ? sh[threadIdx.x] : 0.0f;
    if (wid == 0) {
#pragma unroll
        for (int o = 16; o; o >>= 1) val += __shfl_down_sync(0xffffffffu, val, o);
        if (lane == 0) sh[0] = val;
    }
    __syncthreads();
    val = sh[0];
    __syncthreads();
    return val;
}

__global__ void __launch_bounds__(256) ln_kernel(
    const float* __restrict__ x, const float* __restrict__ g,
    const float* __restrict__ bta, float* __restrict__ out)
{
    __shared__ float red[32];
    const int row = blockIdx.x;
    const float* xr = x + (size_t)row * D_;
    float s = 0.0f, s2 = 0.0f;
    for (int i = threadIdx.x; i < D_; i += 256) {
        float v = xr[i];
        s += v; s2 += v * v;
    }
    s  = block_reduce_sum(s,  red);
    s2 = block_reduce_sum(s2, red);
    const float mean = s * (1.0f / D_);
    const float var  = s2 * (1.0f / D_) - mean * mean;
    const float rstd = rsqrtf(var + 1e-5f);
    float* orow = out + (size_t)row * D_;
    for (int i = threadIdx.x; i < D_; i += 256)
        orow[i] = f2tf((xr[i] - mean) * rstd * g[i] + bta[i]);
}

// ---------------- attention: 8 queries/block, smem-tiled K/V ----------------
// block = 8 warps; warp w -> query s = blockIdx.x*8 + w of head blockIdx.y, batch z.
// K/V staged through a 128-row x 64-col smem chunk (row stride 68 floats:
// conflict-free for both float4 row reads and float2 column reads).
#define ATT_STRIDE 68
#define ATT_SMEM ((128 * ATT_STRIDE + 8 * S_ + 8 * DK_) * 4)   // 69632 B

__global__ void __launch_bounds__(256) attn_kernel(
    const float* __restrict__ q, const float* __restrict__ k,
    const float* __restrict__ v, float* __restrict__ y)
{
    extern __shared__ float asmem[];
    float* Kb = asmem;                         // [128][68]
    float* sp = asmem + 128 * ATT_STRIDE;      // [8][1024]
    float* qs = sp + 8 * S_;                   // [8][64]
    const int tid = threadIdx.x, wid = tid >> 5, lane = tid & 31;
    const int s0 = blockIdx.x * 8;
    const int s = s0 + wid;
    const int h = blockIdx.y, b = blockIdx.z;
    const size_t base = (size_t)b * S_ * D_ + (size_t)h * DK_;

    {
        const float2 qv = *(const float2*)(q + base + (size_t)s * D_ + lane * 2);
        qs[wid * DK_ + lane * 2]     = qv.x;
        qs[wid * DK_ + lane * 2 + 1] = qv.y;
    }
    __syncwarp();

    const int nkmax = s0 + 8;   // rows 0..s0+7 needed by this block
    float lmax = -INFINITY;

    // phase 1: scores
    for (int c0 = 0; c0 < nkmax; c0 += 128) {
        __syncthreads();
#pragma unroll
        for (int i = 0; i < 8; i++) {
            const int ch = tid + (i << 8);            // 0..2047
            const int row = ch >> 4, q4 = (ch & 15) * 4;
            *(float4*)(Kb + row * ATT_STRIDE + q4) =
                *(const float4*)(k + base + (size_t)(c0 + row) * D_ + q4);
        }
        __syncthreads();
        const int lim = min(c0 + 128, s + 1);
        for (int t = c0 + lane; t < lim; t += 32) {
            const float* kr = Kb + (t - c0) * ATT_STRIDE;
            float d = 0.0f;
#pragma unroll
            for (int i = 0; i < DK_; i += 4) {
                const float4 kv = *(const float4*)(kr + i);
                d += qs[wid * DK_ + i] * kv.x + qs[wid * DK_ + i + 1] * kv.y
                   + qs[wid * DK_ + i + 2] * kv.z + qs[wid * DK_ + i + 3] * kv.w;
            }
            d *= 0.125f;
            sp[wid * S_ + t] = d;
            lmax = fmaxf(lmax, d);
        }
    }
#pragma unroll
    for (int o = 16; o; o >>= 1) lmax = fmaxf(lmax, __shfl_xor_sync(0xffffffffu, lmax, o));

    float lsum = 0.0f;
    for (int t = lane; t < s + 1; t += 32) {
        const float e = expf(sp[wid * S_ + t] - lmax);
        sp[wid * S_ + t] = e;
        lsum += e;
    }
#pragma unroll
    for (int o = 16; o; o >>= 1) lsum += __shfl_xor_sync(0xffffffffu, lsum, o);
    const float inv = 1.0f / lsum;
    __syncwarp();

    // phase 2: V accumulation (each lane owns 2 dims)
    const int dd = lane * 2;
    float a0 = 0.0f, a1 = 0.0f;
    for (int c0 = 0; c0 < nkmax; c0 += 128) {
        __syncthreads();
#pragma unroll
        for (int i = 0; i < 8; i++) {
            const int ch = tid + (i << 8);
            const int row = ch >> 4, q4 = (ch & 15) * 4;
            *(float4*)(Kb + row * ATT_STRIDE + q4) =
                *(const float4*)(v + base + (size_t)(c0 + row) * D_ + q4);
        }
        __syncthreads();
        const int lim = min(c0 + 128, s + 1);
#pragma unroll 4
        for (int t = c0; t < lim; t++) {
            const float p = sp[wid * S_ + t];
            a0 += p * Kb[(t - c0) * ATT_STRIDE + dd];
            a1 += p * Kb[(t - c0) * ATT_STRIDE + dd + 1];
        }
    }
    // y feeds the Wo GEMM only -> write tf32-rounded
    *(float2*)(y + base + (size_t)s * D_ + dd) = make_float2(f2tf(a0 * inv), f2tf(a1 * inv));
}

// ---------------- driver ----------------
extern "C" void kernel_launch(void* const* d_in, const int* in_sizes, int n_in,
                              void* d_out, int out_size)
{
    const int*   idx   = (const int*)  d_in[0];
    const float* te    = (const float*)d_in[1];
    const float* pe    = (const float*)d_in[2];
    const float* wq    = (const float*)d_in[3];
    const float* bq    = (const float*)d_in[4];
    const float* wk    = (const float*)d_in[5];
    const float* bk    = (const float*)d_in[6];
    const float* wv    = (const float*)d_in[7];
    const float* bv    = (const float*)d_in[8];
    const float* wo    = (const float*)d_in[9];
    const float* bo    = (const float*)d_in[10];
    const float* ln2g  = (const float*)d_in[11];
    const float* ln2b  = (const float*)d_in[12];
    const float* w1    = (const float*)d_in[13];
    const float* b1    = (const float*)d_in[14];
    const float* w2    = (const float*)d_in[15];
    const float* b2    = (const float*)d_in[16];
    const float* lnfg  = (const float*)d_in[17];
    const float* lnfb  = (const float*)d_in[18];
    float* out = (float*)d_out;

    float *x, *xr, *q, *k, *v, *y, *t, *hb, *wT, *teR;
    cudaGetSymbolAddress((void**)&x,   g_x);
    cudaGetSymbolAddress((void**)&xr,  g_xr);
    cudaGetSymbolAddress((void**)&q,   g_q);
    cudaGetSymbolAddress((void**)&k,   g_k);
    cudaGetSymbolAddress((void**)&v,   g_v);
    cudaGetSymbolAddress((void**)&y,   g_y);
    cudaGetSymbolAddress((void**)&t,   g_t);
    cudaGetSymbolAddress((void**)&hb,  g_h);
    cudaGetSymbolAddress((void**)&wT,  g_wT);
    cudaGetSymbolAddress((void**)&teR, g_teR);

    cudaFuncSetAttribute(mma_gemm<false, false, false, false>, cudaFuncAttributeMaxDynamicSharedMemorySize, GEMM_SMEM);
    cudaFuncSetAttribute(mma_gemm<false, true , false, false>, cudaFuncAttributeMaxDynamicSharedMemorySize, GEMM_SMEM);
    cudaFuncSetAttribute(mma_gemm<true , false, true , false>, cudaFuncAttributeMaxDynamicSharedMemorySize, GEMM_SMEM);
    cudaFuncSetAttribute(mma_gemm<false, true , false, true >, cudaFuncAttributeMaxDynamicSharedMemorySize, GEMM_SMEM);
    cudaFuncSetAttribute(attn_kernel, cudaFuncAttributeMaxDynamicSharedMemorySize, ATT_SMEM);

    const int M = M_TOK;

    // prep: 4 launches before the first GEMM (keeps ncu -s 5 on mma_gemm)
    embed_kernel<<<M, 256>>>(idx, te, pe, x, xr);
    tDD_kernel<<<dim3(D_ / 32, D_ / 32, 4 * L_), 256>>>(wq, wk, wv, wo, wT);
    tW1_kernel<<<dim3(DFF_ / 32, D_ / 32, L_), 256>>>(w1, wT);
    tW2_kernel<<<dim3(D_ / 32, DFF_ / 32, L_), 256>>>(w2, wT);

    const dim3 gDD(D_ / 128, M / 128);     // 8 x 16
    const dim3 gDF(DFF_ / 128, M / 128);   // 32 x 16
    const dim3 gLM((V_ + 127) / 128, M / 128);
    const dim3 gAT(S_ / 8, H_, B_);

    for (int l = 0; l < L_; l++) {
        const size_t lw = (size_t)l * LAYER_WELEMS;
        const float *wqT = wT + lw;
        const float *wkT = wT + lw + 1 * D_ * D_;
        const float *wvT = wT + lw + 2 * D_ * D_;
        const float *woT = wT + lw + 3 * D_ * D_;
        const float *w1T = wT + lw + 4 * D_ * D_;
        const float *w2T = w1T + (size_t)D_ * DFF_;

        mma_gemm<false, false, false, false><<<gDD, 256, GEMM_SMEM>>>(xr, wqT, bq + (size_t)l * D_, nullptr, q, nullptr, M, D_, D_);
        mma_gemm<false, false, false, false><<<gDD, 256, GEMM_SMEM>>>(xr, wkT, bk + (size_t)l * D_, nullptr, k, nullptr, M, D_, D_);
        mma_gemm<false, false, false, false><<<gDD, 256, GEMM_SMEM>>>(xr, wvT, bv + (size_t)l * D_, nullptr, v, nullptr, M, D_, D_);

        attn_kernel<<<gAT, 256, ATT_SMEM>>>(q, k, v, y);

        // x = x + y@Wo + bo (fp32; y pre-rounded by attn)
        mma_gemm<false, true, false, false><<<gDD, 256, GEMM_SMEM>>>(y, woT, bo + (size_t)l * D_, x, x, nullptr, M, D_, D_);

        // t = round(LN(x))
        ln_kernel<<<M, 256>>>(x, ln2g + (size_t)l * D_, ln2b + (size_t)l * D_, t);

        // hb = round(gelu(t@W1 + b1))
        mma_gemm<true, false, true, false><<<gDF, 256, GEMM_SMEM>>>(t, w1T, b1 + (size_t)l * DFF_, nullptr, hb, nullptr, M, DFF_, D_);

        // x = x + hb@W2 + b2 (fp32) and xr = round(x) for next layer's QKV
        mma_gemm<false, true, false, true><<<gDD, 256, GEMM_SMEM>>>(hb, w2T, b2 + (size_t)l * D_, x, x, xr, M, D_, DFF_);
    }

    // final LN + weight-tied LM head (te rounded into teR just-in-time)
    ln_kernel<<<M, 256>>>(x, lnfg, lnfb, t);
    round_kernel<<<(V_ * D_ / 4 + 255) / 256, 256>>>(te, teR, V_ * D_);
    mma_gemm<false, false, false, false><<<gLM, 256, GEMM_SMEM>>>(t, teR, nullptr, nullptr, out, nullptr, M, V_, D_);
}

// round 7
// speedup vs baseline: 3.6741x; 1.0041x over previous
#include <cuda_runtime.h>
#include <math.h>
#include <stdint.h>

// Problem constants
#define B_ 2
#define S_ 1024
#define D_ 1024
#define H_ 16
#define DK_ 64
#define DFF_ 4096
#define L_ 4
#define V_ 50257
#define M_TOK (B_ * S_)   // 2048 rows
#define QKV3 (3 * D_)     // 3072

// ---------------- scratch (static device globals; no allocation allowed) ----
__device__ float g_x[M_TOK * D_];       // residual stream (fp32)
__device__ float g_xr[M_TOK * D_];      // tf32-rounded copy of x
__device__ float g_qkv[M_TOK * QKV3];   // fused q|k|v (tf32-valued)
__device__ float g_y[M_TOK * D_];       // attention out (tf32-rounded)
__device__ float g_t[M_TOK * D_];       // ln out (tf32-rounded)
__device__ float g_h[M_TOK * DFF_];     // mlp hidden (tf32-rounded)

// transposed + tf32-rounded weights: per layer [wqT][wkT][wvT][woT][w1T][w2T]
#define LAYER_WELEMS (4 * D_ * D_ + D_ * DFF_ + DFF_ * D_)
__device__ float g_wT[(size_t)L_ * LAYER_WELEMS];
__device__ float g_bqkv[L_ * QKV3];     // packed qkv bias
__device__ float g_teR[(size_t)V_ * D_]; // tf32-rounded token embedding

// ---------------- PTX helpers (sm_80+ portable only) ----------------
__device__ __forceinline__ uint32_t smem_u32(const void* p) {
    uint32_t a;
    asm("{ .reg .u64 t; cvta.to.shared.u64 t, %1; cvt.u32.u64 %0, t; }" : "=r"(a) : "l"(p));
    return a;
}
__device__ __forceinline__ void cp_async16(uint32_t dst, const void* src, int szbytes) {
    asm volatile("cp.async.cg.shared.global [%0], [%1], 16, %2;" :: "r"(dst), "l"(src), "r"(szbytes));
}
__device__ __forceinline__ void cp_commit() { asm volatile("cp.async.commit_group;" ::: "memory"); }
template<int N> __device__ __forceinline__ void cp_wait() { asm volatile("cp.async.wait_group %0;" :: "n"(N) : "memory"); }

__device__ __forceinline__ void ldsm_x4(uint32_t& r0, uint32_t& r1, uint32_t& r2, uint32_t& r3, uint32_t addr) {
    asm volatile("ldmatrix.sync.aligned.m8n8.x4.shared.b16 {%0,%1,%2,%3}, [%4];"
                 : "=r"(r0), "=r"(r1), "=r"(r2), "=r"(r3) : "r"(addr));
}
// fp32 -> tf32 round-to-nearest (unbiased)
__device__ __forceinline__ float f2tf(float x) {
    uint32_t r;
    asm("cvt.rna.tf32.f32 %0, %1;" : "=r"(r) : "f"(x));
    return __uint_as_float(r);
}
__device__ __forceinline__ void mma1688_tf32(float* c, const uint32_t* a, uint32_t b0, uint32_t b1) {
    asm volatile("mma.sync.aligned.m16n8k8.row.col.f32.tf32.tf32.f32 "
                 "{%0,%1,%2,%3}, {%4,%5,%6,%7}, {%8,%9}, {%0,%1,%2,%3};"
                 : "+f"(c[0]), "+f"(c[1]), "+f"(c[2]), "+f"(c[3])
                 : "r"(a[0]), "r"(a[1]), "r"(a[2]), "r"(a[3]), "r"(b0), "r"(b1));
}

#define SW128(o) ((o) ^ (((o) >> 3) & 0x70))

// ---------------- TF32 GEMM (inputs pre-rounded to tf32) ----------------
// C[M,N] = act( A[M,K] @ B[N,K]^T + bias ) (+ res), fp32 accum.
// CTA tile 128 x BN, BK=32 fp32 (128B SW128 rows), 3-stage cp.async pipeline
// with ONE barrier per chunk. Warp tile 64x32; warps = 2 x (BN/32).
// Grid: blockIdx.x = M-block (fastest -> B-tile L2 reuse), blockIdx.y = N-block.
// M % 128 == 0, K % 32 == 0; N tail OK (clamp+zfill, scalar store guard).

template<int BN> struct GemmCfg {
    static constexpr int NT    = (BN == 128) ? 256 : 512;   // threads
    static constexpr int OCC   = (BN == 128) ? 2 : 1;
    static constexpr int STAGE = 16384 + BN * 128;          // bytes per stage
    static constexpr int SMEM  = 3 * STAGE;
};

template<int BN, bool GELU_, bool RES_, bool ROUND_, bool WR_>
__global__ void __launch_bounds__(GemmCfg<BN>::NT, GemmCfg<BN>::OCC)
mma_gemm(const float* __restrict__ A, const float* __restrict__ Bm,
         const float* __restrict__ bias, const float* __restrict__ res,
         float* __restrict__ C, float* __restrict__ Cr, int M, int N, int K)
{
    constexpr int NT = GemmCfg<BN>::NT;
    constexpr int STAGE = GemmCfg<BN>::STAGE;
    extern __shared__ __align__(1024) char smem_raw[];
    const uint32_t sb = smem_u32(smem_raw);
    const int tid = threadIdx.x, wid = tid >> 5, lane = tid & 31;
    const int bm = blockIdx.x << 7, bn = blockIdx.y * BN;
    const int wr = wid & 1, wc = wid >> 1;            // 2 x (BN/32) warp grid
    const int rl = lane & 15, qh = lane >> 4;         // A-frag ldmatrix addressing
    const int brl = (lane & 7) + ((lane & 16) >> 1);  // B-frag row
    const int bqh = (lane >> 3) & 1;                  // B-frag chunk parity

    float acc[4][4][4];
#pragma unroll
    for (int i = 0; i < 4; i++)
#pragma unroll
        for (int j = 0; j < 4; j++)
#pragma unroll
            for (int r = 0; r < 4; r++) acc[i][j][r] = 0.0f;

    auto load_chunk = [&](int c, int stage) {
        const int k0 = c << 5;
        const uint32_t sA = sb + (uint32_t)stage * STAGE;
        const uint32_t sB = sA + 16384;
#pragma unroll
        for (int ch = tid; ch < 1024; ch += NT) {
            const int r = ch >> 3, qd = ch & 7;
            cp_async16(sA + SW128((uint32_t)(r * 128 + qd * 16)),
                       A + (size_t)(bm + r) * K + k0 + qd * 4, 16);
        }
#pragma unroll
        for (int ch = tid; ch < BN * 8; ch += NT) {
            const int r = ch >> 3, qd = ch & 7;
            const int gn = bn + r;
            const int vn = gn < N ? gn : N - 1;
            const int vsz = gn < N ? 16 : 0;
            cp_async16(sB + SW128((uint32_t)(r * 128 + qd * 16)),
                       Bm + (size_t)vn * K + k0 + qd * 4, vsz);
        }
    };

    const int NC = K >> 5;
    load_chunk(0, 0);
    cp_commit();
    if (NC > 1) { load_chunk(1, 1); cp_commit(); }

    int buf = 0, nxt = 2;
    for (int c = 0; c < NC; c++) {
        if (c + 1 < NC) cp_wait<1>(); else cp_wait<0>();
        __syncthreads();

        const uint32_t tA = sb + (uint32_t)buf * STAGE;
        const uint32_t tB = tA + 16384;
#pragma unroll
        for (int s = 0; s < 4; s++) {             // 4 k8 steps per 32-K chunk
            uint32_t a[4][4], b[2][4];
#pragma unroll
            for (int i = 0; i < 4; i++) {
                const uint32_t off = SW128((uint32_t)((wr * 64 + i * 16 + rl) * 128 + (2 * s + qh) * 16));
                ldsm_x4(a[i][0], a[i][1], a[i][2], a[i][3], tA + off);
            }
#pragma unroll
            for (int p = 0; p < 2; p++) {
                const uint32_t off = SW128((uint32_t)((wc * 32 + p * 16 + brl) * 128 + (2 * s + bqh) * 16));
                ldsm_x4(b[p][0], b[p][1], b[p][2], b[p][3], tB + off);
            }
#pragma unroll
            for (int i = 0; i < 4; i++)
#pragma unroll
                for (int j = 0; j < 4; j++)
                    mma1688_tf32(acc[i][j], a[i], b[j >> 1][(j & 1) * 2], b[j >> 1][(j & 1) * 2 + 1]);
        }

        if (c + 2 < NC) { load_chunk(c + 2, nxt); cp_commit(); }
        buf = buf == 2 ? 0 : buf + 1;
        nxt = nxt == 2 ? 0 : nxt + 1;
    }

    // epilogue (scalar stores: N may be odd)
    const int quad = lane >> 2, tq = lane & 3;
#pragma unroll
    for (int i = 0; i < 4; i++) {
        const int m0 = bm + wr * 64 + i * 16 + quad;
#pragma unroll
        for (int j = 0; j < 4; j++) {
            const int n0 = bn + wc * 32 + j * 8 + tq * 2;
#pragma unroll
            for (int half = 0; half < 2; half++) {
                const int m = m0 + half * 8;
                float c0 = acc[i][j][half * 2 + 0];
                float c1 = acc[i][j][half * 2 + 1];
                if (bias) { c0 += bias[n0]; c1 += bias[n0 + 1]; }
                if (GELU_) {
                    c0 = 0.5f * c0 * (1.0f + erff(c0 * 0.70710678118654752f));
                    c1 = 0.5f * c1 * (1.0f + erff(c1 * 0.70710678118654752f));
                }
                if (RES_) {
                    c0 += res[(size_t)m * N + n0];
                    c1 += res[(size_t)m * N + n0 + 1];
                }
                float s0 = ROUND_ ? f2tf(c0) : c0;
                float s1 = ROUND_ ? f2tf(c1) : c1;
                if (n0 < N)     C[(size_t)m * N + n0]     = s0;
                if (n0 + 1 < N) C[(size_t)m * N + n0 + 1] = s1;
                if (WR_) {
                    if (n0 < N)     Cr[(size_t)m * N + n0]     = f2tf(c0);
                    if (n0 + 1 < N) Cr[(size_t)m * N + n0 + 1] = f2tf(c1);
                }
            }
        }
    }
}

// ---------------- weight prep ----------------
// all 16 DxD matrices (z = layer*4 + {q,k,v,o}); also packs qkv bias on by==0
__global__ void __launch_bounds__(256) tDD_kernel(
    const float* __restrict__ wq, const float* __restrict__ wk,
    const float* __restrict__ wv, const float* __restrict__ wo,
    const float* __restrict__ bq, const float* __restrict__ bk,
    const float* __restrict__ bv, float* __restrict__ wT, float* __restrict__ bqkv)
{
    __shared__ float tile[32][33];
    const int m = blockIdx.z, l = m >> 2, which = m & 3;
    const float* W = (which == 0 ? wq : which == 1 ? wk : which == 2 ? wv : wo)
                     + (size_t)l * D_ * D_;
    float* WT = wT + (size_t)l * LAYER_WELEMS + (size_t)which * D_ * D_;
    const int tx = threadIdx.x & 31, ty = threadIdx.x >> 5;
    const int k0 = blockIdx.y << 5, n0 = blockIdx.x << 5;
#pragma unroll
    for (int i = 0; i < 4; i++)
        tile[ty + i * 8][tx] = W[(size_t)(k0 + ty + i * 8) * D_ + n0 + tx];
    __syncthreads();
#pragma unroll
    for (int i = 0; i < 4; i++)
        WT[(size_t)(n0 + ty + i * 8) * D_ + k0 + tx] = f2tf(tile[tx][ty + i * 8]);
    if (blockIdx.y == 0 && which < 3 && threadIdx.x < 32) {
        const float* bsrc = which == 0 ? bq : which == 1 ? bk : bv;
        bqkv[l * QKV3 + which * D_ + n0 + threadIdx.x] = bsrc[l * D_ + n0 + threadIdx.x];
    }
}

// w1 [D, DFF] -> [DFF, D] and w2 [DFF, D] -> [D, DFF], all layers in one launch.
// grid (128, 64, L): by<32 -> w1 tile; by>=32 -> w2 tile via flattened id.
__global__ void __launch_bounds__(256) tFF_kernel(
    const float* __restrict__ w1, const float* __restrict__ w2, float* __restrict__ wT)
{
    __shared__ float tile[32][33];
    const int l = blockIdx.z;
    const int tx = threadIdx.x & 31, ty = threadIdx.x >> 5;
    const float* W; float* WT; int Kd, Nd, k0, n0;
    if (blockIdx.y < 32) {
        W = w1 + (size_t)l * D_ * DFF_;
        WT = wT + (size_t)l * LAYER_WELEMS + (size_t)4 * D_ * D_;
        Kd = D_; Nd = DFF_;
        k0 = blockIdx.y << 5; n0 = blockIdx.x << 5;
    } else {
        const int id = blockIdx.x + ((blockIdx.y - 32) << 7);  // 0..4095
        W = w2 + (size_t)l * DFF_ * D_;
        WT = wT + (size_t)l * LAYER_WELEMS + (size_t)4 * D_ * D_ + (size_t)D_ * DFF_;
        Kd = DFF_; Nd = D_;
        k0 = (id >> 5) << 5; n0 = (id & 31) << 5;
    }
#pragma unroll
    for (int i = 0; i < 4; i++)
        tile[ty + i * 8][tx] = W[(size_t)(k0 + ty + i * 8) * Nd + n0 + tx];
    __syncthreads();
#pragma unroll
    for (int i = 0; i < 4; i++)
        WT[(size_t)(n0 + ty + i * 8) * Kd + k0 + tx] = f2tf(tile[tx][ty + i * 8]);
}

// elementwise tf32 round (te -> teR); n % 4 == 0
__global__ void __launch_bounds__(256) round_kernel(
    const float* __restrict__ x, float* __restrict__ r, int n)
{
    const int i = (blockIdx.x * 256 + threadIdx.x) * 4;
    if (i >= n) return;
    const float4 v = *(const float4*)(x + i);
    float4 o;
    o.x = f2tf(v.x); o.y = f2tf(v.y); o.z = f2tf(v.z); o.w = f2tf(v.w);
    *(float4*)(r + i) = o;
}

// ---------------- embedding (x fp32 + xr tf32) ----------------
__global__ void __launch_bounds__(256) embed_kernel(
    const int* __restrict__ idx, const float* __restrict__ te,
    const float* __restrict__ pe, float* __restrict__ x, float* __restrict__ xr)
{
    const int bs = blockIdx.x;
    const int s  = bs & (S_ - 1);
    const int tok = idx[bs];
    const float4* tr = (const float4*)(te + (size_t)tok * D_);
    const float4* pr = (const float4*)(pe + (size_t)s * D_);
    float4* xo = (float4*)(x + (size_t)bs * D_);
    float4* xro = (float4*)(xr + (size_t)bs * D_);
    for (int i = threadIdx.x; i < D_ / 4; i += blockDim.x) {
        float4 t = tr[i], p = pr[i];
        float4 s4 = make_float4(t.x + p.x, t.y + p.y, t.z + p.z, t.w + p.w);
        xo[i] = s4;
        xro[i] = make_float4(f2tf(s4.x), f2tf(s4.y), f2tf(s4.z), f2tf(s4.w));
    }
}

// ---------------- layernorm (tf32-rounded out) ----------------
__device__ __forceinline__ float block_reduce_sum(float val, float* sh) {
    const int lane = threadIdx.x & 31;
    const int wid  = threadIdx.x >> 5;
#pragma unroll
    for (int o = 16; o; o >>= 1) val += __shfl_down_sync(0xffffffffu, val, o);
    if (lane == 0) sh[wid] = val;
    __syncthreads();
    const int nw = (blockDim.x + 31) >> 5;
    val = (threadIdx.x < nw) ? sh[threadIdx.x] : 0.0f;
    if (wid == 0) {
#pragma unroll
        for (int o = 16; o; o >>= 1) val += __shfl_down_sync(0xffffffffu, val, o);
        if (lane == 0) sh[0] = val;
    }
    __syncthreads();
    val = sh[0];
    __syncthreads();
    return val;
}

__global__ void __launch_bounds__(256) ln_kernel(
    const float* __restrict__ x, const float* __restrict__ g,
    const float* __restrict__ bta, float* __restrict__ out)
{
    __shared__ float red[32];
    const int row = blockIdx.x;
    const float* xr = x + (size_t)row * D_;
    float s = 0.0f, s2 = 0.0f;
    for (int i = threadIdx.x; i < D_; i += 256) {
        float v = xr[i];
        s += v; s2 += v * v;
    }
    s  = block_reduce_sum(s,  red);
    s2 = block_reduce_sum(s2, red);
    const float mean = s * (1.0f / D_);
    const float var  = s2 * (1.0f / D_) - mean * mean;
    const float rstd = rsqrtf(var + 1e-5f);
    float* orow = out + (size_t)row * D_;
    for (int i = threadIdx.x; i < D_; i += 256)
        orow[i] = f2tf((xr[i] - mean) * rstd * g[i] + bta[i]);
}

// ---------------- attention: 8 queries/block, smem-tiled K/V ----------------
// reads fused qkv [M, 3072]: q at col 0, k at 1024, v at 2048 (head h at +h*64)
#define ATT_STRIDE 68
#define ATT_SMEM ((128 * ATT_STRIDE + 8 * S_ + 8 * DK_) * 4)   // 69632 B

__global__ void __launch_bounds__(256) attn_kernel(
    const float* __restrict__ qkv, float* __restrict__ y)
{
    extern __shared__ float asmem[];
    float* Kb = asmem;                         // [128][68]
    float* sp = asmem + 128 * ATT_STRIDE;      // [8][1024]
    float* qs = sp + 8 * S_;                   // [8][64]
    const int tid = threadIdx.x, wid = tid >> 5, lane = tid & 31;
    const int s0 = blockIdx.x * 8;
    const int s = s0 + wid;
    const int h = blockIdx.y, b = blockIdx.z;
    const size_t base = (size_t)b * S_ * QKV3 + (size_t)h * DK_;
    const float* kp = qkv + base + D_;
    const float* vp = qkv + base + 2 * D_;

    {
        const float2 qv = *(const float2*)(qkv + base + (size_t)s * QKV3 + lane * 2);
        qs[wid * DK_ + lane * 2]     = qv.x;
        qs[wid * DK_ + lane * 2 + 1] = qv.y;
    }
    __syncwarp();

    const int nkmax = s0 + 8;
    float lmax = -INFINITY;

    // phase 1: scores
    for (int c0 = 0; c0 < nkmax; c0 += 128) {
        __syncthreads();
#pragma unroll
        for (int i = 0; i < 8; i++) {
            const int ch = tid + (i << 8);
            const int row = ch >> 4, q4 = (ch & 15) * 4;
            *(float4*)(Kb + row * ATT_STRIDE + q4) =
                *(const float4*)(kp + (size_t)(c0 + row) * QKV3 + q4);
        }
        __syncthreads();
        const int lim = min(c0 + 128, s + 1);
        for (int t = c0 + lane; t < lim; t += 32) {
            const float* kr = Kb + (t - c0) * ATT_STRIDE;
            float d = 0.0f;
#pragma unroll
            for (int i = 0; i < DK_; i += 4) {
                const float4 kv = *(const float4*)(kr + i);
                d += qs[wid * DK_ + i] * kv.x + qs[wid * DK_ + i + 1] * kv.y
                   + qs[wid * DK_ + i + 2] * kv.z + qs[wid * DK_ + i + 3] * kv.w;
            }
            d *= 0.125f;
            sp[wid * S_ + t] = d;
            lmax = fmaxf(lmax, d);
        }
    }
#pragma unroll
    for (int o = 16; o; o >>= 1) lmax = fmaxf(lmax, __shfl_xor_sync(0xffffffffu, lmax, o));

    float lsum = 0.0f;
    for (int t = lane; t < s + 1; t += 32) {
        const float e = expf(sp[wid * S_ + t] - lmax);
        sp[wid * S_ + t] = e;
        lsum += e;
    }
#pragma unroll
    for (int o = 16; o; o >>= 1) lsum += __shfl_xor_sync(0xffffffffu, lsum, o);
    const float inv = 1.0f / lsum;
    __syncwarp();

    // phase 2: V accumulation
    const int dd = lane * 2;
    float a0 = 0.0f, a1 = 0.0f;
    for (int c0 = 0; c0 < nkmax; c0 += 128) {
        __syncthreads();
#pragma unroll
        for (int i = 0; i < 8; i++) {
            const int ch = tid + (i << 8);
            const int row = ch >> 4, q4 = (ch & 15) * 4;
            *(float4*)(Kb + row * ATT_STRIDE + q4) =
                *(const float4*)(vp + (size_t)(c0 + row) * QKV3 + q4);
        }
        __syncthreads();
        const int lim = min(c0 + 128, s + 1);
#pragma unroll 4
        for (int t = c0; t < lim; t++) {
            const float p = sp[wid * S_ + t];
            a0 += p * Kb[(t - c0) * ATT_STRIDE + dd];
            a1 += p * Kb[(t - c0) * ATT_STRIDE + dd + 1];
        }
    }
    *(float2*)(y + (size_t)b * S_ * D_ + (size_t)h * DK_ + (size_t)s * D_ + dd) =
        make_float2(f2tf(a0 * inv), f2tf(a1 * inv));
}

// ---------------- driver ----------------
extern "C" void kernel_launch(void* const* d_in, const int* in_sizes, int n_in,
                              void* d_out, int out_size)
{
    const int*   idx   = (const int*)  d_in[0];
    const float* te    = (const float*)d_in[1];
    const float* pe    = (const float*)d_in[2];
    const float* wq    = (const float*)d_in[3];
    const float* bq    = (const float*)d_in[4];
    const float* wk    = (const float*)d_in[5];
    const float* bk    = (const float*)d_in[6];
    const float* wv    = (const float*)d_in[7];
    const float* bv    = (const float*)d_in[8];
    const float* wo    = (const float*)d_in[9];
    const float* bo    = (const float*)d_in[10];
    const float* ln2g  = (const float*)d_in[11];
    const float* ln2b  = (const float*)d_in[12];
    const float* w1    = (const float*)d_in[13];
    const float* b1    = (const float*)d_in[14];
    const float* w2    = (const float*)d_in[15];
    const float* b2    = (const float*)d_in[16];
    const float* lnfg  = (const float*)d_in[17];
    const float* lnfb  = (const float*)d_in[18];
    float* out = (float*)d_out;

    float *x, *xr, *qkv, *y, *t, *hb, *wT, *bqkv, *teR;
    cudaGetSymbolAddress((void**)&x,    g_x);
    cudaGetSymbolAddress((void**)&xr,   g_xr);
    cudaGetSymbolAddress((void**)&qkv,  g_qkv);
    cudaGetSymbolAddress((void**)&y,    g_y);
    cudaGetSymbolAddress((void**)&t,    g_t);
    cudaGetSymbolAddress((void**)&hb,   g_h);
    cudaGetSymbolAddress((void**)&wT,   g_wT);
    cudaGetSymbolAddress((void**)&bqkv, g_bqkv);
    cudaGetSymbolAddress((void**)&teR,  g_teR);

    constexpr int SM128 = GemmCfg<128>::SMEM;   // 96 KB
    constexpr int SM256 = GemmCfg<256>::SMEM;   // 144 KB
    cudaFuncSetAttribute(mma_gemm<128, false, false, false, false>, cudaFuncAttributeMaxDynamicSharedMemorySize, SM128);
    cudaFuncSetAttribute(mma_gemm<128, false, true , false, false>, cudaFuncAttributeMaxDynamicSharedMemorySize, SM128);
    cudaFuncSetAttribute(mma_gemm<128, true , false, true , false>, cudaFuncAttributeMaxDynamicSharedMemorySize, SM128);
    cudaFuncSetAttribute(mma_gemm<128, false, true , false, true >, cudaFuncAttributeMaxDynamicSharedMemorySize, SM128);
    cudaFuncSetAttribute(mma_gemm<256, false, false, false, false>, cudaFuncAttributeMaxDynamicSharedMemorySize, SM256);
    cudaFuncSetAttribute(attn_kernel, cudaFuncAttributeMaxDynamicSharedMemorySize, ATT_SMEM);

    const int M = M_TOK;

    // prep (3 launches; keeps ncu -s 5 landing on the first mma_gemm)
    embed_kernel<<<M, 256>>>(idx, te, pe, x, xr);
    tDD_kernel<<<dim3(32, 32, 4 * L_), 256>>>(wq, wk, wv, wo, bq, bk, bv, wT, bqkv);
    tFF_kernel<<<dim3(128, 64, L_), 256>>>(w1, w2, wT);

    // grids: blockIdx.x = M-block (fastest), blockIdx.y = N-block
    const dim3 gQKV(M / 128, QKV3 / 128);   // 16 x 24
    const dim3 gDD (M / 128, D_ / 128);     // 16 x 8
    const dim3 gDF (M / 128, DFF_ / 128);   // 16 x 32
    const dim3 gLM (M / 128, (V_ + 255) / 256);  // 16 x 197
    const dim3 gAT (S_ / 8, H_, B_);

    for (int l = 0; l < L_; l++) {
        const size_t lw = (size_t)l * LAYER_WELEMS;
        const float *wqkvT = wT + lw;                      // wq|wk|wv contiguous
        const float *woT   = wT + lw + 3 * D_ * D_;
        const float *w1T   = wT + lw + 4 * D_ * D_;
        const float *w2T   = w1T + (size_t)D_ * DFF_;

        // fused qkv = xr @ [Wq|Wk|Wv] + bqkv
        mma_gemm<128, false, false, false, false><<<gQKV, 256, SM128>>>(
            xr, wqkvT, bqkv + l * QKV3, nullptr, qkv, nullptr, M, QKV3, D_);

        attn_kernel<<<gAT, 256, ATT_SMEM>>>(qkv, y);

        // x = x + y@Wo + bo
        mma_gemm<128, false, true, false, false><<<gDD, 256, SM128>>>(
            y, woT, bo + (size_t)l * D_, x, x, nullptr, M, D_, D_);

        // t = round(LN(x))
        ln_kernel<<<M, 256>>>(x, ln2g + (size_t)l * D_, ln2b + (size_t)l * D_, t);

        // hb = round(gelu(t@W1 + b1))
        mma_gemm<128, true, false, true, false><<<gDF, 256, SM128>>>(
            t, w1T, b1 + (size_t)l * DFF_, nullptr, hb, nullptr, M, DFF_, D_);

        // x = x + hb@W2 + b2 ; xr = round(x)
        mma_gemm<128, false, true, false, true><<<gDD, 256, SM128>>>(
            hb, w2T, b2 + (size_t)l * D_, x, x, xr, M, D_, DFF_);
    }

    // final LN + weight-tied LM head (wide tile)
    ln_kernel<<<M, 256>>>(x, lnfg, lnfb, t);
    round_kernel<<<(V_ * D_ / 4 + 255) / 256, 256>>>(te, teR, V_ * D_);
    mma_gemm<256, false, false, false, false><<<gLM, 512, SM256>>>(
        t, teR, nullptr, nullptr, out, nullptr, M, V_, D_);
}

// round 8
// speedup vs baseline: 3.7603x; 1.0234x over previous
#include <cuda_runtime.h>
#include <math.h>
#include <stdint.h>

// Problem constants
#define B_ 2
#define S_ 1024
#define D_ 1024
#define H_ 16
#define DK_ 64
#define DFF_ 4096
#define L_ 4
#define V_ 50257
#define M_TOK (B_ * S_)   // 2048 rows
#define QKV3 (3 * D_)     // 3072

// ---------------- scratch (static device globals; no allocation allowed) ----
__device__ float g_x[M_TOK * D_];       // residual stream (fp32)
__device__ float g_xr[M_TOK * D_];      // tf32-rounded copy of x
__device__ float g_qkv[M_TOK * QKV3];   // fused q|k|v (tf32-valued)
__device__ float g_y[M_TOK * D_];       // attention out (tf32-rounded)
__device__ float g_t[M_TOK * D_];       // ln out (tf32-rounded)
__device__ float g_h[M_TOK * DFF_];     // mlp hidden (tf32-rounded)

// transposed + tf32-rounded weights: per layer [wqT][wkT][wvT][woT][w1T][w2T]
#define LAYER_WELEMS (4 * D_ * D_ + D_ * DFF_ + DFF_ * D_)
__device__ float g_wT[(size_t)L_ * LAYER_WELEMS];
__device__ float g_bqkv[L_ * QKV3];      // packed qkv bias
__device__ float g_teR[(size_t)V_ * D_]; // tf32-rounded token embedding

// ---------------- PTX helpers (sm_80+ portable only) ----------------
__device__ __forceinline__ uint32_t smem_u32(const void* p) {
    uint32_t a;
    asm("{ .reg .u64 t; cvta.to.shared.u64 t, %1; cvt.u32.u64 %0, t; }" : "=r"(a) : "l"(p));
    return a;
}
__device__ __forceinline__ void cp_async16(uint32_t dst, const void* src, int szbytes) {
    asm volatile("cp.async.cg.shared.global [%0], [%1], 16, %2;" :: "r"(dst), "l"(src), "r"(szbytes));
}
__device__ __forceinline__ void cp_commit() { asm volatile("cp.async.commit_group;" ::: "memory"); }
template<int N> __device__ __forceinline__ void cp_wait() { asm volatile("cp.async.wait_group %0;" :: "n"(N) : "memory"); }

__device__ __forceinline__ void ldsm_x4(uint32_t& r0, uint32_t& r1, uint32_t& r2, uint32_t& r3, uint32_t addr) {
    asm volatile("ldmatrix.sync.aligned.m8n8.x4.shared.b16 {%0,%1,%2,%3}, [%4];"
                 : "=r"(r0), "=r"(r1), "=r"(r2), "=r"(r3) : "r"(addr));
}
// fp32 -> tf32 round-to-nearest (unbiased)
__device__ __forceinline__ float f2tf(float x) {
    uint32_t r;
    asm("cvt.rna.tf32.f32 %0, %1;" : "=r"(r) : "f"(x));
    return __uint_as_float(r);
}
__device__ __forceinline__ void mma1688_tf32(float* c, const uint32_t* a, uint32_t b0, uint32_t b1) {
    asm volatile("mma.sync.aligned.m16n8k8.row.col.f32.tf32.tf32.f32 "
                 "{%0,%1,%2,%3}, {%4,%5,%6,%7}, {%8,%9}, {%0,%1,%2,%3};"
                 : "+f"(c[0]), "+f"(c[1]), "+f"(c[2]), "+f"(c[3])
                 : "r"(a[0]), "r"(a[1]), "r"(a[2]), "r"(a[3]), "r"(b0), "r"(b1));
}

#define SW128(o) ((o) ^ (((o) >> 3) & 0x70))

// ---------------- TF32 GEMM (inputs pre-rounded to tf32) ----------------
// C[M,N] = act( A[M,K] @ B[N,K]^T + bias ) (+ res), fp32 accum.
// CTA tile BM x BN, BK=32 (128B SW128 rows), 3-stage cp.async, one barrier/chunk.
// Warp tile 64 x WN; warps = (BM/64) x (BN/WN); 128 threads.
//   cfg A (wide-warp): BM=128, BN=128, WN=64 -> 4 warps 2x2, occ 2
//   cfg B (small-M)  : BM=64,  BN=128, WN=32 -> 4 warps 1x4, occ 3
// Grid: blockIdx.x = M-block (fastest), blockIdx.y = N-block.
// M % BM == 0, K % 32 == 0; N tail OK (clamp+zfill, scalar store guard).

template<int BM, int BN, int WN> struct GemmCfg {
    static constexpr int WRN   = BM / 64;              // warp rows
    static constexpr int NWARP = WRN * (BN / WN);
    static constexpr int NT    = NWARP * 32;           // 128
    static constexpr int OCC   = (BM == 64) ? 3 : 2;
    static constexpr int STAGE = (BM + BN) * 128;      // bytes per stage
    static constexpr int SMEM  = 3 * STAGE;
};

template<int BM, int BN, int WN, bool GELU_, bool RES_, bool ROUND_, bool WR_>
__global__ void __launch_bounds__((GemmCfg<BM,BN,WN>::NT), (GemmCfg<BM,BN,WN>::OCC))
mma_gemm(const float* __restrict__ A, const float* __restrict__ Bm,
         const float* __restrict__ bias, const float* __restrict__ res,
         float* __restrict__ C, float* __restrict__ Cr, int M, int N, int K)
{
    using CFG = GemmCfg<BM, BN, WN>;
    constexpr int NT = CFG::NT, STAGE = CFG::STAGE, WRN = CFG::WRN;
    constexpr int NJ = WN / 8;     // n8 tiles per warp
    constexpr int NB = WN / 16;    // B ldsm groups per warp
    constexpr int MI = BM / (WRN * 16);  // = 4 m16 tiles per warp

    extern __shared__ __align__(1024) char smem_raw[];
    const uint32_t sb = smem_u32(smem_raw);
    const int tid = threadIdx.x, wid = tid >> 5, lane = tid & 31;
    const int bm = blockIdx.x * BM, bn = blockIdx.y * BN;
    const int wr = (WRN == 1) ? 0 : (wid & (WRN - 1));
    const int wc = (WRN == 1) ? wid : (wid >> 1);
    const int rl = lane & 15, qh = lane >> 4;         // A-frag addressing
    const int brl = (lane & 7) + ((lane & 16) >> 1);  // B-frag row
    const int bqh = (lane >> 3) & 1;                  // B-frag chunk parity

    float acc[MI][NJ][4];
#pragma unroll
    for (int i = 0; i < MI; i++)
#pragma unroll
        for (int j = 0; j < NJ; j++)
#pragma unroll
            for (int r = 0; r < 4; r++) acc[i][j][r] = 0.0f;

    auto load_chunk = [&](int c, int stage) {
        const int k0 = c << 5;
        const uint32_t sA = sb + (uint32_t)stage * STAGE;
        const uint32_t sB = sA + BM * 128;
#pragma unroll
        for (int ch = tid; ch < BM * 8; ch += NT) {
            const int r = ch >> 3, qd = ch & 7;
            cp_async16(sA + SW128((uint32_t)(r * 128 + qd * 16)),
                       A + (size_t)(bm + r) * K + k0 + qd * 4, 16);
        }
#pragma unroll
        for (int ch = tid; ch < BN * 8; ch += NT) {
            const int r = ch >> 3, qd = ch & 7;
            const int gn = bn + r;
            const int vn = gn < N ? gn : N - 1;
            const int vsz = gn < N ? 16 : 0;
            cp_async16(sB + SW128((uint32_t)(r * 128 + qd * 16)),
                       Bm + (size_t)vn * K + k0 + qd * 4, vsz);
        }
    };

    const int NC = K >> 5;
    load_chunk(0, 0);
    cp_commit();
    if (NC > 1) { load_chunk(1, 1); cp_commit(); }

    int buf = 0, nxt = 2;
    for (int c = 0; c < NC; c++) {
        if (c + 1 < NC) cp_wait<1>(); else cp_wait<0>();
        __syncthreads();

        const uint32_t tA = sb + (uint32_t)buf * STAGE;
        const uint32_t tB = tA + BM * 128;
#pragma unroll
        for (int s = 0; s < 4; s++) {             // 4 k8 steps per 32-K chunk
            uint32_t a[MI][4], b[NB][4];
#pragma unroll
            for (int i = 0; i < MI; i++) {
                const uint32_t off = SW128((uint32_t)((wr * 64 + i * 16 + rl) * 128 + (2 * s + qh) * 16));
                ldsm_x4(a[i][0], a[i][1], a[i][2], a[i][3], tA + off);
            }
#pragma unroll
            for (int p = 0; p < NB; p++) {
                const uint32_t off = SW128((uint32_t)((wc * WN + p * 16 + brl) * 128 + (2 * s + bqh) * 16));
                ldsm_x4(b[p][0], b[p][1], b[p][2], b[p][3], tB + off);
            }
#pragma unroll
            for (int i = 0; i < MI; i++)
#pragma unroll
                for (int j = 0; j < NJ; j++)
                    mma1688_tf32(acc[i][j], a[i], b[j >> 1][(j & 1) * 2], b[j >> 1][(j & 1) * 2 + 1]);
        }

        if (c + 2 < NC) { load_chunk(c + 2, nxt); cp_commit(); }
        buf = buf == 2 ? 0 : buf + 1;
        nxt = nxt == 2 ? 0 : nxt + 1;
    }

    // epilogue (scalar stores: N may be odd)
    const int quad = lane >> 2, tq = lane & 3;
#pragma unroll
    for (int i = 0; i < MI; i++) {
        const int m0 = bm + wr * 64 + i * 16 + quad;
#pragma unroll
        for (int j = 0; j < NJ; j++) {
            const int n0 = bn + wc * WN + j * 8 + tq * 2;
#pragma unroll
            for (int half = 0; half < 2; half++) {
                const int m = m0 + half * 8;
                float c0 = acc[i][j][half * 2 + 0];
                float c1 = acc[i][j][half * 2 + 1];
                if (bias) { c0 += bias[n0]; c1 += bias[n0 + 1]; }
                if (GELU_) {
                    c0 = 0.5f * c0 * (1.0f + erff(c0 * 0.70710678118654752f));
                    c1 = 0.5f * c1 * (1.0f + erff(c1 * 0.70710678118654752f));
                }
                if (RES_) {
                    c0 += res[(size_t)m * N + n0];
                    c1 += res[(size_t)m * N + n0 + 1];
                }
                float s0 = ROUND_ ? f2tf(c0) : c0;
                float s1 = ROUND_ ? f2tf(c1) : c1;
                if (n0 < N)     C[(size_t)m * N + n0]     = s0;
                if (n0 + 1 < N) C[(size_t)m * N + n0 + 1] = s1;
                if (WR_) {
                    if (n0 < N)     Cr[(size_t)m * N + n0]     = f2tf(c0);
                    if (n0 + 1 < N) Cr[(size_t)m * N + n0 + 1] = f2tf(c1);
                }
            }
        }
    }
}

// ---------------- weight prep ----------------
__global__ void __launch_bounds__(256) tDD_kernel(
    const float* __restrict__ wq, const float* __restrict__ wk,
    const float* __restrict__ wv, const float* __restrict__ wo,
    const float* __restrict__ bq, const float* __restrict__ bk,
    const float* __restrict__ bv, float* __restrict__ wT, float* __restrict__ bqkv)
{
    __shared__ float tile[32][33];
    const int m = blockIdx.z, l = m >> 2, which = m & 3;
    const float* W = (which == 0 ? wq : which == 1 ? wk : which == 2 ? wv : wo)
                     + (size_t)l * D_ * D_;
    float* WT = wT + (size_t)l * LAYER_WELEMS + (size_t)which * D_ * D_;
    const int tx = threadIdx.x & 31, ty = threadIdx.x >> 5;
    const int k0 = blockIdx.y << 5, n0 = blockIdx.x << 5;
#pragma unroll
    for (int i = 0; i < 4; i++)
        tile[ty + i * 8][tx] = W[(size_t)(k0 + ty + i * 8) * D_ + n0 + tx];
    __syncthreads();
#pragma unroll
    for (int i = 0; i < 4; i++)
        WT[(size_t)(n0 + ty + i * 8) * D_ + k0 + tx] = f2tf(tile[tx][ty + i * 8]);
    if (blockIdx.y == 0 && which < 3 && threadIdx.x < 32) {
        const float* bsrc = which == 0 ? bq : which == 1 ? bk : bv;
        bqkv[l * QKV3 + which * D_ + n0 + threadIdx.x] = bsrc[l * D_ + n0 + threadIdx.x];
    }
}

__global__ void __launch_bounds__(256) tFF_kernel(
    const float* __restrict__ w1, const float* __restrict__ w2, float* __restrict__ wT)
{
    __shared__ float tile[32][33];
    const int l = blockIdx.z;
    const int tx = threadIdx.x & 31, ty = threadIdx.x >> 5;
    const float* W; float* WT; int Kd, Nd, k0, n0;
    if (blockIdx.y < 32) {
        W = w1 + (size_t)l * D_ * DFF_;
        WT = wT + (size_t)l * LAYER_WELEMS + (size_t)4 * D_ * D_;
        Kd = D_; Nd = DFF_;
        k0 = blockIdx.y << 5; n0 = blockIdx.x << 5;
    } else {
        const int id = blockIdx.x + ((blockIdx.y - 32) << 7);
        W = w2 + (size_t)l * DFF_ * D_;
        WT = wT + (size_t)l * LAYER_WELEMS + (size_t)4 * D_ * D_ + (size_t)D_ * DFF_;
        Kd = DFF_; Nd = D_;
        k0 = (id >> 5) << 5; n0 = (id & 31) << 5;
    }
#pragma unroll
    for (int i = 0; i < 4; i++)
        tile[ty + i * 8][tx] = W[(size_t)(k0 + ty + i * 8) * Nd + n0 + tx];
    __syncthreads();
#pragma unroll
    for (int i = 0; i < 4; i++)
        WT[(size_t)(n0 + ty + i * 8) * Kd + k0 + tx] = f2tf(tile[tx][ty + i * 8]);
}

__global__ void __launch_bounds__(256) round_kernel(
    const float* __restrict__ x, float* __restrict__ r, int n)
{
    const int i = (blockIdx.x * 256 + threadIdx.x) * 4;
    if (i >= n) return;
    const float4 v = *(const float4*)(x + i);
    float4 o;
    o.x = f2tf(v.x); o.y = f2tf(v.y); o.z = f2tf(v.z); o.w = f2tf(v.w);
    *(float4*)(r + i) = o;
}

// ---------------- embedding (x fp32 + xr tf32) ----------------
__global__ void __launch_bounds__(256) embed_kernel(
    const int* __restrict__ idx, const float* __restrict__ te,
    const float* __restrict__ pe, float* __restrict__ x, float* __restrict__ xr)
{
    const int bs = blockIdx.x;
    const int s  = bs & (S_ - 1);
    const int tok = idx[bs];
    const float4* tr = (const float4*)(te + (size_t)tok * D_);
    const float4* pr = (const float4*)(pe + (size_t)s * D_);
    float4* xo = (float4*)(x + (size_t)bs * D_);
    float4* xro = (float4*)(xr + (size_t)bs * D_);
    for (int i = threadIdx.x; i < D_ / 4; i += blockDim.x) {
        float4 t = tr[i], p = pr[i];
        float4 s4 = make_float4(t.x + p.x, t.y + p.y, t.z + p.z, t.w + p.w);
        xo[i] = s4;
        xro[i] = make_float4(f2tf(s4.x), f2tf(s4.y), f2tf(s4.z), f2tf(s4.w));
    }
}

// ---------------- layernorm (tf32-rounded out) ----------------
__device__ __forceinline__ float block_reduce_sum(float val, float* sh) {
    const int lane = threadIdx.x & 31;
    const int wid  = threadIdx.x >> 5;
#pragma unroll
    for (int o = 16; o; o >>= 1) val += __shfl_down_sync(0xffffffffu, val, o);
    if (lane == 0) sh[wid] = val;
    __syncthreads();
    const int nw = (blockDim.x + 31) >> 5;
    val = (threadIdx.x < nw) ? sh[threadIdx.x] : 0.0f;
    if (wid == 0) {
#pragma unroll
        for (int o = 16; o; o >>= 1) val += __shfl_down_sync(0xffffffffu, val, o);
        if (lane == 0) sh[0] = val;
    }
    __syncthreads();
    val = sh[0];
    __syncthreads();
    return val;
}

__global__ void __launch_bounds__(256) ln_kernel(
    const float* __restrict__ x, const float* __restrict__ g,
    const float* __restrict__ bta, float* __restrict__ out)
{
    __shared__ float red[32];
    const int row = blockIdx.x;
    const float* xr = x + (size_t)row * D_;
    float s = 0.0f, s2 = 0.0f;
    for (int i = threadIdx.x; i < D_; i += 256) {
        float v = xr[i];
        s += v; s2 += v * v;
    }
    s  = block_reduce_sum(s,  red);
    s2 = block_reduce_sum(s2, red);
    const float mean = s * (1.0f / D_);
    const float var  = s2 * (1.0f / D_) - mean * mean;
    const float rstd = rsqrtf(var + 1e-5f);
    float* orow = out + (size_t)row * D_;
    for (int i = threadIdx.x; i < D_; i += 256)
        orow[i] = f2tf((xr[i] - mean) * rstd * g[i] + bta[i]);
}

// ---------------- attention: 8 queries/block, smem-tiled K/V ----------------
#define ATT_STRIDE 68
#define ATT_SMEM ((128 * ATT_STRIDE + 8 * S_ + 8 * DK_) * 4)   // 69632 B

__global__ void __launch_bounds__(256) attn_kernel(
    const float* __restrict__ qkv, float* __restrict__ y)
{
    extern __shared__ float asmem[];
    float* Kb = asmem;
    float* sp = asmem + 128 * ATT_STRIDE;
    float* qs = sp + 8 * S_;
    const int tid = threadIdx.x, wid = tid >> 5, lane = tid & 31;
    const int s0 = blockIdx.x * 8;
    const int s = s0 + wid;
    const int h = blockIdx.y, b = blockIdx.z;
    const size_t base = (size_t)b * S_ * QKV3 + (size_t)h * DK_;
    const float* kp = qkv + base + D_;
    const float* vp = qkv + base + 2 * D_;

    {
        const float2 qv = *(const float2*)(qkv + base + (size_t)s * QKV3 + lane * 2);
        qs[wid * DK_ + lane * 2]     = qv.x;
        qs[wid * DK_ + lane * 2 + 1] = qv.y;
    }
    __syncwarp();

    const int nkmax = s0 + 8;
    float lmax = -INFINITY;

    for (int c0 = 0; c0 < nkmax; c0 += 128) {
        __syncthreads();
#pragma unroll
        for (int i = 0; i < 8; i++) {
            const int ch = tid + (i << 8);
            const int row = ch >> 4, q4 = (ch & 15) * 4;
            *(float4*)(Kb + row * ATT_STRIDE + q4) =
                *(const float4*)(kp + (size_t)(c0 + row) * QKV3 + q4);
        }
        __syncthreads();
        const int lim = min(c0 + 128, s + 1);
        for (int t = c0 + lane; t < lim; t += 32) {
            const float* kr = Kb + (t - c0) * ATT_STRIDE;
            float d = 0.0f;
#pragma unroll
            for (int i = 0; i < DK_; i += 4) {
                const float4 kv = *(const float4*)(kr + i);
                d += qs[wid * DK_ + i] * kv.x + qs[wid * DK_ + i + 1] * kv.y
                   + qs[wid * DK_ + i + 2] * kv.z + qs[wid * DK_ + i + 3] * kv.w;
            }
            d *= 0.125f;
            sp[wid * S_ + t] = d;
            lmax = fmaxf(lmax, d);
        }
    }
#pragma unroll
    for (int o = 16; o; o >>= 1) lmax = fmaxf(lmax, __shfl_xor_sync(0xffffffffu, lmax, o));

    float lsum = 0.0f;
    for (int t = lane; t < s + 1; t += 32) {
        const float e = expf(sp[wid * S_ + t] - lmax);
        sp[wid * S_ + t] = e;
        lsum += e;
    }
#pragma unroll
    for (int o = 16; o; o >>= 1) lsum += __shfl_xor_sync(0xffffffffu, lsum, o);
    const float inv = 1.0f / lsum;
    __syncwarp();

    const int dd = lane * 2;
    float a0 = 0.0f, a1 = 0.0f;
    for (int c0 = 0; c0 < nkmax; c0 += 128) {
        __syncthreads();
#pragma unroll
        for (int i = 0; i < 8; i++) {
            const int ch = tid + (i << 8);
            const int row = ch >> 4, q4 = (ch & 15) * 4;
            *(float4*)(Kb + row * ATT_STRIDE + q4) =
                *(const float4*)(vp + (size_t)(c0 + row) * QKV3 + q4);
        }
        __syncthreads();
        const int lim = min(c0 + 128, s + 1);
#pragma unroll 4
        for (int t = c0; t < lim; t++) {
            const float p = sp[wid * S_ + t];
            a0 += p * Kb[(t - c0) * ATT_STRIDE + dd];
            a1 += p * Kb[(t - c0) * ATT_STRIDE + dd + 1];
        }
    }
    *(float2*)(y + (size_t)b * S_ * D_ + (size_t)h * DK_ + (size_t)s * D_ + dd) =
        make_float2(f2tf(a0 * inv), f2tf(a1 * inv));
}

// ---------------- driver ----------------
extern "C" void kernel_launch(void* const* d_in, const int* in_sizes, int n_in,
                              void* d_out, int out_size)
{
    const int*   idx   = (const int*)  d_in[0];
    const float* te    = (const float*)d_in[1];
    const float* pe    = (const float*)d_in[2];
    const float* wq    = (const float*)d_in[3];
    const float* bq    = (const float*)d_in[4];
    const float* wk    = (const float*)d_in[5];
    const float* bk    = (const float*)d_in[6];
    const float* wv    = (const float*)d_in[7];
    const float* bv    = (const float*)d_in[8];
    const float* wo    = (const float*)d_in[9];
    const float* bo    = (const float*)d_in[10];
    const float* ln2g  = (const float*)d_in[11];
    const float* ln2b  = (const float*)d_in[12];
    const float* w1    = (const float*)d_in[13];
    const float* b1    = (const float*)d_in[14];
    const float* w2    = (const float*)d_in[15];
    const float* b2    = (const float*)d_in[16];
    const float* lnfg  = (const float*)d_in[17];
    const float* lnfb  = (const float*)d_in[18];
    float* out = (float*)d_out;

    float *x, *xr, *qkv, *y, *t, *hb, *wT, *bqkv, *teR;
    cudaGetSymbolAddress((void**)&x,    g_x);
    cudaGetSymbolAddress((void**)&xr,   g_xr);
    cudaGetSymbolAddress((void**)&qkv,  g_qkv);
    cudaGetSymbolAddress((void**)&y,    g_y);
    cudaGetSymbolAddress((void**)&t,    g_t);
    cudaGetSymbolAddress((void**)&hb,   g_h);
    cudaGetSymbolAddress((void**)&wT,   g_wT);
    cudaGetSymbolAddress((void**)&bqkv, g_bqkv);
    cudaGetSymbolAddress((void**)&teR,  g_teR);

    constexpr int SMA = GemmCfg<128, 128, 64>::SMEM;   // 96 KB (wide-warp)
    constexpr int SMB = GemmCfg<64, 128, 32>::SMEM;    // 72 KB (small-M)
    cudaFuncSetAttribute(mma_gemm<128, 128, 64, false, false, false, false>, cudaFuncAttributeMaxDynamicSharedMemorySize, SMA);
    cudaFuncSetAttribute(mma_gemm<128, 128, 64, true , false, true , false>, cudaFuncAttributeMaxDynamicSharedMemorySize, SMA);
    cudaFuncSetAttribute(mma_gemm<64, 128, 32, false, true , false, false>, cudaFuncAttributeMaxDynamicSharedMemorySize, SMB);
    cudaFuncSetAttribute(mma_gemm<64, 128, 32, false, true , false, true >, cudaFuncAttributeMaxDynamicSharedMemorySize, SMB);
    cudaFuncSetAttribute(attn_kernel, cudaFuncAttributeMaxDynamicSharedMemorySize, ATT_SMEM);

    const int M = M_TOK;

    // prep
    embed_kernel<<<M, 256>>>(idx, te, pe, x, xr);
    tDD_kernel<<<dim3(32, 32, 4 * L_), 256>>>(wq, wk, wv, wo, bq, bk, bv, wT, bqkv);
    tFF_kernel<<<dim3(128, 64, L_), 256>>>(w1, w2, wT);

    // grids: blockIdx.x = M-block (fastest), blockIdx.y = N-block
    const dim3 gQKV(M / 128, QKV3 / 128);        // 16 x 24  (cfg A)
    const dim3 gW1 (M / 128, DFF_ / 128);        // 16 x 32  (cfg A)
    const dim3 gSM (M / 64, D_ / 128);           // 32 x 8   (cfg B)
    const dim3 gLM (M / 128, (V_ + 127) / 128);  // 16 x 393 (cfg A)
    const dim3 gAT (S_ / 8, H_, B_);

    for (int l = 0; l < L_; l++) {
        const size_t lw = (size_t)l * LAYER_WELEMS;
        const float *wqkvT = wT + lw;
        const float *woT   = wT + lw + 3 * D_ * D_;
        const float *w1T   = wT + lw + 4 * D_ * D_;
        const float *w2T   = w1T + (size_t)D_ * DFF_;

        // fused qkv = xr @ [Wq|Wk|Wv] + bqkv
        mma_gemm<128, 128, 64, false, false, false, false><<<gQKV, 128, SMA>>>(
            xr, wqkvT, bqkv + l * QKV3, nullptr, qkv, nullptr, M, QKV3, D_);

        attn_kernel<<<gAT, 256, ATT_SMEM>>>(qkv, y);

        // x = x + y@Wo + bo
        mma_gemm<64, 128, 32, false, true, false, false><<<gSM, 128, SMB>>>(
            y, woT, bo + (size_t)l * D_, x, x, nullptr, M, D_, D_);

        // t = round(LN(x))
        ln_kernel<<<M, 256>>>(x, ln2g + (size_t)l * D_, ln2b + (size_t)l * D_, t);

        // hb = round(gelu(t@W1 + b1))
        mma_gemm<128, 128, 64, true, false, true, false><<<gW1, 128, SMA>>>(
            t, w1T, b1 + (size_t)l * DFF_, nullptr, hb, nullptr, M, DFF_, D_);

        // x = x + hb@W2 + b2 ; xr = round(x)
        mma_gemm<64, 128, 32, false, true, false, true><<<gSM, 128, SMB>>>(
            hb, w2T, b2 + (size_t)l * D_, x, x, xr, M, D_, DFF_);
    }

    // final LN + weight-tied LM head
    ln_kernel<<<M, 256>>>(x, lnfg, lnfb, t);
    round_kernel<<<(V_ * D_ / 4 + 255) / 256, 256>>>(te, teR, V_ * D_);
    mma_gemm<128, 128, 64, false, false, false, false><<<gLM, 128, SMA>>>(
        t, teR, nullptr, nullptr, out, nullptr, M, V_, D_);
}

// round 9
// speedup vs baseline: 3.7733x; 1.0035x over previous
#include <cuda_runtime.h>
#include <math.h>
#include <stdint.h>

// Problem constants
#define B_ 2
#define S_ 1024
#define D_ 1024
#define H_ 16
#define DK_ 64
#define DFF_ 4096
#define L_ 4
#define V_ 50257
#define M_TOK (B_ * S_)   // 2048 rows
#define QKV3 (3 * D_)     // 3072

// ---------------- scratch (static device globals; no allocation allowed) ----
__device__ float g_x[M_TOK * D_];       // residual stream (fp32)
__device__ float g_xr[M_TOK * D_];      // tf32-rounded copy of x
__device__ float g_qkv[M_TOK * QKV3];   // fused q|k|v (tf32-valued)
__device__ float g_y[M_TOK * D_];       // attention out (tf32-rounded)
__device__ float g_t[M_TOK * D_];       // ln out (tf32-rounded)
__device__ float g_h[M_TOK * DFF_];     // mlp hidden (tf32-rounded)

// transposed + tf32-rounded weights: per layer [wqT][wkT][wvT][woT][w1T][w2T]
#define LAYER_WELEMS (4 * D_ * D_ + D_ * DFF_ + DFF_ * D_)
__device__ float g_wT[(size_t)L_ * LAYER_WELEMS];
__device__ float g_bqkv[L_ * QKV3];      // packed qkv bias
__device__ float g_teR[(size_t)V_ * D_]; // tf32-rounded token embedding

// ---------------- PTX helpers (sm_80+ portable only) ----------------
__device__ __forceinline__ uint32_t smem_u32(const void* p) {
    uint32_t a;
    asm("{ .reg .u64 t; cvta.to.shared.u64 t, %1; cvt.u32.u64 %0, t; }" : "=r"(a) : "l"(p));
    return a;
}
__device__ __forceinline__ void cp_async16(uint32_t dst, const void* src, int szbytes) {
    asm volatile("cp.async.cg.shared.global [%0], [%1], 16, %2;" :: "r"(dst), "l"(src), "r"(szbytes));
}
__device__ __forceinline__ void cp_commit() { asm volatile("cp.async.commit_group;" ::: "memory"); }
template<int N> __device__ __forceinline__ void cp_wait() { asm volatile("cp.async.wait_group %0;" :: "n"(N) : "memory"); }

__device__ __forceinline__ void ldsm_x4(uint32_t& r0, uint32_t& r1, uint32_t& r2, uint32_t& r3, uint32_t addr) {
    asm volatile("ldmatrix.sync.aligned.m8n8.x4.shared.b16 {%0,%1,%2,%3}, [%4];"
                 : "=r"(r0), "=r"(r1), "=r"(r2), "=r"(r3) : "r"(addr));
}
// fp32 -> tf32 round-to-nearest (unbiased)
__device__ __forceinline__ float f2tf(float x) {
    uint32_t r;
    asm("cvt.rna.tf32.f32 %0, %1;" : "=r"(r) : "f"(x));
    return __uint_as_float(r);
}
__device__ __forceinline__ void mma1688_tf32(float* c, const uint32_t* a, uint32_t b0, uint32_t b1) {
    asm volatile("mma.sync.aligned.m16n8k8.row.col.f32.tf32.tf32.f32 "
                 "{%0,%1,%2,%3}, {%4,%5,%6,%7}, {%8,%9}, {%0,%1,%2,%3};"
                 : "+f"(c[0]), "+f"(c[1]), "+f"(c[2]), "+f"(c[3])
                 : "r"(a[0]), "r"(a[1]), "r"(a[2]), "r"(a[3]), "r"(b0), "r"(b1));
}

#define SW128(o) ((o) ^ (((o) >> 3) & 0x70))

// ---------------- TF32 GEMM (inputs pre-rounded to tf32) ----------------
// C[M,N] = act( A[M,K] @ B[N,K]^T + bias ) (+ res), fp32 accum.
// Single config: CTA 128x64, BK=32 (128B SW128 rows), 3-stage cp.async,
// 4 warps (2 rows x 2 cols), warp tile 64x32, 128 threads, occ 3 (12 warps/SM).
// Fragment double-buffering: ldsm for step s+1 issued before MMAs of step s.
// Grid: blockIdx.x = M-block (fastest), blockIdx.y = N-block.
// M % 128 == 0, K % 32 == 0; N tail OK (clamp+zfill, scalar store guard).
#define G_STAGE ((128 + 64) * 128)        // 24576 B per stage
#define G_SMEM  (3 * G_STAGE)             // 73728 B

template<bool GELU_, bool RES_, bool ROUND_, bool WR_>
__global__ void __launch_bounds__(128, 3)
mma_gemm(const float* __restrict__ A, const float* __restrict__ Bm,
         const float* __restrict__ bias, const float* __restrict__ res,
         float* __restrict__ C, float* __restrict__ Cr, int M, int N, int K)
{
    extern __shared__ __align__(1024) char smem_raw[];
    const uint32_t sb = smem_u32(smem_raw);
    const int tid = threadIdx.x, wid = tid >> 5, lane = tid & 31;
    const int bm = blockIdx.x << 7, bn = blockIdx.y << 6;
    const int wr = wid & 1, wc = wid >> 1;            // 2 x 2 warp grid
    const int rl = lane & 15, qh = lane >> 4;         // A-frag addressing
    const int brl = (lane & 7) + ((lane & 16) >> 1);  // B-frag row
    const int bqh = (lane >> 3) & 1;                  // B-frag chunk parity

    float acc[4][4][4];
#pragma unroll
    for (int i = 0; i < 4; i++)
#pragma unroll
        for (int j = 0; j < 4; j++)
#pragma unroll
            for (int r = 0; r < 4; r++) acc[i][j][r] = 0.0f;

    auto load_chunk = [&](int c, int stage) {
        const int k0 = c << 5;
        const uint32_t sA = sb + (uint32_t)stage * G_STAGE;
        const uint32_t sB = sA + 128 * 128;
#pragma unroll
        for (int u = 0; u < 8; u++) {                 // A: 1024 chunks / 128 thr
            const int ch = tid + (u << 7);
            const int r = ch >> 3, qd = ch & 7;
            cp_async16(sA + SW128((uint32_t)(r * 128 + qd * 16)),
                       A + (size_t)(bm + r) * K + k0 + qd * 4, 16);
        }
#pragma unroll
        for (int u = 0; u < 4; u++) {                 // B: 512 chunks / 128 thr
            const int ch = tid + (u << 7);
            const int r = ch >> 3, qd = ch & 7;
            const int gn = bn + r;
            const int vn = gn < N ? gn : N - 1;
            const int vsz = gn < N ? 16 : 0;
            cp_async16(sB + SW128((uint32_t)(r * 128 + qd * 16)),
                       Bm + (size_t)vn * K + k0 + qd * 4, vsz);
        }
    };

    uint32_t a[2][4][4], b[2][2][4];     // double-buffered fragments

    const int NC = K >> 5;
    load_chunk(0, 0);
    cp_commit();
    if (NC > 1) { load_chunk(1, 1); cp_commit(); }

    int buf = 0, nxt = 2;
    for (int c = 0; c < NC; c++) {
        if (c + 1 < NC) cp_wait<1>(); else cp_wait<0>();
        __syncthreads();

        const uint32_t tA = sb + (uint32_t)buf * G_STAGE;
        const uint32_t tB = tA + 128 * 128;

        // prologue ldsm for step 0
#pragma unroll
        for (int i = 0; i < 4; i++) {
            const uint32_t off = SW128((uint32_t)((wr * 64 + i * 16 + rl) * 128 + qh * 16));
            ldsm_x4(a[0][i][0], a[0][i][1], a[0][i][2], a[0][i][3], tA + off);
        }
#pragma unroll
        for (int p = 0; p < 2; p++) {
            const uint32_t off = SW128((uint32_t)((wc * 32 + p * 16 + brl) * 128 + bqh * 16));
            ldsm_x4(b[0][p][0], b[0][p][1], b[0][p][2], b[0][p][3], tB + off);
        }

        // issue next-next chunk's loads while MMAs run
        if (c + 2 < NC) { load_chunk(c + 2, nxt); cp_commit(); }

#pragma unroll
        for (int s = 0; s < 4; s++) {
            const int pb = s & 1, nb = pb ^ 1;
            if (s < 3) {   // prefetch fragments for step s+1
#pragma unroll
                for (int i = 0; i < 4; i++) {
                    const uint32_t off = SW128((uint32_t)((wr * 64 + i * 16 + rl) * 128 + (2 * (s + 1) + qh) * 16));
                    ldsm_x4(a[nb][i][0], a[nb][i][1], a[nb][i][2], a[nb][i][3], tA + off);
                }
#pragma unroll
                for (int p = 0; p < 2; p++) {
                    const uint32_t off = SW128((uint32_t)((wc * 32 + p * 16 + brl) * 128 + (2 * (s + 1) + bqh) * 16));
                    ldsm_x4(b[nb][p][0], b[nb][p][1], b[nb][p][2], b[nb][p][3], tB + off);
                }
            }
#pragma unroll
            for (int i = 0; i < 4; i++)
#pragma unroll
                for (int j = 0; j < 4; j++)
                    mma1688_tf32(acc[i][j], a[pb][i],
                                 b[pb][j >> 1][(j & 1) * 2], b[pb][j >> 1][(j & 1) * 2 + 1]);
        }

        buf = buf == 2 ? 0 : buf + 1;
        nxt = nxt == 2 ? 0 : nxt + 1;
    }

    // epilogue (scalar stores: N may be odd)
    const int quad = lane >> 2, tq = lane & 3;
#pragma unroll
    for (int i = 0; i < 4; i++) {
        const int m0 = bm + wr * 64 + i * 16 + quad;
#pragma unroll
        for (int j = 0; j < 4; j++) {
            const int n0 = bn + wc * 32 + j * 8 + tq * 2;
#pragma unroll
            for (int half = 0; half < 2; half++) {
                const int m = m0 + half * 8;
                float c0 = acc[i][j][half * 2 + 0];
                float c1 = acc[i][j][half * 2 + 1];
                if (bias) { c0 += bias[n0]; c1 += bias[n0 + 1]; }
                if (GELU_) {
                    c0 = 0.5f * c0 * (1.0f + erff(c0 * 0.70710678118654752f));
                    c1 = 0.5f * c1 * (1.0f + erff(c1 * 0.70710678118654752f));
                }
                if (RES_) {
                    c0 += res[(size_t)m * N + n0];
                    c1 += res[(size_t)m * N + n0 + 1];
                }
                float s0 = ROUND_ ? f2tf(c0) : c0;
                float s1 = ROUND_ ? f2tf(c1) : c1;
                if (n0 < N)     C[(size_t)m * N + n0]     = s0;
                if (n0 + 1 < N) C[(size_t)m * N + n0 + 1] = s1;
                if (WR_) {
                    if (n0 < N)     Cr[(size_t)m * N + n0]     = f2tf(c0);
                    if (n0 + 1 < N) Cr[(size_t)m * N + n0 + 1] = f2tf(c1);
                }
            }
        }
    }
}

// ---------------- weight prep ----------------
__global__ void __launch_bounds__(256) tDD_kernel(
    const float* __restrict__ wq, const float* __restrict__ wk,
    const float* __restrict__ wv, const float* __restrict__ wo,
    const float* __restrict__ bq, const float* __restrict__ bk,
    const float* __restrict__ bv, float* __restrict__ wT, float* __restrict__ bqkv)
{
    __shared__ float tile[32][33];
    const int m = blockIdx.z, l = m >> 2, which = m & 3;
    const float* W = (which == 0 ? wq : which == 1 ? wk : which == 2 ? wv : wo)
                     + (size_t)l * D_ * D_;
    float* WT = wT + (size_t)l * LAYER_WELEMS + (size_t)which * D_ * D_;
    const int tx = threadIdx.x & 31, ty = threadIdx.x >> 5;
    const int k0 = blockIdx.y << 5, n0 = blockIdx.x << 5;
#pragma unroll
    for (int i = 0; i < 4; i++)
        tile[ty + i * 8][tx] = W[(size_t)(k0 + ty + i * 8) * D_ + n0 + tx];
    __syncthreads();
#pragma unroll
    for (int i = 0; i < 4; i++)
        WT[(size_t)(n0 + ty + i * 8) * D_ + k0 + tx] = f2tf(tile[tx][ty + i * 8]);
    if (blockIdx.y == 0 && which < 3 && threadIdx.x < 32) {
        const float* bsrc = which == 0 ? bq : which == 1 ? bk : bv;
        bqkv[l * QKV3 + which * D_ + n0 + threadIdx.x] = bsrc[l * D_ + n0 + threadIdx.x];
    }
}

__global__ void __launch_bounds__(256) tFF_kernel(
    const float* __restrict__ w1, const float* __restrict__ w2, float* __restrict__ wT)
{
    __shared__ float tile[32][33];
    const int l = blockIdx.z;
    const int tx = threadIdx.x & 31, ty = threadIdx.x >> 5;
    const float* W; float* WT; int Kd, Nd, k0, n0;
    if (blockIdx.y < 32) {
        W = w1 + (size_t)l * D_ * DFF_;
        WT = wT + (size_t)l * LAYER_WELEMS + (size_t)4 * D_ * D_;
        Kd = D_; Nd = DFF_;
        k0 = blockIdx.y << 5; n0 = blockIdx.x << 5;
    } else {
        const int id = blockIdx.x + ((blockIdx.y - 32) << 7);
        W = w2 + (size_t)l * DFF_ * D_;
        WT = wT + (size_t)l * LAYER_WELEMS + (size_t)4 * D_ * D_ + (size_t)D_ * DFF_;
        Kd = DFF_; Nd = D_;
        k0 = (id >> 5) << 5; n0 = (id & 31) << 5;
    }
#pragma unroll
    for (int i = 0; i < 4; i++)
        tile[ty + i * 8][tx] = W[(size_t)(k0 + ty + i * 8) * Nd + n0 + tx];
    __syncthreads();
#pragma unroll
    for (int i = 0; i < 4; i++)
        WT[(size_t)(n0 + ty + i * 8) * Kd + k0 + tx] = f2tf(tile[tx][ty + i * 8]);
}

__global__ void __launch_bounds__(256) round_kernel(
    const float* __restrict__ x, float* __restrict__ r, int n)
{
    const int i = (blockIdx.x * 256 + threadIdx.x) * 4;
    if (i >= n) return;
    const float4 v = *(const float4*)(x + i);
    float4 o;
    o.x = f2tf(v.x); o.y = f2tf(v.y); o.z = f2tf(v.z); o.w = f2tf(v.w);
    *(float4*)(r + i) = o;
}

// ---------------- embedding (x fp32 + xr tf32) ----------------
__global__ void __launch_bounds__(256) embed_kernel(
    const int* __restrict__ idx, const float* __restrict__ te,
    const float* __restrict__ pe, float* __restrict__ x, float* __restrict__ xr)
{
    const int bs = blockIdx.x;
    const int s  = bs & (S_ - 1);
    const int tok = idx[bs];
    const float4* tr = (const float4*)(te + (size_t)tok * D_);
    const float4* pr = (const float4*)(pe + (size_t)s * D_);
    float4* xo = (float4*)(x + (size_t)bs * D_);
    float4* xro = (float4*)(xr + (size_t)bs * D_);
    for (int i = threadIdx.x; i < D_ / 4; i += blockDim.x) {
        float4 t = tr[i], p = pr[i];
        float4 s4 = make_float4(t.x + p.x, t.y + p.y, t.z + p.z, t.w + p.w);
        xo[i] = s4;
        xro[i] = make_float4(f2tf(s4.x), f2tf(s4.y), f2tf(s4.z), f2tf(s4.w));
    }
}

// ---------------- layernorm (tf32-rounded out) ----------------
__device__ __forceinline__ float block_reduce_sum(float val, float* sh) {
    const int lane = threadIdx.x & 31;
    const int wid  = threadIdx.x >> 5;
#pragma unroll
    for (int o = 16; o; o >>= 1) val += __shfl_down_sync(0xffffffffu, val, o);
    if (lane == 0) sh[wid] = val;
    __syncthreads();
    const int nw = (blockDim.x + 31) >> 5;
    val = (threadIdx.x < nw) ? sh[threadIdx.x] : 0.0f;
    if (wid == 0) {
#pragma unroll
        for (int o = 16; o; o >>= 1) val += __shfl_down_sync(0xffffffffu, val, o);
        if (lane == 0) sh[0] = val;
    }
    __syncthreads();
    val = sh[0];
    __syncthreads();
    return val;
}

__global__ void __launch_bounds__(256) ln_kernel(
    const float* __restrict__ x, const float* __restrict__ g,
    const float* __restrict__ bta, float* __restrict__ out)
{
    __shared__ float red[32];
    const int row = blockIdx.x;
    const float* xr = x + (size_t)row * D_;
    float s = 0.0f, s2 = 0.0f;
    for (int i = threadIdx.x; i < D_; i += 256) {
        float v = xr[i];
        s += v; s2 += v * v;
    }
    s  = block_reduce_sum(s,  red);
    s2 = block_reduce_sum(s2, red);
    const float mean = s * (1.0f / D_);
    const float var  = s2 * (1.0f / D_) - mean * mean;
    const float rstd = rsqrtf(var + 1e-5f);
    float* orow = out + (size_t)row * D_;
    for (int i = threadIdx.x; i < D_; i += 256)
        orow[i] = f2tf((xr[i] - mean) * rstd * g[i] + bta[i]);
}

// ---------------- attention: 8 queries/block, smem-tiled K/V ----------------
#define ATT_STRIDE 68
#define ATT_SMEM ((128 * ATT_STRIDE + 8 * S_ + 8 * DK_) * 4)   // 69632 B

__global__ void __launch_bounds__(256) attn_kernel(
    const float* __restrict__ qkv, float* __restrict__ y)
{
    extern __shared__ float asmem[];
    float* Kb = asmem;
    float* sp = asmem + 128 * ATT_STRIDE;
    float* qs = sp + 8 * S_;
    const int tid = threadIdx.x, wid = tid >> 5, lane = tid & 31;
    const int s0 = blockIdx.x * 8;
    const int s = s0 + wid;
    const int h = blockIdx.y, b = blockIdx.z;
    const size_t base = (size_t)b * S_ * QKV3 + (size_t)h * DK_;
    const float* kp = qkv + base + D_;
    const float* vp = qkv + base + 2 * D_;

    {
        const float2 qv = *(const float2*)(qkv + base + (size_t)s * QKV3 + lane * 2);
        qs[wid * DK_ + lane * 2]     = qv.x;
        qs[wid * DK_ + lane * 2 + 1] = qv.y;
    }
    __syncwarp();

    const int nkmax = s0 + 8;
    float lmax = -INFINITY;

    for (int c0 = 0; c0 < nkmax; c0 += 128) {
        __syncthreads();
#pragma unroll
        for (int i = 0; i < 8; i++) {
            const int ch = tid + (i << 8);
            const int row = ch >> 4, q4 = (ch & 15) * 4;
            *(float4*)(Kb + row * ATT_STRIDE + q4) =
                *(const float4*)(kp + (size_t)(c0 + row) * QKV3 + q4);
        }
        __syncthreads();
        const int lim = min(c0 + 128, s + 1);
        for (int t = c0 + lane; t < lim; t += 32) {
            const float* kr = Kb + (t - c0) * ATT_STRIDE;
            float d = 0.0f;
#pragma unroll
            for (int i = 0; i < DK_; i += 4) {
                const float4 kv = *(const float4*)(kr + i);
                d += qs[wid * DK_ + i] * kv.x + qs[wid * DK_ + i + 1] * kv.y
                   + qs[wid * DK_ + i + 2] * kv.z + qs[wid * DK_ + i + 3] * kv.w;
            }
            d *= 0.125f;
            sp[wid * S_ + t] = d;
            lmax = fmaxf(lmax, d);
        }
    }
#pragma unroll
    for (int o = 16; o; o >>= 1) lmax = fmaxf(lmax, __shfl_xor_sync(0xffffffffu, lmax, o));

    float lsum = 0.0f;
    for (int t = lane; t < s + 1; t += 32) {
        const float e = expf(sp[wid * S_ + t] - lmax);
        sp[wid * S_ + t] = e;
        lsum += e;
    }
#pragma unroll
    for (int o = 16; o; o >>= 1) lsum += __shfl_xor_sync(0xffffffffu, lsum, o);
    const float inv = 1.0f / lsum;
    __syncwarp();

    // V accumulation: 2 independent accumulator pairs break the FMA chain
    const int dd = lane * 2;
    float a0 = 0.0f, a1 = 0.0f, c0a = 0.0f, c1a = 0.0f;
    for (int c0 = 0; c0 < nkmax; c0 += 128) {
        __syncthreads();
#pragma unroll
        for (int i = 0; i < 8; i++) {
            const int ch = tid + (i << 8);
            const int row = ch >> 4, q4 = (ch & 15) * 4;
            *(float4*)(Kb + row * ATT_STRIDE + q4) =
                *(const float4*)(vp + (size_t)(c0 + row) * QKV3 + q4);
        }
        __syncthreads();
        const int lim = min(c0 + 128, s + 1);
        int t = c0;
        for (; t + 2 <= lim; t += 2) {
            const float p0 = sp[wid * S_ + t], p1 = sp[wid * S_ + t + 1];
            a0  += p0 * Kb[(t - c0) * ATT_STRIDE + dd];
            a1  += p0 * Kb[(t - c0) * ATT_STRIDE + dd + 1];
            c0a += p1 * Kb[(t + 1 - c0) * ATT_STRIDE + dd];
            c1a += p1 * Kb[(t + 1 - c0) * ATT_STRIDE + dd + 1];
        }
        for (; t < lim; t++) {
            const float p = sp[wid * S_ + t];
            a0 += p * Kb[(t - c0) * ATT_STRIDE + dd];
            a1 += p * Kb[(t - c0) * ATT_STRIDE + dd + 1];
        }
    }
    *(float2*)(y + (size_t)b * S_ * D_ + (size_t)h * DK_ + (size_t)s * D_ + dd) =
        make_float2(f2tf((a0 + c0a) * inv), f2tf((a1 + c1a) * inv));
}

// ---------------- driver ----------------
extern "C" void kernel_launch(void* const* d_in, const int* in_sizes, int n_in,
                              void* d_out, int out_size)
{
    const int*   idx   = (const int*)  d_in[0];
    const float* te    = (const float*)d_in[1];
    const float* pe    = (const float*)d_in[2];
    const float* wq    = (const float*)d_in[3];
    const float* bq    = (const float*)d_in[4];
    const float* wk    = (const float*)d_in[5];
    const float* bk    = (const float*)d_in[6];
    const float* wv    = (const float*)d_in[7];
    const float* bv    = (const float*)d_in[8];
    const float* wo    = (const float*)d_in[9];
    const float* bo    = (const float*)d_in[10];
    const float* ln2g  = (const float*)d_in[11];
    const float* ln2b  = (const float*)d_in[12];
    const float* w1    = (const float*)d_in[13];
    const float* b1    = (const float*)d_in[14];
    const float* w2    = (const float*)d_in[15];
    const float* b2    = (const float*)d_in[16];
    const float* lnfg  = (const float*)d_in[17];
    const float* lnfb  = (const float*)d_in[18];
    float* out = (float*)d_out;

    float *x, *xr, *qkv, *y, *t, *hb, *wT, *bqkv, *teR;
    cudaGetSymbolAddress((void**)&x,    g_x);
    cudaGetSymbolAddress((void**)&xr,   g_xr);
    cudaGetSymbolAddress((void**)&qkv,  g_qkv);
    cudaGetSymbolAddress((void**)&y,    g_y);
    cudaGetSymbolAddress((void**)&t,    g_t);
    cudaGetSymbolAddress((void**)&hb,   g_h);
    cudaGetSymbolAddress((void**)&wT,   g_wT);
    cudaGetSymbolAddress((void**)&bqkv, g_bqkv);
    cudaGetSymbolAddress((void**)&teR,  g_teR);

    cudaFuncSetAttribute(mma_gemm<false, false, false, false>, cudaFuncAttributeMaxDynamicSharedMemorySize, G_SMEM);
    cudaFuncSetAttribute(mma_gemm<false, true , false, false>, cudaFuncAttributeMaxDynamicSharedMemorySize, G_SMEM);
    cudaFuncSetAttribute(mma_gemm<true , false, true , false>, cudaFuncAttributeMaxDynamicSharedMemorySize, G_SMEM);
    cudaFuncSetAttribute(mma_gemm<false, true , false, true >, cudaFuncAttributeMaxDynamicSharedMemorySize, G_SMEM);
    cudaFuncSetAttribute(attn_kernel, cudaFuncAttributeMaxDynamicSharedMemorySize, ATT_SMEM);

    const int M = M_TOK;

    // prep
    embed_kernel<<<M, 256>>>(idx, te, pe, x, xr);
    tDD_kernel<<<dim3(32, 32, 4 * L_), 256>>>(wq, wk, wv, wo, bq, bk, bv, wT, bqkv);
    tFF_kernel<<<dim3(128, 64, L_), 256>>>(w1, w2, wT);

    // grids: blockIdx.x = M-block (fastest), blockIdx.y = N-block (BN=64)
    const dim3 gQKV(M / 128, QKV3 / 64);        // 16 x 48
    const dim3 gW1 (M / 128, DFF_ / 64);        // 16 x 64
    const dim3 gDD (M / 128, D_ / 64);          // 16 x 16
    const dim3 gLM (M / 128, (V_ + 63) / 64);   // 16 x 786
    const dim3 gAT (S_ / 8, H_, B_);

    for (int l = 0; l < L_; l++) {
        const size_t lw = (size_t)l * LAYER_WELEMS;
        const float *wqkvT = wT + lw;
        const float *woT   = wT + lw + 3 * D_ * D_;
        const float *w1T   = wT + lw + 4 * D_ * D_;
        const float *w2T   = w1T + (size_t)D_ * DFF_;

        // fused qkv = xr @ [Wq|Wk|Wv] + bqkv
        mma_gemm<false, false, false, false><<<gQKV, 128, G_SMEM>>>(
            xr, wqkvT, bqkv + l * QKV3, nullptr, qkv, nullptr, M, QKV3, D_);

        attn_kernel<<<gAT, 256, ATT_SMEM>>>(qkv, y);

        // x = x + y@Wo + bo
        mma_gemm<false, true, false, false><<<gDD, 128, G_SMEM>>>(
            y, woT, bo + (size_t)l * D_, x, x, nullptr, M, D_, D_);

        // t = round(LN(x))
        ln_kernel<<<M, 256>>>(x, ln2g + (size_t)l * D_, ln2b + (size_t)l * D_, t);

        // hb = round(gelu(t@W1 + b1))
        mma_gemm<true, false, true, false><<<gW1, 128, G_SMEM>>>(
            t, w1T, b1 + (size_t)l * DFF_, nullptr, hb, nullptr, M, DFF_, D_);

        // x = x + hb@W2 + b2 ; xr = round(x)
        mma_gemm<false, true, false, true><<<gDD, 128, G_SMEM>>>(
            hb, w2T, b2 + (size_t)l * D_, x, x, xr, M, D_, DFF_);
    }

    // final LN + weight-tied LM head
    ln_kernel<<<M, 256>>>(x, lnfg, lnfb, t);
    round_kernel<<<(V_ * D_ / 4 + 255) / 256, 256>>>(te, teR, V_ * D_);
    mma_gemm<false, false, false, false><<<gLM, 128, G_SMEM>>>(
        t, teR, nullptr, nullptr, out, nullptr, M, V_, D_);
}

// round 11
// speedup vs baseline: 4.8730x; 1.2915x over previous
#include <cuda_runtime.h>
#include <cuda_fp16.h>
#include <math.h>
#include <stdint.h>

// Problem constants
#define B_ 2
#define S_ 1024
#define D_ 1024
#define H_ 16
#define DK_ 64
#define DFF_ 4096
#define L_ 4
#define V_ 50257
#define M_TOK (B_ * S_)   // 2048 rows
#define QKV3 (3 * D_)     // 3072

// ---------------- scratch (static device globals; no allocation allowed) ----
__device__ float  g_x[M_TOK * D_];        // residual stream (fp32)
__device__ __half g_xh[M_TOK * D_];       // fp16 copy of x (QKV A input)
__device__ __half g_qkv[M_TOK * QKV3];    // fused q|k|v (fp16)
__device__ __half g_y[M_TOK * D_];        // attention out (fp16)
__device__ __half g_t[M_TOK * D_];        // ln out (fp16)
__device__ __half g_h[M_TOK * DFF_];      // mlp hidden (fp16)

// transposed fp16 weights: per layer [wqT][wkT][wvT][woT][w1T][w2T]
#define LAYER_WELEMS (4 * D_ * D_ + D_ * DFF_ + DFF_ * D_)
__device__ __half g_wH[(size_t)L_ * LAYER_WELEMS];
__device__ float  g_bqkv[L_ * QKV3];       // packed qkv bias (fp32)
__device__ __half g_teH[(size_t)V_ * D_];  // fp16 token embedding ([V,D]=[N,K])

// ---------------- PTX helpers (sm_80+ portable only) ----------------
__device__ __forceinline__ uint32_t smem_u32(const void* p) {
    uint32_t a;
    asm("{ .reg .u64 t; cvta.to.shared.u64 t, %1; cvt.u32.u64 %0, t; }" : "=r"(a) : "l"(p));
    return a;
}
__device__ __forceinline__ void cp_async16(uint32_t dst, const void* src, int szbytes) {
    asm volatile("cp.async.cg.shared.global [%0], [%1], 16, %2;" :: "r"(dst), "l"(src), "r"(szbytes));
}
__device__ __forceinline__ void cp_commit() { asm volatile("cp.async.commit_group;" ::: "memory"); }
template<int N> __device__ __forceinline__ void cp_wait() { asm volatile("cp.async.wait_group %0;" :: "n"(N) : "memory"); }

__device__ __forceinline__ void ldsm_x4(uint32_t& r0, uint32_t& r1, uint32_t& r2, uint32_t& r3, uint32_t addr) {
    asm volatile("ldmatrix.sync.aligned.m8n8.x4.shared.b16 {%0,%1,%2,%3}, [%4];"
                 : "=r"(r0), "=r"(r1), "=r"(r2), "=r"(r3) : "r"(addr));
}
// fp16 MMA, fp32 accumulate: 2048 FLOP/instr (2x tf32 m16n8k8 at same issue rate)
__device__ __forceinline__ void mma16816(float* c, const uint32_t* a, uint32_t b0, uint32_t b1) {
    asm volatile("mma.sync.aligned.m16n8k16.row.col.f32.f16.f16.f32 "
                 "{%0,%1,%2,%3}, {%4,%5,%6,%7}, {%8,%9}, {%0,%1,%2,%3};"
                 : "+f"(c[0]), "+f"(c[1]), "+f"(c[2]), "+f"(c[3])
                 : "r"(a[0]), "r"(a[1]), "r"(a[2]), "r"(a[3]), "r"(b0), "r"(b1));
}

#define SW128(o) ((o) ^ (((o) >> 3) & 0x70))

// ---------------- fp16 GEMM (fp32 accumulate) ----------------
// C[M,N] = act( A[M,K] @ B[N,K]^T + bias ) (+ res)
// CTA 128x128, BK=64 halves (128B SW128 rows), 3-stage cp.async,
// 8 warps (2x4), warp tile 64x32, 256 threads, occ 2 (16 warps/SM).
// Grid: blockIdx.x = M-block (fastest, B L2 reuse), blockIdx.y = N-block.
// M % 128 == 0, K % 64 == 0; N tail OK (clamp+zfill, scalar store guard).
// WF_: write fp32 C.  WH_: write fp16 Ch.
#define G_STAGE 32768              // (128+128) rows x 128B
#define G_SMEM  (3 * G_STAGE)      // 98304 B

template<bool GELU_, bool RES_, bool WF_, bool WH_>
__global__ void __launch_bounds__(256, 2)
mma_gemm(const __half* __restrict__ A, const __half* __restrict__ Bm,
         const float* __restrict__ bias, const float* __restrict__ res,
         float* __restrict__ C, __half* __restrict__ Ch, int M, int N, int K)
{
    extern __shared__ __align__(1024) char smem_raw[];
    const uint32_t sb = smem_u32(smem_raw);
    const int tid = threadIdx.x, wid = tid >> 5, lane = tid & 31;
    const int bm = blockIdx.x << 7, bn = blockIdx.y << 7;
    const int wr = wid >> 2, wc = wid & 3;       // 2 x 4 warp grid
    const int rl = lane & 15, qh = lane >> 4;    // ldmatrix addressing

    float acc[4][4][4];
#pragma unroll
    for (int i = 0; i < 4; i++)
#pragma unroll
        for (int j = 0; j < 4; j++)
#pragma unroll
            for (int r = 0; r < 4; r++) acc[i][j][r] = 0.0f;

    auto load_chunk = [&](int c, int stage) {
        const int k0 = c << 6;                    // half-element K offset
        const uint32_t sA = sb + (uint32_t)stage * G_STAGE;
        const uint32_t sB = sA + 16384;
#pragma unroll
        for (int u = 0; u < 4; u++) {             // A: 1024 16B-chunks / 256 thr
            const int ch = tid + (u << 8);
            const int r = ch >> 3, qd = ch & 7;
            cp_async16(sA + SW128((uint32_t)(r * 128 + qd * 16)),
                       A + (size_t)(bm + r) * K + k0 + qd * 8, 16);
        }
#pragma unroll
        for (int u = 0; u < 4; u++) {             // B: 1024 chunks / 256 thr
            const int ch = tid + (u << 8);
            const int r = ch >> 3, qd = ch & 7;
            const int gn = bn + r;
            const int vn = gn < N ? gn : N - 1;
            const int vsz = gn < N ? 16 : 0;      // zero-fill OOB B rows
            cp_async16(sB + SW128((uint32_t)(r * 128 + qd * 16)),
                       Bm + (size_t)vn * K + k0 + qd * 8, vsz);
        }
    };

    const int NC = K >> 6;
    load_chunk(0, 0);
    cp_commit();
    if (NC > 1) { load_chunk(1, 1); cp_commit(); }

    int buf = 0, nxt = 2;
    for (int c = 0; c < NC; c++) {
        if (c + 1 < NC) cp_wait<1>(); else cp_wait<0>();
        __syncthreads();

        if (c + 2 < NC) { load_chunk(c + 2, nxt); cp_commit(); }

        const uint32_t tA = sb + (uint32_t)buf * G_STAGE;
        const uint32_t tB = tA + 16384;
#pragma unroll
        for (int k16 = 0; k16 < 4; k16++) {       // 4 k16 steps per 64-K chunk
            uint32_t a[4][4], b[2][4];
#pragma unroll
            for (int i = 0; i < 4; i++) {
                const uint32_t off = SW128((uint32_t)((wr * 64 + i * 16 + rl) * 128 + (k16 * 2 + qh) * 16));
                ldsm_x4(a[i][0], a[i][1], a[i][2], a[i][3], tA + off);
            }
#pragma unroll
            for (int g = 0; g < 2; g++) {
                const uint32_t off = SW128((uint32_t)((wc * 32 + g * 16 + rl) * 128 + (k16 * 2 + qh) * 16));
                ldsm_x4(b[g][0], b[g][1], b[g][2], b[g][3], tB + off);
            }
            // B fragment pairing (m16n8k16): n-tile o of group g uses {b[g][o], b[g][o+2]}
#pragma unroll
            for (int i = 0; i < 4; i++)
#pragma unroll
                for (int j = 0; j < 4; j++)
                    mma16816(acc[i][j], a[i], b[j >> 1][j & 1], b[j >> 1][(j & 1) + 2]);
        }

        buf = buf == 2 ? 0 : buf + 1;
        nxt = nxt == 2 ? 0 : nxt + 1;
    }

    // epilogue (scalar stores: N may be odd)
    const int quad = lane >> 2, tq = lane & 3;
#pragma unroll
    for (int i = 0; i < 4; i++) {
        const int m0 = bm + wr * 64 + i * 16 + quad;
#pragma unroll
        for (int j = 0; j < 4; j++) {
            const int n0 = bn + wc * 32 + j * 8 + tq * 2;
#pragma unroll
            for (int half = 0; half < 2; half++) {
                const int m = m0 + half * 8;
                float c0 = acc[i][j][half * 2 + 0];
                float c1 = acc[i][j][half * 2 + 1];
                if (bias) { c0 += bias[n0]; c1 += bias[n0 + 1]; }
                if (GELU_) {
                    c0 = 0.5f * c0 * (1.0f + erff(c0 * 0.70710678118654752f));
                    c1 = 0.5f * c1 * (1.0f + erff(c1 * 0.70710678118654752f));
                }
                if (RES_) {
                    c0 += res[(size_t)m * N + n0];
                    c1 += res[(size_t)m * N + n0 + 1];
                }
                if (WF_) {
                    if (n0 < N)     C[(size_t)m * N + n0]     = c0;
                    if (n0 + 1 < N) C[(size_t)m * N + n0 + 1] = c1;
                }
                if (WH_) {
                    if (n0 < N)     Ch[(size_t)m * N + n0]     = __float2half(c0);
                    if (n0 + 1 < N) Ch[(size_t)m * N + n0 + 1] = __float2half(c1);
                }
            }
        }
    }
}

// ---------------- weight prep (transpose + fp16) ----------------
__global__ void __launch_bounds__(256) tDD_kernel(
    const float* __restrict__ wq, const float* __restrict__ wk,
    const float* __restrict__ wv, const float* __restrict__ wo,
    const float* __restrict__ bq, const float* __restrict__ bk,
    const float* __restrict__ bv, __half* __restrict__ wH, float* __restrict__ bqkv)
{
    __shared__ float tile[32][33];
    const int m = blockIdx.z, l = m >> 2, which = m & 3;
    const float* W = (which == 0 ? wq : which == 1 ? wk : which == 2 ? wv : wo)
                     + (size_t)l * D_ * D_;
    __half* WT = wH + (size_t)l * LAYER_WELEMS + (size_t)which * D_ * D_;
    const int tx = threadIdx.x & 31, ty = threadIdx.x >> 5;
    const int k0 = blockIdx.y << 5, n0 = blockIdx.x << 5;
#pragma unroll
    for (int i = 0; i < 4; i++)
        tile[ty + i * 8][tx] = W[(size_t)(k0 + ty + i * 8) * D_ + n0 + tx];
    __syncthreads();
#pragma unroll
    for (int i = 0; i < 4; i++)
        WT[(size_t)(n0 + ty + i * 8) * D_ + k0 + tx] = __float2half(tile[tx][ty + i * 8]);
    if (blockIdx.y == 0 && which < 3 && threadIdx.x < 32) {
        const float* bsrc = which == 0 ? bq : which == 1 ? bk : bv;
        bqkv[l * QKV3 + which * D_ + n0 + threadIdx.x] = bsrc[l * D_ + n0 + threadIdx.x];
    }
}

__global__ void __launch_bounds__(256) tFF_kernel(
    const float* __restrict__ w1, const float* __restrict__ w2, __half* __restrict__ wH)
{
    __shared__ float tile[32][33];
    const int l = blockIdx.z;
    const int tx = threadIdx.x & 31, ty = threadIdx.x >> 5;
    const float* W; __half* WT; int Kd, Nd, k0, n0;
    if (blockIdx.y < 32) {
        W = w1 + (size_t)l * D_ * DFF_;
        WT = wH + (size_t)l * LAYER_WELEMS + (size_t)4 * D_ * D_;
        Kd = D_; Nd = DFF_;
        k0 = blockIdx.y << 5; n0 = blockIdx.x << 5;
    } else {
        const int id = blockIdx.x + ((blockIdx.y - 32) << 7);
        W = w2 + (size_t)l * DFF_ * D_;
        WT = wH + (size_t)l * LAYER_WELEMS + (size_t)4 * D_ * D_ + (size_t)D_ * DFF_;
        Kd = DFF_; Nd = D_;
        k0 = (id >> 5) << 5; n0 = (id & 31) << 5;
    }
#pragma unroll
    for (int i = 0; i < 4; i++)
        tile[ty + i * 8][tx] = W[(size_t)(k0 + ty + i * 8) * Nd + n0 + tx];
    __syncthreads();
#pragma unroll
    for (int i = 0; i < 4; i++)
        WT[(size_t)(n0 + ty + i * 8) * Kd + k0 + tx] = __float2half(tile[tx][ty + i * 8]);
}

// elementwise fp32 -> fp16 (te -> teH); n % 4 == 0
__global__ void __launch_bounds__(256) h2_kernel(
    const float* __restrict__ x, __half* __restrict__ r, int n)
{
    const int i = (blockIdx.x * 256 + threadIdx.x) * 4;
    if (i >= n) return;
    const float4 v = *(const float4*)(x + i);
    *(__half2*)(r + i)     = __floats2half2_rn(v.x, v.y);
    *(__half2*)(r + i + 2) = __floats2half2_rn(v.z, v.w);
}

// ---------------- embedding (x fp32 + xh fp16) ----------------
__global__ void __launch_bounds__(256) embed_kernel(
    const int* __restrict__ idx, const float* __restrict__ te,
    const float* __restrict__ pe, float* __restrict__ x, __half* __restrict__ xh)
{
    const int bs = blockIdx.x;
    const int s  = bs & (S_ - 1);
    const int tok = idx[bs];
    const float4* tr = (const float4*)(te + (size_t)tok * D_);
    const float4* pr = (const float4*)(pe + (size_t)s * D_);
    float4* xo = (float4*)(x + (size_t)bs * D_);
    __half* xho = xh + (size_t)bs * D_;
    for (int i = threadIdx.x; i < D_ / 4; i += blockDim.x) {
        float4 t = tr[i], p = pr[i];
        float4 s4 = make_float4(t.x + p.x, t.y + p.y, t.z + p.z, t.w + p.w);
        xo[i] = s4;
        *(__half2*)(xho + i * 4)     = __floats2half2_rn(s4.x, s4.y);
        *(__half2*)(xho + i * 4 + 2) = __floats2half2_rn(s4.z, s4.w);
    }
}

// ---------------- layernorm (fp32 in, fp16 out) ----------------
__device__ __forceinline__ float block_reduce_sum(float val, float* sh) {
    const int lane = threadIdx.x & 31;
    const int wid  = threadIdx.x >> 5;
#pragma unroll
    for (int o = 16; o; o >>= 1) val += __shfl_down_sync(0xffffffffu, val, o);
    if (lane == 0) sh[wid] = val;
    __syncthreads();
    const int nw = (blockDim.x + 31) >> 5;
    val = (threadIdx.x < nw) ? sh[threadIdx.x] : 0.0f;
    if (wid == 0) {
#pragma unroll
        for (int o = 16; o; o >>= 1) val += __shfl_down_sync(0xffffffffu, val, o);
        if (lane == 0) sh[0] = val;
    }
    __syncthreads();
    val = sh[0];
    __syncthreads();
    return val;
}

__global__ void __launch_bounds__(256) ln_kernel(
    const float* __restrict__ x, const float* __restrict__ g,
    const float* __restrict__ bta, __half* __restrict__ out)
{
    __shared__ float red[32];
    const int row = blockIdx.x;
    const float* xr = x + (size_t)row * D_;
    float s = 0.0f, s2 = 0.0f;
    for (int i = threadIdx.x; i < D_; i += 256) {
        float v = xr[i];
        s += v; s2 += v * v;
    }
    s  = block_reduce_sum(s,  red);
    s2 = block_reduce_sum(s2, red);
    const float mean = s * (1.0f / D_);
    const float var  = s2 * (1.0f / D_) - mean * mean;
    const float rstd = rsqrtf(var + 1e-5f);
    __half* orow = out + (size_t)row * D_;
    for (int i = threadIdx.x; i < D_; i += 256)
        orow[i] = __float2half((xr[i] - mean) * rstd * g[i] + bta[i]);
}

// ---------------- attention: 8 queries/block, smem-tiled fp16 K/V ----------------
#define ATT_STRIDE 68
#define ATT_SMEM ((128 * ATT_STRIDE + 8 * S_ + 8 * DK_) * 4)   // 69632 B

__global__ void __launch_bounds__(256) attn_kernel(
    const __half* __restrict__ qkv, __half* __restrict__ y)
{
    extern __shared__ float asmem[];
    float* Kb = asmem;
    float* sp = asmem + 128 * ATT_STRIDE;
    float* qs = sp + 8 * S_;
    const int tid = threadIdx.x, wid = tid >> 5, lane = tid & 31;
    const int s0 = blockIdx.x * 8;
    const int s = s0 + wid;
    const int h = blockIdx.y, b = blockIdx.z;
    const size_t base = (size_t)b * S_ * QKV3 + (size_t)h * DK_;
    const __half* kp = qkv + base + D_;
    const __half* vp = qkv + base + 2 * D_;

    {
        const float2 qv = __half22float2(*(const __half2*)(qkv + base + (size_t)s * QKV3 + lane * 2));
        qs[wid * DK_ + lane * 2]     = qv.x;
        qs[wid * DK_ + lane * 2 + 1] = qv.y;
    }
    __syncwarp();

    const int nkmax = s0 + 8;
    float lmax = -INFINITY;

    for (int c0 = 0; c0 < nkmax; c0 += 128) {
        __syncthreads();
#pragma unroll
        for (int i = 0; i < 8; i++) {
            const int ch = tid + (i << 8);            // 0..2047
            const int row = ch >> 4, q4 = (ch & 15) * 4;
            const __half2* src = (const __half2*)(kp + (size_t)(c0 + row) * QKV3 + q4);
            const float2 f0 = __half22float2(src[0]);
            const float2 f1 = __half22float2(src[1]);
            float* dst = Kb + row * ATT_STRIDE + q4;
            dst[0] = f0.x; dst[1] = f0.y; dst[2] = f1.x; dst[3] = f1.y;
        }
        __syncthreads();
        const int lim = min(c0 + 128, s + 1);
        for (int t = c0 + lane; t < lim; t += 32) {
            const float* kr = Kb + (t - c0) * ATT_STRIDE;
            float d = 0.0f;
#pragma unroll
            for (int i = 0; i < DK_; i += 4) {
                const float4 kv = *(const float4*)(kr + i);
                d += qs[wid * DK_ + i] * kv.x + qs[wid * DK_ + i + 1] * kv.y
                   + qs[wid * DK_ + i + 2] * kv.z + qs[wid * DK_ + i + 3] * kv.w;
            }
            d *= 0.125f;
            sp[wid * S_ + t] = d;
            lmax = fmaxf(lmax, d);
        }
    }
#pragma unroll
    for (int o = 16; o; o >>= 1) lmax = fmaxf(lmax, __shfl_xor_sync(0xffffffffu, lmax, o));

    float lsum = 0.0f;
    for (int t = lane; t < s + 1; t += 32) {
        const float e = expf(sp[wid * S_ + t] - lmax);
        sp[wid * S_ + t] = e;
        lsum += e;
    }
#pragma unroll
    for (int o = 16; o; o >>= 1) lsum += __shfl_xor_sync(0xffffffffu, lsum, o);
    const float inv = 1.0f / lsum;
    __syncwarp();

    const int dd = lane * 2;
    float a0 = 0.0f, a1 = 0.0f, c0a = 0.0f, c1a = 0.0f;
    for (int c0 = 0; c0 < nkmax; c0 += 128) {
        __syncthreads();
#pragma unroll
        for (int i = 0; i < 8; i++) {
            const int ch = tid + (i << 8);
            const int row = ch >> 4, q4 = (ch & 15) * 4;
            const __half2* src = (const __half2*)(vp + (size_t)(c0 + row) * QKV3 + q4);
            const float2 f0 = __half22float2(src[0]);
            const float2 f1 = __half22float2(src[1]);
            float* dst = Kb + row * ATT_STRIDE + q4;
            dst[0] = f0.x; dst[1] = f0.y; dst[2] = f1.x; dst[3] = f1.y;
        }
        __syncthreads();
        const int lim = min(c0 + 128, s + 1);
        int t = c0;
        for (; t + 2 <= lim; t += 2) {
            const float p0 = sp[wid * S_ + t], p1 = sp[wid * S_ + t + 1];
            a0  += p0 * Kb[(t - c0) * ATT_STRIDE + dd];
            a1  += p0 * Kb[(t - c0) * ATT_STRIDE + dd + 1];
            c0a += p1 * Kb[(t + 1 - c0) * ATT_STRIDE + dd];
            c1a += p1 * Kb[(t + 1 - c0) * ATT_STRIDE + dd + 1];
        }
        for (; t < lim; t++) {
            const float p = sp[wid * S_ + t];
            a0 += p * Kb[(t - c0) * ATT_STRIDE + dd];
            a1 += p * Kb[(t - c0) * ATT_STRIDE + dd + 1];
        }
    }
    *(__half2*)(y + (size_t)b * S_ * D_ + (size_t)h * DK_ + (size_t)s * D_ + dd) =
        __floats2half2_rn((a0 + c0a) * inv, (a1 + c1a) * inv);
}

// ---------------- driver ----------------
extern "C" void kernel_launch(void* const* d_in, const int* in_sizes, int n_in,
                              void* d_out, int out_size)
{
    const int*   idx   = (const int*)  d_in[0];
    const float* te    = (const float*)d_in[1];
    const float* pe    = (const float*)d_in[2];
    const float* wq    = (const float*)d_in[3];
    const float* bq    = (const float*)d_in[4];
    const float* wk    = (const float*)d_in[5];
    const float* bk    = (const float*)d_in[6];
    const float* wv    = (const float*)d_in[7];
    const float* bv    = (const float*)d_in[8];
    const float* wo    = (const float*)d_in[9];
    const float* bo    = (const float*)d_in[10];
    const float* ln2g  = (const float*)d_in[11];
    const float* ln2b  = (const float*)d_in[12];
    const float* w1    = (const float*)d_in[13];
    const float* b1    = (const float*)d_in[14];
    const float* w2    = (const float*)d_in[15];
    const float* b2    = (const float*)d_in[16];
    const float* lnfg  = (const float*)d_in[17];
    const float* lnfb  = (const float*)d_in[18];
    float* out = (float*)d_out;

    float *x, *bqkv;
    __half *xh, *qkv, *y, *t, *hb, *wH, *teH;
    cudaGetSymbolAddress((void**)&x,    g_x);
    cudaGetSymbolAddress((void**)&xh,   g_xh);
    cudaGetSymbolAddress((void**)&qkv,  g_qkv);
    cudaGetSymbolAddress((void**)&y,    g_y);
    cudaGetSymbolAddress((void**)&t,    g_t);
    cudaGetSymbolAddress((void**)&hb,   g_h);
    cudaGetSymbolAddress((void**)&wH,   g_wH);
    cudaGetSymbolAddress((void**)&bqkv, g_bqkv);
    cudaGetSymbolAddress((void**)&teH,  g_teH);

    cudaFuncSetAttribute(mma_gemm<false, false, false, true >, cudaFuncAttributeMaxDynamicSharedMemorySize, G_SMEM);
    cudaFuncSetAttribute(mma_gemm<false, true , true , false>, cudaFuncAttributeMaxDynamicSharedMemorySize, G_SMEM);
    cudaFuncSetAttribute(mma_gemm<true , false, false, true >, cudaFuncAttributeMaxDynamicSharedMemorySize, G_SMEM);
    cudaFuncSetAttribute(mma_gemm<false, true , true , true >, cudaFuncAttributeMaxDynamicSharedMemorySize, G_SMEM);
    cudaFuncSetAttribute(mma_gemm<false, false, true , false>, cudaFuncAttributeMaxDynamicSharedMemorySize, G_SMEM);
    cudaFuncSetAttribute(attn_kernel, cudaFuncAttributeMaxDynamicSharedMemorySize, ATT_SMEM);

    const int M = M_TOK;

    // prep
    embed_kernel<<<M, 256>>>(idx, te, pe, x, xh);
    tDD_kernel<<<dim3(32, 32, 4 * L_), 256>>>(wq, wk, wv, wo, bq, bk, bv, wH, bqkv);
    tFF_kernel<<<dim3(128, 64, L_), 256>>>(w1, w2, wH);

    // grids: blockIdx.x = M-block (fastest), blockIdx.y = N-block (BN=128)
    const dim3 gQKV(M / 128, QKV3 / 128);        // 16 x 24
    const dim3 gW1 (M / 128, DFF_ / 128);        // 16 x 32
    const dim3 gDD (M / 128, D_ / 128);          // 16 x 8
    const dim3 gLM (M / 128, (V_ + 127) / 128);  // 16 x 393
    const dim3 gAT (S_ / 8, H_, B_);

    for (int l = 0; l < L_; l++) {
        const size_t lw = (size_t)l * LAYER_WELEMS;
        const __half *wqkvT = wH + lw;
        const __half *woT   = wH + lw + 3 * D_ * D_;
        const __half *w1T   = wH + lw + 4 * D_ * D_;
        const __half *w2T   = w1T + (size_t)D_ * DFF_;

        // qkv(fp16) = xh @ [Wq|Wk|Wv] + bqkv
        mma_gemm<false, false, false, true><<<gQKV, 256, G_SMEM>>>(
            xh, wqkvT, bqkv + l * QKV3, nullptr, nullptr, qkv, M, QKV3, D_);

        attn_kernel<<<gAT, 256, ATT_SMEM>>>(qkv, y);

        // x(fp32) = x + y@Wo + bo
        mma_gemm<false, true, true, false><<<gDD, 256, G_SMEM>>>(
            y, woT, bo + (size_t)l * D_, x, x, nullptr, M, D_, D_);

        // t(fp16) = LN(x)
        ln_kernel<<<M, 256>>>(x, ln2g + (size_t)l * D_, ln2b + (size_t)l * D_, t);

        // hb(fp16) = gelu(t@W1 + b1)
        mma_gemm<true, false, false, true><<<gW1, 256, G_SMEM>>>(
            t, w1T, b1 + (size_t)l * DFF_, nullptr, nullptr, hb, M, DFF_, D_);

        // x(fp32) = x + hb@W2 + b2 ; xh(fp16) = x
        mma_gemm<false, true, true, true><<<gDD, 256, G_SMEM>>>(
            hb, w2T, b2 + (size_t)l * D_, x, x, xh, M, D_, DFF_);
    }

    // final LN + weight-tied LM head
    ln_kernel<<<M, 256>>>(x, lnfg, lnfb, t);
    h2_kernel<<<(V_ * D_ / 4 + 255) / 256, 256>>>(te, teH, V_ * D_);
    mma_gemm<false, false, true, false><<<gLM, 256, G_SMEM>>>(
        t, teH, nullptr, nullptr, out, nullptr, M, V_, D_);
}

// round 12
// speedup vs baseline: 5.0213x; 1.0304x over previous
#include <cuda_runtime.h>
#include <cuda_fp16.h>
#include <math.h>
#include <stdint.h>

// Problem constants
#define B_ 2
#define S_ 1024
#define D_ 1024
#define H_ 16
#define DK_ 64
#define DFF_ 4096
#define L_ 4
#define V_ 50257
#define M_TOK (B_ * S_)   // 2048 rows
#define QKV3 (3 * D_)     // 3072

// ---------------- scratch (static device globals; no allocation allowed) ----
__device__ float  g_x[M_TOK * D_];        // residual stream (fp32)
__device__ __half g_xh[M_TOK * D_];       // fp16 copy of x (QKV A input)
__device__ __half g_qkv[M_TOK * QKV3];    // fused q|k|v (fp16)
__device__ __half g_y[M_TOK * D_];        // attention out (fp16)
__device__ __half g_t[M_TOK * D_];        // ln out (fp16)
__device__ __half g_h[M_TOK * DFF_];      // mlp hidden (fp16)

// transposed fp16 weights: per layer [wqT][wkT][wvT][woT][w1T][w2T]
#define LAYER_WELEMS (4 * D_ * D_ + D_ * DFF_ + DFF_ * D_)
__device__ __half g_wH[(size_t)L_ * LAYER_WELEMS];
__device__ float  g_bqkv[L_ * QKV3];       // packed qkv bias (fp32)
__device__ __half g_teH[(size_t)V_ * D_];  // fp16 token embedding ([V,D]=[N,K])

// ---------------- PTX helpers (sm_80+ portable only) ----------------
__device__ __forceinline__ uint32_t smem_u32(const void* p) {
    uint32_t a;
    asm("{ .reg .u64 t; cvta.to.shared.u64 t, %1; cvt.u32.u64 %0, t; }" : "=r"(a) : "l"(p));
    return a;
}
__device__ __forceinline__ void cp_async16(uint32_t dst, const void* src, int szbytes) {
    asm volatile("cp.async.cg.shared.global [%0], [%1], 16, %2;" :: "r"(dst), "l"(src), "r"(szbytes));
}
__device__ __forceinline__ void cp_commit() { asm volatile("cp.async.commit_group;" ::: "memory"); }
template<int N> __device__ __forceinline__ void cp_wait() { asm volatile("cp.async.wait_group %0;" :: "n"(N) : "memory"); }

__device__ __forceinline__ void ldsm_x4(uint32_t& r0, uint32_t& r1, uint32_t& r2, uint32_t& r3, uint32_t addr) {
    asm volatile("ldmatrix.sync.aligned.m8n8.x4.shared.b16 {%0,%1,%2,%3}, [%4];"
                 : "=r"(r0), "=r"(r1), "=r"(r2), "=r"(r3) : "r"(addr));
}
// fp16 MMA, fp32 accumulate
__device__ __forceinline__ void mma16816(float* c, const uint32_t* a, uint32_t b0, uint32_t b1) {
    asm volatile("mma.sync.aligned.m16n8k16.row.col.f32.f16.f16.f32 "
                 "{%0,%1,%2,%3}, {%4,%5,%6,%7}, {%8,%9}, {%0,%1,%2,%3};"
                 : "+f"(c[0]), "+f"(c[1]), "+f"(c[2]), "+f"(c[3])
                 : "r"(a[0]), "r"(a[1]), "r"(a[2]), "r"(a[3]), "r"(b0), "r"(b1));
}

#define SW128(o) ((o) ^ (((o) >> 3) & 0x70))

// ---------------- fp16 GEMM (fp32 accumulate) ----------------
// C[M,N] = act( A[M,K] @ B[N,K]^T + bias ) (+ res)
// CTA BM x BN, BK=64 halves (128B SW128 rows), 3-stage cp.async, 128 threads.
// Warp tile 64 x WN; warps = (BM/64) x (BN/WN).
//   WIDE  : BM=128, BN=128, WN=64 -> 2x2 warps, occ 2 (less smem re-read)
//   SMALLM: BM=64,  BN=128, WN=32 -> 1x4 warps, occ 3 (fills SMs on small-M GEMMs)
// Grid: blockIdx.x = M-block (fastest, B-tile L2 reuse), blockIdx.y = N-block.
// M % BM == 0, K % 64 == 0; N tail OK (clamp+zfill, scalar store guard).
// WF_: write fp32 C.  WH_: write fp16 Ch.

template<int BM, int BN, int WN> struct GCfg {
    static constexpr int WRN = BM / 64;          // warp rows
    static constexpr int WCN = BN / WN;          // warp cols
    static constexpr int NT  = WRN * WCN * 32;   // 128
    static constexpr int OCC = (BM == 64) ? 3 : 2;
    static constexpr int STAGE = (BM + BN) * 128;
    static constexpr int SMEM  = 3 * STAGE;
    static constexpr int NJ = WN / 8;            // n8 tiles per warp
    static constexpr int NB = WN / 16;           // B ldsm groups per warp
};

template<int BM, int BN, int WN, bool GELU_, bool RES_, bool WF_, bool WH_>
__global__ void __launch_bounds__((GCfg<BM,BN,WN>::NT), (GCfg<BM,BN,WN>::OCC))
mma_gemm(const __half* __restrict__ A, const __half* __restrict__ Bm,
         const float* __restrict__ bias, const float* __restrict__ res,
         float* __restrict__ C, __half* __restrict__ Ch, int M, int N, int K)
{
    using CFG = GCfg<BM, BN, WN>;
    constexpr int NT = CFG::NT, STAGE = CFG::STAGE, WRN = CFG::WRN;
    constexpr int NJ = CFG::NJ, NB = CFG::NB;

    extern __shared__ __align__(1024) char smem_raw[];
    const uint32_t sb = smem_u32(smem_raw);
    const int tid = threadIdx.x, wid = tid >> 5, lane = tid & 31;
    const int bm = blockIdx.x * BM, bn = blockIdx.y * BN;
    const int wr = (WRN == 1) ? 0 : (wid & (WRN - 1));
    const int wc = (WRN == 1) ? wid : (wid >> 1);
    const int rl = lane & 15, qh = lane >> 4;    // ldmatrix addressing

    float acc[4][NJ][4];
#pragma unroll
    for (int i = 0; i < 4; i++)
#pragma unroll
        for (int j = 0; j < NJ; j++)
#pragma unroll
            for (int r = 0; r < 4; r++) acc[i][j][r] = 0.0f;

    auto load_chunk = [&](int c, int stage) {
        const int k0 = c << 6;                    // half-element K offset
        const uint32_t sA = sb + (uint32_t)stage * STAGE;
        const uint32_t sB = sA + BM * 128;
#pragma unroll
        for (int ch = tid; ch < BM * 8; ch += NT) {
            const int r = ch >> 3, qd = ch & 7;
            cp_async16(sA + SW128((uint32_t)(r * 128 + qd * 16)),
                       A + (size_t)(bm + r) * K + k0 + qd * 8, 16);
        }
#pragma unroll
        for (int ch = tid; ch < BN * 8; ch += NT) {
            const int r = ch >> 3, qd = ch & 7;
            const int gn = bn + r;
            const int vn = gn < N ? gn : N - 1;
            const int vsz = gn < N ? 16 : 0;      // zero-fill OOB B rows
            cp_async16(sB + SW128((uint32_t)(r * 128 + qd * 16)),
                       Bm + (size_t)vn * K + k0 + qd * 8, vsz);
        }
    };

    const int NC = K >> 6;
    load_chunk(0, 0);
    cp_commit();
    if (NC > 1) { load_chunk(1, 1); cp_commit(); }

    int buf = 0, nxt = 2;
    for (int c = 0; c < NC; c++) {
        if (c + 1 < NC) cp_wait<1>(); else cp_wait<0>();
        __syncthreads();

        if (c + 2 < NC) { load_chunk(c + 2, nxt); cp_commit(); }

        const uint32_t tA = sb + (uint32_t)buf * STAGE;
        const uint32_t tB = tA + BM * 128;
#pragma unroll
        for (int k16 = 0; k16 < 4; k16++) {       // 4 k16 steps per 64-K chunk
            uint32_t a[4][4], b[NB][4];
#pragma unroll
            for (int i = 0; i < 4; i++) {
                const uint32_t off = SW128((uint32_t)((wr * 64 + i * 16 + rl) * 128 + (k16 * 2 + qh) * 16));
                ldsm_x4(a[i][0], a[i][1], a[i][2], a[i][3], tA + off);
            }
#pragma unroll
            for (int g = 0; g < NB; g++) {
                const uint32_t off = SW128((uint32_t)((wc * WN + g * 16 + rl) * 128 + (k16 * 2 + qh) * 16));
                ldsm_x4(b[g][0], b[g][1], b[g][2], b[g][3], tB + off);
            }
            // B fragment pairing (m16n8k16): n-tile o of group g uses {b[g][o], b[g][o+2]}
#pragma unroll
            for (int i = 0; i < 4; i++)
#pragma unroll
                for (int j = 0; j < NJ; j++)
                    mma16816(acc[i][j], a[i], b[j >> 1][j & 1], b[j >> 1][(j & 1) + 2]);
        }

        buf = buf == 2 ? 0 : buf + 1;
        nxt = nxt == 2 ? 0 : nxt + 1;
    }

    // epilogue (scalar stores: N may be odd)
    const int quad = lane >> 2, tq = lane & 3;
#pragma unroll
    for (int i = 0; i < 4; i++) {
        const int m0 = bm + wr * 64 + i * 16 + quad;
#pragma unroll
        for (int j = 0; j < NJ; j++) {
            const int n0 = bn + wc * WN + j * 8 + tq * 2;
#pragma unroll
            for (int half = 0; half < 2; half++) {
                const int m = m0 + half * 8;
                float c0 = acc[i][j][half * 2 + 0];
                float c1 = acc[i][j][half * 2 + 1];
                if (bias) { c0 += bias[n0]; c1 += bias[n0 + 1]; }
                if (GELU_) {
                    c0 = 0.5f * c0 * (1.0f + erff(c0 * 0.70710678118654752f));
                    c1 = 0.5f * c1 * (1.0f + erff(c1 * 0.70710678118654752f));
                }
                if (RES_) {
                    c0 += res[(size_t)m * N + n0];
                    c1 += res[(size_t)m * N + n0 + 1];
                }
                if (WF_) {
                    if (n0 < N)     C[(size_t)m * N + n0]     = c0;
                    if (n0 + 1 < N) C[(size_t)m * N + n0 + 1] = c1;
                }
                if (WH_) {
                    if (n0 < N)     Ch[(size_t)m * N + n0]     = __float2half(c0);
                    if (n0 + 1 < N) Ch[(size_t)m * N + n0 + 1] = __float2half(c1);
                }
            }
        }
    }
}

// ---------------- weight prep (transpose + fp16) ----------------
__global__ void __launch_bounds__(256) tDD_kernel(
    const float* __restrict__ wq, const float* __restrict__ wk,
    const float* __restrict__ wv, const float* __restrict__ wo,
    const float* __restrict__ bq, const float* __restrict__ bk,
    const float* __restrict__ bv, __half* __restrict__ wH, float* __restrict__ bqkv)
{
    __shared__ float tile[32][33];
    const int m = blockIdx.z, l = m >> 2, which = m & 3;
    const float* W = (which == 0 ? wq : which == 1 ? wk : which == 2 ? wv : wo)
                     + (size_t)l * D_ * D_;
    __half* WT = wH + (size_t)l * LAYER_WELEMS + (size_t)which * D_ * D_;
    const int tx = threadIdx.x & 31, ty = threadIdx.x >> 5;
    const int k0 = blockIdx.y << 5, n0 = blockIdx.x << 5;
#pragma unroll
    for (int i = 0; i < 4; i++)
        tile[ty + i * 8][tx] = W[(size_t)(k0 + ty + i * 8) * D_ + n0 + tx];
    __syncthreads();
#pragma unroll
    for (int i = 0; i < 4; i++)
        WT[(size_t)(n0 + ty + i * 8) * D_ + k0 + tx] = __float2half(tile[tx][ty + i * 8]);
    if (blockIdx.y == 0 && which < 3 && threadIdx.x < 32) {
        const float* bsrc = which == 0 ? bq : which == 1 ? bk : bv;
        bqkv[l * QKV3 + which * D_ + n0 + threadIdx.x] = bsrc[l * D_ + n0 + threadIdx.x];
    }
}

__global__ void __launch_bounds__(256) tFF_kernel(
    const float* __restrict__ w1, const float* __restrict__ w2, __half* __restrict__ wH)
{
    __shared__ float tile[32][33];
    const int l = blockIdx.z;
    const int tx = threadIdx.x & 31, ty = threadIdx.x >> 5;
    const float* W; __half* WT; int Kd, Nd, k0, n0;
    if (blockIdx.y < 32) {
        W = w1 + (size_t)l * D_ * DFF_;
        WT = wH + (size_t)l * LAYER_WELEMS + (size_t)4 * D_ * D_;
        Kd = D_; Nd = DFF_;
        k0 = blockIdx.y << 5; n0 = blockIdx.x << 5;
    } else {
        const int id = blockIdx.x + ((blockIdx.y - 32) << 7);
        W = w2 + (size_t)l * DFF_ * D_;
        WT = wH + (size_t)l * LAYER_WELEMS + (size_t)4 * D_ * D_ + (size_t)D_ * DFF_;
        Kd = DFF_; Nd = D_;
        k0 = (id >> 5) << 5; n0 = (id & 31) << 5;
    }
#pragma unroll
    for (int i = 0; i < 4; i++)
        tile[ty + i * 8][tx] = W[(size_t)(k0 + ty + i * 8) * Nd + n0 + tx];
    __syncthreads();
#pragma unroll
    for (int i = 0; i < 4; i++)
        WT[(size_t)(n0 + ty + i * 8) * Kd + k0 + tx] = __float2half(tile[tx][ty + i * 8]);
}

// elementwise fp32 -> fp16 (te -> teH); n % 4 == 0
__global__ void __launch_bounds__(256) h2_kernel(
    const float* __restrict__ x, __half* __restrict__ r, int n)
{
    const int i = (blockIdx.x * 256 + threadIdx.x) * 4;
    if (i >= n) return;
    const float4 v = *(const float4*)(x + i);
    *(__half2*)(r + i)     = __floats2half2_rn(v.x, v.y);
    *(__half2*)(r + i + 2) = __floats2half2_rn(v.z, v.w);
}

// ---------------- embedding (x fp32 + xh fp16) ----------------
__global__ void __launch_bounds__(256) embed_kernel(
    const int* __restrict__ idx, const float* __restrict__ te,
    const float* __restrict__ pe, float* __restrict__ x, __half* __restrict__ xh)
{
    const int bs = blockIdx.x;
    const int s  = bs & (S_ - 1);
    const int tok = idx[bs];
    const float4* tr = (const float4*)(te + (size_t)tok * D_);
    const float4* pr = (const float4*)(pe + (size_t)s * D_);
    float4* xo = (float4*)(x + (size_t)bs * D_);
    __half* xho = xh + (size_t)bs * D_;
    for (int i = threadIdx.x; i < D_ / 4; i += blockDim.x) {
        float4 t = tr[i], p = pr[i];
        float4 s4 = make_float4(t.x + p.x, t.y + p.y, t.z + p.z, t.w + p.w);
        xo[i] = s4;
        *(__half2*)(xho + i * 4)     = __floats2half2_rn(s4.x, s4.y);
        *(__half2*)(xho + i * 4 + 2) = __floats2half2_rn(s4.z, s4.w);
    }
}

// ---------------- layernorm (fp32 in, fp16 out) ----------------
__device__ __forceinline__ float block_reduce_sum(float val, float* sh) {
    const int lane = threadIdx.x & 31;
    const int wid  = threadIdx.x >> 5;
#pragma unroll
    for (int o = 16; o; o >>= 1) val += __shfl_down_sync(0xffffffffu, val, o);
    if (lane == 0) sh[wid] = val;
    __syncthreads();
    const int nw = (blockDim.x + 31) >> 5;
    val = (threadIdx.x < nw) ? sh[threadIdx.x] : 0.0f;
    if (wid == 0) {
#pragma unroll
        for (int o = 16; o; o >>= 1) val += __shfl_down_sync(0xffffffffu, val, o);
        if (lane == 0) sh[0] = val;
    }
    __syncthreads();
    val = sh[0];
    __syncthreads();
    return val;
}

__global__ void __launch_bounds__(256) ln_kernel(
    const float* __restrict__ x, const float* __restrict__ g,
    const float* __restrict__ bta, __half* __restrict__ out)
{
    __shared__ float red[32];
    const int row = blockIdx.x;
    const float* xr = x + (size_t)row * D_;
    float s = 0.0f, s2 = 0.0f;
    for (int i = threadIdx.x; i < D_; i += 256) {
        float v = xr[i];
        s += v; s2 += v * v;
    }
    s  = block_reduce_sum(s,  red);
    s2 = block_reduce_sum(s2, red);
    const float mean = s * (1.0f / D_);
    const float var  = s2 * (1.0f / D_) - mean * mean;
    const float rstd = rsqrtf(var + 1e-5f);
    __half* orow = out + (size_t)row * D_;
    for (int i = threadIdx.x; i < D_; i += 256)
        orow[i] = __float2half((xr[i] - mean) * rstd * g[i] + bta[i]);
}

// ---------------- attention: 8 queries/block, smem-tiled fp16 K/V ----------------
#define ATT_STRIDE 68
#define ATT_SMEM ((128 * ATT_STRIDE + 8 * S_ + 8 * DK_) * 4)   // 69632 B

__global__ void __launch_bounds__(256) attn_kernel(
    const __half* __restrict__ qkv, __half* __restrict__ y)
{
    extern __shared__ float asmem[];
    float* Kb = asmem;
    float* sp = asmem + 128 * ATT_STRIDE;
    float* qs = sp + 8 * S_;
    const int tid = threadIdx.x, wid = tid >> 5, lane = tid & 31;
    const int s0 = blockIdx.x * 8;
    const int s = s0 + wid;
    const int h = blockIdx.y, b = blockIdx.z;
    const size_t base = (size_t)b * S_ * QKV3 + (size_t)h * DK_;
    const __half* kp = qkv + base + D_;
    const __half* vp = qkv + base + 2 * D_;

    {
        const float2 qv = __half22float2(*(const __half2*)(qkv + base + (size_t)s * QKV3 + lane * 2));
        qs[wid * DK_ + lane * 2]     = qv.x;
        qs[wid * DK_ + lane * 2 + 1] = qv.y;
    }
    __syncwarp();

    const int nkmax = s0 + 8;
    float lmax = -INFINITY;

    for (int c0 = 0; c0 < nkmax; c0 += 128) {
        __syncthreads();
#pragma unroll
        for (int i = 0; i < 8; i++) {
            const int ch = tid + (i << 8);            // 0..2047
            const int row = ch >> 4, q4 = (ch & 15) * 4;
            const __half2* src = (const __half2*)(kp + (size_t)(c0 + row) * QKV3 + q4);
            const float2 f0 = __half22float2(src[0]);
            const float2 f1 = __half22float2(src[1]);
            float* dst = Kb + row * ATT_STRIDE + q4;
            dst[0] = f0.x; dst[1] = f0.y; dst[2] = f1.x; dst[3] = f1.y;
        }
        __syncthreads();
        const int lim = min(c0 + 128, s + 1);
        for (int t = c0 + lane; t < lim; t += 32) {
            const float* kr = Kb + (t - c0) * ATT_STRIDE;
            float d = 0.0f;
#pragma unroll
            for (int i = 0; i < DK_; i += 4) {
                const float4 kv = *(const float4*)(kr + i);
                d += qs[wid * DK_ + i] * kv.x + qs[wid * DK_ + i + 1] * kv.y
                   + qs[wid * DK_ + i + 2] * kv.z + qs[wid * DK_ + i + 3] * kv.w;
            }
            d *= 0.125f;
            sp[wid * S_ + t] = d;
            lmax = fmaxf(lmax, d);
        }
    }
#pragma unroll
    for (int o = 16; o; o >>= 1) lmax = fmaxf(lmax, __shfl_xor_sync(0xffffffffu, lmax, o));

    float lsum = 0.0f;
    for (int t = lane; t < s + 1; t += 32) {
        const float e = expf(sp[wid * S_ + t] - lmax);
        sp[wid * S_ + t] = e;
        lsum += e;
    }
#pragma unroll
    for (int o = 16; o; o >>= 1) lsum += __shfl_xor_sync(0xffffffffu, lsum, o);
    const float inv = 1.0f / lsum;
    __syncwarp();

    const int dd = lane * 2;
    float a0 = 0.0f, a1 = 0.0f, c0a = 0.0f, c1a = 0.0f;
    for (int c0 = 0; c0 < nkmax; c0 += 128) {
        __syncthreads();
#pragma unroll
        for (int i = 0; i < 8; i++) {
            const int ch = tid + (i << 8);
            const int row = ch >> 4, q4 = (ch & 15) * 4;
            const __half2* src = (const __half2*)(vp + (size_t)(c0 + row) * QKV3 + q4);
            const float2 f0 = __half22float2(src[0]);
            const float2 f1 = __half22float2(src[1]);
            float* dst = Kb + row * ATT_STRIDE + q4;
            dst[0] = f0.x; dst[1] = f0.y; dst[2] = f1.x; dst[3] = f1.y;
        }
        __syncthreads();
        const int lim = min(c0 + 128, s + 1);
        int t = c0;
        for (; t + 2 <= lim; t += 2) {
            const float p0 = sp[wid * S_ + t], p1 = sp[wid * S_ + t + 1];
            a0  += p0 * Kb[(t - c0) * ATT_STRIDE + dd];
            a1  += p0 * Kb[(t - c0) * ATT_STRIDE + dd + 1];
            c0a += p1 * Kb[(t + 1 - c0) * ATT_STRIDE + dd];
            c1a += p1 * Kb[(t + 1 - c0) * ATT_STRIDE + dd + 1];
        }
        for (; t < lim; t++) {
            const float p = sp[wid * S_ + t];
            a0 += p * Kb[(t - c0) * ATT_STRIDE + dd];
            a1 += p * Kb[(t - c0) * ATT_STRIDE + dd + 1];
        }
    }
    *(__half2*)(y + (size_t)b * S_ * D_ + (size_t)h * DK_ + (size_t)s * D_ + dd) =
        __floats2half2_rn((a0 + c0a) * inv, (a1 + c1a) * inv);
}

// ---------------- driver ----------------
extern "C" void kernel_launch(void* const* d_in, const int* in_sizes, int n_in,
                              void* d_out, int out_size)
{
    const int*   idx   = (const int*)  d_in[0];
    const float* te    = (const float*)d_in[1];
    const float* pe    = (const float*)d_in[2];
    const float* wq    = (const float*)d_in[3];
    const float* bq    = (const float*)d_in[4];
    const float* wk    = (const float*)d_in[5];
    const float* bk    = (const float*)d_in[6];
    const float* wv    = (const float*)d_in[7];
    const float* bv    = (const float*)d_in[8];
    const float* wo    = (const float*)d_in[9];
    const float* bo    = (const float*)d_in[10];
    const float* ln2g  = (const float*)d_in[11];
    const float* ln2b  = (const float*)d_in[12];
    const float* w1    = (const float*)d_in[13];
    const float* b1    = (const float*)d_in[14];
    const float* w2    = (const float*)d_in[15];
    const float* b2    = (const float*)d_in[16];
    const float* lnfg  = (const float*)d_in[17];
    const float* lnfb  = (const float*)d_in[18];
    float* out = (float*)d_out;

    float *x, *bqkv;
    __half *xh, *qkv, *y, *t, *hb, *wH, *teH;
    cudaGetSymbolAddress((void**)&x,    g_x);
    cudaGetSymbolAddress((void**)&xh,   g_xh);
    cudaGetSymbolAddress((void**)&qkv,  g_qkv);
    cudaGetSymbolAddress((void**)&y,    g_y);
    cudaGetSymbolAddress((void**)&t,    g_t);
    cudaGetSymbolAddress((void**)&hb,   g_h);
    cudaGetSymbolAddress((void**)&wH,   g_wH);
    cudaGetSymbolAddress((void**)&bqkv, g_bqkv);
    cudaGetSymbolAddress((void**)&teH,  g_teH);

    constexpr int SMW = GCfg<128, 128, 64>::SMEM;   // 96 KB (WIDE)
    constexpr int SMS = GCfg<64, 128, 32>::SMEM;    // 72 KB (SMALLM)
    cudaFuncSetAttribute(mma_gemm<128, 128, 64, false, false, false, true >, cudaFuncAttributeMaxDynamicSharedMemorySize, SMW);
    cudaFuncSetAttribute(mma_gemm<128, 128, 64, true , false, false, true >, cudaFuncAttributeMaxDynamicSharedMemorySize, SMW);
    cudaFuncSetAttribute(mma_gemm<128, 128, 64, false, false, true , false>, cudaFuncAttributeMaxDynamicSharedMemorySize, SMW);
    cudaFuncSetAttribute(mma_gemm<64, 128, 32, false, true , true , false>, cudaFuncAttributeMaxDynamicSharedMemorySize, SMS);
    cudaFuncSetAttribute(mma_gemm<64, 128, 32, false, true , true , true >, cudaFuncAttributeMaxDynamicSharedMemorySize, SMS);
    cudaFuncSetAttribute(attn_kernel, cudaFuncAttributeMaxDynamicSharedMemorySize, ATT_SMEM);

    const int M = M_TOK;

    // prep
    embed_kernel<<<M, 256>>>(idx, te, pe, x, xh);
    tDD_kernel<<<dim3(32, 32, 4 * L_), 256>>>(wq, wk, wv, wo, bq, bk, bv, wH, bqkv);
    tFF_kernel<<<dim3(128, 64, L_), 256>>>(w1, w2, wH);

    // grids: blockIdx.x = M-block (fastest), blockIdx.y = N-block
    const dim3 gQKV(M / 128, QKV3 / 128);        // 16 x 24  (WIDE)
    const dim3 gW1 (M / 128, DFF_ / 128);        // 16 x 32  (WIDE)
    const dim3 gSM (M / 64, D_ / 128);           // 32 x 8   (SMALLM)
    const dim3 gLM (M / 128, (V_ + 127) / 128);  // 16 x 393 (WIDE)
    const dim3 gAT (S_ / 8, H_, B_);

    for (int l = 0; l < L_; l++) {
        const size_t lw = (size_t)l * LAYER_WELEMS;
        const __half *wqkvT = wH + lw;
        const __half *woT   = wH + lw + 3 * D_ * D_;
        const __half *w1T   = wH + lw + 4 * D_ * D_;
        const __half *w2T   = w1T + (size_t)D_ * DFF_;

        // qkv(fp16) = xh @ [Wq|Wk|Wv] + bqkv
        mma_gemm<128, 128, 64, false, false, false, true><<<gQKV, 128, SMW>>>(
            xh, wqkvT, bqkv + l * QKV3, nullptr, nullptr, qkv, M, QKV3, D_);

        attn_kernel<<<gAT, 256, ATT_SMEM>>>(qkv, y);

        // x(fp32) = x + y@Wo + bo
        mma_gemm<64, 128, 32, false, true, true, false><<<gSM, 128, SMS>>>(
            y, woT, bo + (size_t)l * D_, x, x, nullptr, M, D_, D_);

        // t(fp16) = LN(x)
        ln_kernel<<<M, 256>>>(x, ln2g + (size_t)l * D_, ln2b + (size_t)l * D_, t);

        // hb(fp16) = gelu(t@W1 + b1)
        mma_gemm<128, 128, 64, true, false, false, true><<<gW1, 128, SMW>>>(
            t, w1T, b1 + (size_t)l * DFF_, nullptr, nullptr, hb, M, DFF_, D_);

        // x(fp32) = x + hb@W2 + b2 ; xh(fp16) = x
        mma_gemm<64, 128, 32, false, true, true, true><<<gSM, 128, SMS>>>(
            hb, w2T, b2 + (size_t)l * D_, x, x, xh, M, D_, DFF_);
    }

    // final LN + weight-tied LM head
    ln_kernel<<<M, 256>>>(x, lnfg, lnfb, t);
    h2_kernel<<<(V_ * D_ / 4 + 255) / 256, 256>>>(te, teH, V_ * D_);
    mma_gemm<128, 128, 64, false, false, true, false><<<gLM, 128, SMW>>>(
        t, teH, nullptr, nullptr, out, nullptr, M, V_, D_);
}